// round 4
// baseline (speedup 1.0000x reference)
#include <cuda_runtime.h>
#include <math.h>

// ---------------- problem dims ----------------
constexpr int B_  = 8192;
constexpr int L_  = 32;
constexpr int V_  = 256;
constexpr int DIN = 256;
constexpr int H_  = 512;
constexpr int E_  = 256;

constexpr int MT  = 32;    // batch rows per CTA
constexpr int NT  = 256;   // threads per CTA
constexpr int ST  = 36;    // transposed activation row stride (floats): pad vs 32 banks

typedef unsigned long long ull;

// ---------------- packed f32x2 FMA: two INDEPENDENT sequential chains ----------------
__device__ __forceinline__ void ffma2(ull &d, ull a, ull b){
    asm("fma.rn.f32x2 %0, %1, %2, %0;" : "+l"(d) : "l"(a), "l"(b));
}
__device__ __forceinline__ ull dup2(float w){
    ull r; asm("mov.b64 %0, {%1, %1};" : "=l"(r) : "f"(w)); return r;
}
__device__ __forceinline__ void unpack2(ull v, float &lo, float &hi){
    asm("mov.b64 {%0, %1}, %2;" : "=f"(lo), "=f"(hi) : "l"(v));
}

// ---------------- XLA:CPU exp (GenerateVF32Exp, Cephes-style with FMA) ----------------
__device__ __forceinline__ float xla_exp(float x){
    float c  = fminf(fmaxf(x, -88.3762626647949f), 88.3762626647950f);
    float fx = floorf(__fmaf_rn(c, 1.44269504088896341f, 0.5f));
    float t1 = __fmul_rn(0.693359375f, fx);
    float t2 = __fmul_rn(-2.12194440e-4f, fx);
    float r  = __fadd_rn(c, -t1);
    r        = __fadd_rn(r, -t2);
    float r2 = __fmul_rn(r, r);
    float y  = 1.9875691500e-4f;
    y = __fmaf_rn(y, r, 1.3981999507e-3f);
    y = __fmaf_rn(y, r, 8.3334519073e-3f);
    y = __fmaf_rn(y, r, 4.1665795894e-2f);
    y = __fmaf_rn(y, r, 1.6666665459e-1f);
    y = __fmaf_rn(y, r, 5.0000001201e-1f);
    y = __fmaf_rn(y, r2, r);
    y = __fadd_rn(y, 1.0f);
    int n = (int)fx;
    float p2n = __int_as_float((n + 127) << 23);
    return __fmul_rn(y, p2n);
}
// XLA logistic_expander: 1 / (1 + exp(-x)), each op separately rounded
__device__ __forceinline__ float xla_sigmoid(float x){
    float e = xla_exp(-x);
    return __fdiv_rn(1.0f, __fadd_rn(1.0f, e));
}
// XLA fast tanh: clamp [-9,9], rational poly with FMA Horner, |x|<4e-4 -> x
__device__ __forceinline__ float xla_tanh(float x){
    float ax = fabsf(x);
    float xc = fminf(fmaxf(x, -9.0f), 9.0f);
    float x2 = __fmul_rn(xc, xc);
    float np = -2.76076847742355e-16f;
    np = __fmaf_rn(np, x2, 2.00018790482477e-13f);
    np = __fmaf_rn(np, x2, -8.60467152213735e-11f);
    np = __fmaf_rn(np, x2, 5.12229709037114e-08f);
    np = __fmaf_rn(np, x2, 1.48572235717979e-05f);
    np = __fmaf_rn(np, x2, 6.37261928875436e-04f);
    np = __fmaf_rn(np, x2, 4.89352455891786e-03f);
    np = __fmul_rn(np, xc);
    float dp = 1.19825839466702e-06f;
    dp = __fmaf_rn(dp, x2, 1.18534705686654e-04f);
    dp = __fmaf_rn(dp, x2, 2.26843463243900e-03f);
    dp = __fmaf_rn(dp, x2, 4.89352518554385e-03f);
    float res = __fdiv_rn(np, dp);
    return (ax < 0.0004f) ? x : res;
}

// one k-step, 3 gates x 4 row-pairs (strict ascending-k chains per element)
#define STEP3(WX, WY, WZ, KOFF) do { \
    ull d0 = dup2(WX), d1 = dup2(WY), d2 = dup2(WZ); \
    const float* ab_ = actT + (size_t)(KOFF) * ST + row0; \
    ull a0 = *(const ull*)(ab_ + 0); ull a1 = *(const ull*)(ab_ + 2); \
    ull a2 = *(const ull*)(ab_ + 4); ull a3 = *(const ull*)(ab_ + 6); \
    ffma2(acc[0][0], a0, d0); ffma2(acc[0][1], a1, d0); ffma2(acc[0][2], a2, d0); ffma2(acc[0][3], a3, d0); \
    ffma2(acc[1][0], a0, d1); ffma2(acc[1][1], a1, d1); ffma2(acc[1][2], a2, d1); ffma2(acc[1][3], a3, d1); \
    ffma2(acc[2][0], a0, d2); ffma2(acc[2][1], a1, d2); ffma2(acc[2][2], a2, d2); ffma2(acc[2][3], a3, d2); \
} while(0)

// 3-gate sequential-k chain accumulation over K elements of actT (transposed [k][row])
template<int KK>
__device__ __forceinline__ void chain3(ull (&acc)[3][4],
    const float* __restrict__ W0, const float* __restrict__ W1, const float* __restrict__ W2,
    const float* __restrict__ actT, int row0)
{
#pragma unroll 1
    for (int k0 = 0; k0 < KK; k0 += 4){
        float4 w0 = *(const float4*)(W0 + k0);
        float4 w1 = *(const float4*)(W1 + k0);
        float4 w2 = *(const float4*)(W2 + k0);
        STEP3(w0.x, w1.x, w2.x, k0 + 0);
        STEP3(w0.y, w1.y, w2.y, k0 + 1);
        STEP3(w0.z, w1.z, w2.z, k0 + 2);
        STEP3(w0.w, w1.w, w2.w, k0 + 3);
    }
}

// 1-gate variant (h0)
template<int KK>
__device__ __forceinline__ void chain1(ull (&acc)[4],
    const float* __restrict__ W0, const float* __restrict__ actT, int row0)
{
#pragma unroll 1
    for (int k0 = 0; k0 < KK; k0 += 4){
        float4 w0 = *(const float4*)(W0 + k0);
#pragma unroll
        for (int j = 0; j < 4; ++j){
            float wv = (j == 0) ? w0.x : (j == 1) ? w0.y : (j == 2) ? w0.z : w0.w;
            ull d0 = dup2(wv);
            const float* ab_ = actT + (size_t)(k0 + j) * ST + row0;
            ffma2(acc[0], *(const ull*)(ab_ + 0), d0);
            ffma2(acc[1], *(const ull*)(ab_ + 2), d0);
            ffma2(acc[2], *(const ull*)(ab_ + 4), d0);
            ffma2(acc[3], *(const ull*)(ab_ + 6), d0);
        }
    }
}

__global__ void __launch_bounds__(NT, 1)
rnn_decoder_kernel(
    const float* __restrict__ x,    const float* __restrict__ emb,
    const float* __restrict__ sos,
    const float* __restrict__ Wi2h, const float* __restrict__ bi2h,
    const float* __restrict__ Wih,  const float* __restrict__ Whh,
    const float* __restrict__ bih,  const float* __restrict__ bhh,
    const float* __restrict__ Wout, const float* __restrict__ bout,
    float* __restrict__ tokf, int* __restrict__ toki, float* __restrict__ lg)
{
    extern __shared__ float sm[];
    float* hT0  = sm;                    // [512][ST] transposed hidden (buffer A)
    float* hT1  = hT0 + H_ * ST;         // [512][ST] buffer B
    float* iT   = hT1 + H_ * ST;         // [256][ST] transposed input embedding
    float* slog = iT + E_ * ST;          // [32][256] logits
    int*   stok = (int*)(slog + MT * V_);// [32]

    const int tid  = threadIdx.x;
    const int b0   = blockIdx.x * MT;
    const int cx   = tid & 63;           // gate-phase column within 64-col block
    const int row0 = (tid >> 6) * 8;     // gate-phase: 8 rows (4 pairs) per thread
    const int lane = tid & 31;
    const int wid  = tid >> 5;

    // ---- load x tile transposed into iT: iT[k][row] = x[b0+row][k] ----
    for (int q = tid; q < MT * (DIN / 4); q += NT){
        const int ch  = q & 63;          // float4 chunk along k (coalesced)
        const int row = q >> 6;
        float4 v = *(const float4*)(x + (size_t)(b0 + row) * DIN + ch * 4);
        iT[(4 * ch + 0) * ST + row] = v.x;
        iT[(4 * ch + 1) * ST + row] = v.y;
        iT[(4 * ch + 2) * ST + row] = v.z;
        iT[(4 * ch + 3) * ST + row] = v.w;
    }
    __syncthreads();

    float* hcur = hT0;
    float* hnxt = hT1;

    // ---- h0 = x @ Wi2h^T + bi2h (Eigen-order chain + single bias add) ----
#pragma unroll 1
    for (int c = 0; c < H_; c += 64){
        const int col = c + cx;
        ull acc[4] = {};
        chain1<DIN>(acc, Wi2h + (size_t)col * DIN, iT, row0);
        const float b = bi2h[col];
#pragma unroll
        for (int p = 0; p < 4; ++p){
            float lo, hi; unpack2(acc[p], lo, hi);
            hcur[col * ST + row0 + 2 * p + 0] = __fadd_rn(lo, b);
            hcur[col * ST + row0 + 2 * p + 1] = __fadd_rn(hi, b);
        }
    }
    __syncthreads();   // h0 done reading iT

    // ---- i0 = sos broadcast (transposed) ----
    for (int q = tid; q < E_ * MT; q += NT){
        const int e = q >> 5, r = q & 31;
        iT[e * ST + r] = sos[e];
    }

    // ---- time loop ----
#pragma unroll 1
    for (int t = 0; t < L_; ++t){
        __syncthreads();   // iT + hcur ready

        // ===== GRU gates (exact chain order) =====
#pragma unroll 1
        for (int c = 0; c < H_; c += 64){
            const int col = c + cx;
            ull gi[3][4] = {};
            ull gh[3][4] = {};
            chain3<E_>(gi, Wih + (size_t)col * E_,
                           Wih + (size_t)(col +     H_) * E_,
                           Wih + (size_t)(col + 2 * H_) * E_, iT, row0);
            chain3<H_>(gh, Whh + (size_t)col * H_,
                           Whh + (size_t)(col +     H_) * H_,
                           Whh + (size_t)(col + 2 * H_) * H_, hcur, row0);
            const float bir = bih[col], biz = bih[col + H_], bin = bih[col + 2 * H_];
            const float bhr = bhh[col], bhz = bhh[col + H_], bhn = bhh[col + 2 * H_];
#pragma unroll
            for (int p = 0; p < 4; ++p){
                float giR0, giR1, giZ0, giZ1, giN0, giN1;
                float ghR0, ghR1, ghZ0, ghZ1, ghN0, ghN1;
                unpack2(gi[0][p], giR0, giR1); unpack2(gi[1][p], giZ0, giZ1); unpack2(gi[2][p], giN0, giN1);
                unpack2(gh[0][p], ghR0, ghR1); unpack2(gh[1][p], ghZ0, ghZ1); unpack2(gh[2][p], ghN0, ghN1);
#pragma unroll
                for (int s = 0; s < 2; ++s){
                    const int row = row0 + 2 * p + s;
                    float dIR = s ? giR1 : giR0, dIZ = s ? giZ1 : giZ0, dIN = s ? giN1 : giN0;
                    float dHR = s ? ghR1 : ghR0, dHZ = s ? ghZ1 : ghZ0, dHN = s ? ghN1 : ghN0;
                    // gi = dot + b_ih ; gh = dot + b_hh ; each op separately rounded
                    float ir = __fadd_rn(dIR, bir), hr = __fadd_rn(dHR, bhr);
                    float iz = __fadd_rn(dIZ, biz), hz = __fadd_rn(dHZ, bhz);
                    float in_ = __fadd_rn(dIN, bin), hn = __fadd_rn(dHN, bhn);
                    float rg = xla_sigmoid(__fadd_rn(ir, hr));
                    float zg = xla_sigmoid(__fadd_rn(iz, hz));
                    float npre = __fadd_rn(in_, __fmul_rn(rg, hn));
                    float n  = xla_tanh(npre);
                    float ho = hcur[col * ST + row];
                    float omz = __fadd_rn(1.0f, -zg);           // 1 - z (exact fsub)
                    float hv  = __fadd_rn(__fmul_rn(omz, n), __fmul_rn(zg, ho));
                    hnxt[col * ST + row] = hv;
                }
            }
        }
        __syncthreads();   // hnxt complete

        // ===== logits = hnxt @ Wout^T + bout (chains over k=0..511) =====
        {
            const int colA = tid & 127;
            const int colB = colA + 128;
            const int pg   = tid >> 7;       // 0/1 -> rows [0,16) / [16,32)
            const int r0   = pg * 16;
            ull aA[8], aB[8];
#pragma unroll
            for (int p = 0; p < 8; ++p){ aA[p] = 0ULL; aB[p] = 0ULL; }
            const float* WA = Wout + (size_t)colA * H_;
            const float* WB = Wout + (size_t)colB * H_;
#pragma unroll 1
            for (int k0 = 0; k0 < H_; k0 += 4){
                float4 wa = *(const float4*)(WA + k0);
                float4 wb = *(const float4*)(WB + k0);
#pragma unroll
                for (int j = 0; j < 4; ++j){
                    float wav = (j == 0) ? wa.x : (j == 1) ? wa.y : (j == 2) ? wa.z : wa.w;
                    float wbv = (j == 0) ? wb.x : (j == 1) ? wb.y : (j == 2) ? wb.z : wb.w;
                    ull da = dup2(wav), db = dup2(wbv);
                    const float* ab_ = hnxt + (size_t)(k0 + j) * ST + r0;
#pragma unroll
                    for (int p = 0; p < 8; ++p){
                        ull av = *(const ull*)(ab_ + 2 * p);
                        ffma2(aA[p], av, da);
                        ffma2(aB[p], av, db);
                    }
                }
            }
            const float boA = bout[colA], boB = bout[colB];
#pragma unroll
            for (int p = 0; p < 8; ++p){
                float a0, a1, b0v, b1v;
                unpack2(aA[p], a0, a1); unpack2(aB[p], b0v, b1v);
                const int rA = r0 + 2 * p, rB = rA + 1;
                float lvA0 = __fadd_rn(a0, boA), lvA1 = __fadd_rn(a1, boA);
                float lvB0 = __fadd_rn(b0v, boB), lvB1 = __fadd_rn(b1v, boB);
                slog[rA * V_ + colA] = lvA0; slog[rB * V_ + colA] = lvA1;
                slog[rA * V_ + colB] = lvB0; slog[rB * V_ + colB] = lvB1;
                if (lg){
                    lg[(size_t)(b0 + rA) * (L_ * V_) + (size_t)t * V_ + colA] = lvA0;
                    lg[(size_t)(b0 + rB) * (L_ * V_) + (size_t)t * V_ + colA] = lvA1;
                    lg[(size_t)(b0 + rA) * (L_ * V_) + (size_t)t * V_ + colB] = lvB0;
                    lg[(size_t)(b0 + rB) * (L_ * V_) + (size_t)t * V_ + colB] = lvB1;
                }
            }
        }
        __syncthreads();   // slog complete

        // ===== argmax (first index on ties, == jnp.argmax) =====
#pragma unroll
        for (int rr2 = 0; rr2 < 4; ++rr2){
            const int row = wid * 4 + rr2;
            float bv = -1e30f; int bi = 0;
#pragma unroll
            for (int j = 0; j < 8; ++j){
                const int idx = lane + 32 * j;
                float v = slog[row * V_ + idx];
                if (v > bv){ bv = v; bi = idx; }
            }
#pragma unroll
            for (int off = 16; off > 0; off >>= 1){
                float ov = __shfl_down_sync(0xffffffffu, bv, off);
                int   oi = __shfl_down_sync(0xffffffffu, bi, off);
                if (ov > bv || (ov == bv && oi < bi)){ bv = ov; bi = oi; }
            }
            if (lane == 0){
                stok[row] = bi;
                if (tokf) tokf[(size_t)(b0 + row) * L_ + t] = (float)bi;
                if (toki) toki[(size_t)(b0 + row) * L_ + t] = bi;
            }
        }
        __syncthreads();   // stok visible

        // ===== gather next input (transposed): iT[e][row] = emb[stok[row]][e] =====
        for (int q = tid; q < MT * (E_ / 4); q += NT){
            const int row = q & 31;
            const int ch  = q >> 5;
            float4 v = *(const float4*)(emb + (size_t)stok[row] * E_ + ch * 4);
            iT[(4 * ch + 0) * ST + row] = v.x;
            iT[(4 * ch + 1) * ST + row] = v.y;
            iT[(4 * ch + 2) * ST + row] = v.z;
            iT[(4 * ch + 3) * ST + row] = v.w;
        }

        float* tmp = hcur; hcur = hnxt; hnxt = tmp;
    }
}

extern "C" void kernel_launch(void* const* d_in, const int* in_sizes, int n_in,
                              void* d_out, int out_size) {
    const float* x    = (const float*)d_in[0];
    const float* emb  = (const float*)d_in[1];
    const float* sos  = (const float*)d_in[2];
    const float* Wi2h = (const float*)d_in[3];
    const float* bi2h = (const float*)d_in[4];
    const float* Wih  = (const float*)d_in[5];
    const float* Whh  = (const float*)d_in[6];
    const float* bih  = (const float*)d_in[7];
    const float* bhh  = (const float*)d_in[8];
    const float* Wout = (const float*)d_in[9];
    const float* bout = (const float*)d_in[10];

    const long long TOKN = (long long)B_ * L_;        // 262144
    const long long LGN  = TOKN * V_;                 // 67108864
    const long long os   = (long long)out_size;

    float* tokf = nullptr;
    int*   toki = nullptr;
    float* lg   = nullptr;

    if (os == TOKN + LGN){           // (tokens, logits) concatenated as float32
        tokf = (float*)d_out;
        lg   = (float*)d_out + TOKN;
    } else if (os == LGN){           // logits only
        lg   = (float*)d_out;
    } else if (os == TOKN){          // tokens only (int32)
        toki = (int*)d_out;
    } else {                         // best guess
        tokf = (float*)d_out;
        lg   = (float*)d_out + TOKN;
    }

    const size_t smem = (size_t)(2 * H_ * ST + E_ * ST + MT * V_) * sizeof(float)
                      + MT * sizeof(int);
    cudaFuncSetAttribute(rnn_decoder_kernel,
                         cudaFuncAttributeMaxDynamicSharedMemorySize, (int)smem);
    rnn_decoder_kernel<<<B_ / MT, NT, smem>>>(
        x, emb, sos, Wi2h, bi2h, Wih, Whh, bih, bhh, Wout, bout,
        tokf, toki, lg);
}

// round 5
// speedup vs baseline: 1.7054x; 1.7054x over previous
#include <cuda_runtime.h>
#include <math.h>

// ---------------- problem dims ----------------
constexpr int B_  = 8192;
constexpr int L_  = 32;
constexpr int V_  = 256;
constexpr int DIN = 256;
constexpr int H_  = 512;
constexpr int E_  = 256;

constexpr int MT  = 32;    // batch rows per CTA
constexpr int NT  = 512;   // threads per CTA
constexpr int ST  = 34;    // transposed activation row stride (even for 8B loads; 2-way store conflicts only)

typedef unsigned long long ull;

// ---------------- packed f32x2 FMA: two INDEPENDENT sequential chains ----------------
__device__ __forceinline__ void ffma2(ull &d, ull a, ull b){
    asm("fma.rn.f32x2 %0, %1, %2, %0;" : "+l"(d) : "l"(a), "l"(b));
}
__device__ __forceinline__ ull dup2(float w){
    ull r; asm("mov.b64 %0, {%1, %1};" : "=l"(r) : "f"(w)); return r;
}
__device__ __forceinline__ void unpack2(ull v, float &lo, float &hi){
    asm("mov.b64 {%0, %1}, %2;" : "=f"(lo), "=f"(hi) : "l"(v));
}

// ---------------- XLA:CPU exp (Cephes-style with FMA) ----------------
__device__ __forceinline__ float xla_exp(float x){
    float c  = fminf(fmaxf(x, -88.3762626647949f), 88.3762626647950f);
    float fx = floorf(__fmaf_rn(c, 1.44269504088896341f, 0.5f));
    float t1 = __fmul_rn(0.693359375f, fx);
    float t2 = __fmul_rn(-2.12194440e-4f, fx);
    float r  = __fadd_rn(c, -t1);
    r        = __fadd_rn(r, -t2);
    float r2 = __fmul_rn(r, r);
    float y  = 1.9875691500e-4f;
    y = __fmaf_rn(y, r, 1.3981999507e-3f);
    y = __fmaf_rn(y, r, 8.3334519073e-3f);
    y = __fmaf_rn(y, r, 4.1665795894e-2f);
    y = __fmaf_rn(y, r, 1.6666665459e-1f);
    y = __fmaf_rn(y, r, 5.0000001201e-1f);
    y = __fmaf_rn(y, r2, r);
    y = __fadd_rn(y, 1.0f);
    int n = (int)fx;
    float p2n = __int_as_float((n + 127) << 23);
    return __fmul_rn(y, p2n);
}
__device__ __forceinline__ float xla_sigmoid(float x){
    float e = xla_exp(-x);
    return __fdiv_rn(1.0f, __fadd_rn(1.0f, e));
}
__device__ __forceinline__ float xla_tanh(float x){
    float ax = fabsf(x);
    float xc = fminf(fmaxf(x, -9.0f), 9.0f);
    float x2 = __fmul_rn(xc, xc);
    float np = -2.76076847742355e-16f;
    np = __fmaf_rn(np, x2, 2.00018790482477e-13f);
    np = __fmaf_rn(np, x2, -8.60467152213735e-11f);
    np = __fmaf_rn(np, x2, 5.12229709037114e-08f);
    np = __fmaf_rn(np, x2, 1.48572235717979e-05f);
    np = __fmaf_rn(np, x2, 6.37261928875436e-04f);
    np = __fmaf_rn(np, x2, 4.89352455891786e-03f);
    np = __fmul_rn(np, xc);
    float dp = 1.19825839466702e-06f;
    dp = __fmaf_rn(dp, x2, 1.18534705686654e-04f);
    dp = __fmaf_rn(dp, x2, 2.26843463243900e-03f);
    dp = __fmaf_rn(dp, x2, 4.89352518554385e-03f);
    float res = __fdiv_rn(np, dp);
    return (ax < 0.0004f) ? x : res;
}

// one k-step, 3 gates x 4 row-pairs (strict ascending-k chains per element)
#define STEP3(WX, WY, WZ, KOFF) do { \
    ull d0 = dup2(WX), d1 = dup2(WY), d2 = dup2(WZ); \
    const float* ab_ = actT + (size_t)(KOFF) * ST + row0; \
    ull a0 = *(const ull*)(ab_ + 0); ull a1 = *(const ull*)(ab_ + 2); \
    ull a2 = *(const ull*)(ab_ + 4); ull a3 = *(const ull*)(ab_ + 6); \
    ffma2(acc[0][0], a0, d0); ffma2(acc[0][1], a1, d0); ffma2(acc[0][2], a2, d0); ffma2(acc[0][3], a3, d0); \
    ffma2(acc[1][0], a0, d1); ffma2(acc[1][1], a1, d1); ffma2(acc[1][2], a2, d1); ffma2(acc[1][3], a3, d1); \
    ffma2(acc[2][0], a0, d2); ffma2(acc[2][1], a1, d2); ffma2(acc[2][2], a2, d2); ffma2(acc[2][3], a3, d2); \
} while(0)

template<int KK>
__device__ __forceinline__ void chain3(ull (&acc)[3][4],
    const float* __restrict__ W0, const float* __restrict__ W1, const float* __restrict__ W2,
    const float* __restrict__ actT, int row0)
{
#pragma unroll 1
    for (int k0 = 0; k0 < KK; k0 += 4){
        float4 w0 = *(const float4*)(W0 + k0);
        float4 w1 = *(const float4*)(W1 + k0);
        float4 w2 = *(const float4*)(W2 + k0);
        STEP3(w0.x, w1.x, w2.x, k0 + 0);
        STEP3(w0.y, w1.y, w2.y, k0 + 1);
        STEP3(w0.z, w1.z, w2.z, k0 + 2);
        STEP3(w0.w, w1.w, w2.w, k0 + 3);
    }
}

template<int KK>
__device__ __forceinline__ void chain1(ull (&acc)[4],
    const float* __restrict__ W0, const float* __restrict__ actT, int row0)
{
#pragma unroll 1
    for (int k0 = 0; k0 < KK; k0 += 4){
        float4 w0 = *(const float4*)(W0 + k0);
#pragma unroll
        for (int j = 0; j < 4; ++j){
            float wv = (j == 0) ? w0.x : (j == 1) ? w0.y : (j == 2) ? w0.z : w0.w;
            ull d0 = dup2(wv);
            const float* ab_ = actT + (size_t)(k0 + j) * ST + row0;
            ffma2(acc[0], *(const ull*)(ab_ + 0), d0);
            ffma2(acc[1], *(const ull*)(ab_ + 2), d0);
            ffma2(acc[2], *(const ull*)(ab_ + 4), d0);
            ffma2(acc[3], *(const ull*)(ab_ + 6), d0);
        }
    }
}

// smem overlay region size (floats): holds iT [256][ST] OR slog [32][256]
constexpr int OVL = (E_ * ST > MT * V_) ? E_ * ST : MT * V_;

__global__ void __launch_bounds__(NT, 1)
rnn_decoder_kernel(
    const float* __restrict__ x,    const float* __restrict__ emb,
    const float* __restrict__ sos,
    const float* __restrict__ Wi2h, const float* __restrict__ bi2h,
    const float* __restrict__ Wih,  const float* __restrict__ Whh,
    const float* __restrict__ bih,  const float* __restrict__ bhh,
    const float* __restrict__ Wout, const float* __restrict__ bout,
    float* __restrict__ tokf, int* __restrict__ toki, float* __restrict__ lg)
{
    extern __shared__ float sm[];
    float* hT0  = sm;                    // [512][ST] transposed hidden (buffer A)
    float* hT1  = hT0 + H_ * ST;         // [512][ST] buffer B
    float* iT   = hT1 + H_ * ST;         // overlay: transposed input emb [256][ST]
    float* slog = iT;                    // overlay: logits [32][256] (disjoint lifetime)
    int*   stok = (int*)(iT + OVL);      // [32]

    const int tid  = threadIdx.x;
    const int b0   = blockIdx.x * MT;
    const int cx   = tid & 127;          // gate-phase column within 128-col block
    const int row0 = (tid >> 7) * 8;     // gate-phase: 8 rows (4 pairs) per thread
    const int lane = tid & 31;
    const int wid  = tid >> 5;

    // ---- load x tile transposed into iT: iT[k][row] = x[b0+row][k] ----
    for (int q = tid; q < MT * (DIN / 4); q += NT){
        const int ch  = q & 63;
        const int row = q >> 6;
        float4 v = *(const float4*)(x + (size_t)(b0 + row) * DIN + ch * 4);
        iT[(4 * ch + 0) * ST + row] = v.x;
        iT[(4 * ch + 1) * ST + row] = v.y;
        iT[(4 * ch + 2) * ST + row] = v.z;
        iT[(4 * ch + 3) * ST + row] = v.w;
    }
    __syncthreads();

    float* hcur = hT0;
    float* hnxt = hT1;

    // ---- h0 = x @ Wi2h^T + bi2h ----
#pragma unroll 1
    for (int c = 0; c < H_; c += 128){
        const int col = c + cx;
        ull acc[4] = {};
        chain1<DIN>(acc, Wi2h + (size_t)col * DIN, iT, row0);
        const float b = bi2h[col];
#pragma unroll
        for (int p = 0; p < 4; ++p){
            float lo, hi; unpack2(acc[p], lo, hi);
            hcur[col * ST + row0 + 2 * p + 0] = __fadd_rn(lo, b);
            hcur[col * ST + row0 + 2 * p + 1] = __fadd_rn(hi, b);
        }
    }
    __syncthreads();   // h0 done reading iT

    // ---- i0 = sos broadcast (transposed) ----
    for (int q = tid; q < E_ * MT; q += NT){
        const int e = q >> 5, r = q & 31;
        iT[e * ST + r] = sos[e];
    }

    // ---- time loop ----
#pragma unroll 1
    for (int t = 0; t < L_; ++t){
        __syncthreads();   // iT + hcur ready

        // ===== GRU gates (exact sequential-k chain order) =====
#pragma unroll 1
        for (int c = 0; c < H_; c += 128){
            const int col = c + cx;
            ull gi[3][4] = {};
            ull gh[3][4] = {};
            chain3<E_>(gi, Wih + (size_t)col * E_,
                           Wih + (size_t)(col +     H_) * E_,
                           Wih + (size_t)(col + 2 * H_) * E_, iT, row0);
            chain3<H_>(gh, Whh + (size_t)col * H_,
                           Whh + (size_t)(col +     H_) * H_,
                           Whh + (size_t)(col + 2 * H_) * H_, hcur, row0);
            const float bir = bih[col], biz = bih[col + H_], bin = bih[col + 2 * H_];
            const float bhr = bhh[col], bhz = bhh[col + H_], bhn = bhh[col + 2 * H_];
#pragma unroll
            for (int p = 0; p < 4; ++p){
                float giR0, giR1, giZ0, giZ1, giN0, giN1;
                float ghR0, ghR1, ghZ0, ghZ1, ghN0, ghN1;
                unpack2(gi[0][p], giR0, giR1); unpack2(gi[1][p], giZ0, giZ1); unpack2(gi[2][p], giN0, giN1);
                unpack2(gh[0][p], ghR0, ghR1); unpack2(gh[1][p], ghZ0, ghZ1); unpack2(gh[2][p], ghN0, ghN1);
#pragma unroll
                for (int s = 0; s < 2; ++s){
                    const int row = row0 + 2 * p + s;
                    float dIR = s ? giR1 : giR0, dIZ = s ? giZ1 : giZ0, dIN = s ? giN1 : giN0;
                    float dHR = s ? ghR1 : ghR0, dHZ = s ? ghZ1 : ghZ0, dHN = s ? ghN1 : ghN0;
                    float ir = __fadd_rn(dIR, bir), hr = __fadd_rn(dHR, bhr);
                    float iz = __fadd_rn(dIZ, biz), hz = __fadd_rn(dHZ, bhz);
                    float in_ = __fadd_rn(dIN, bin), hn = __fadd_rn(dHN, bhn);
                    float rg = xla_sigmoid(__fadd_rn(ir, hr));
                    float zg = xla_sigmoid(__fadd_rn(iz, hz));
                    float npre = __fadd_rn(in_, __fmul_rn(rg, hn));
                    float n  = xla_tanh(npre);
                    float ho = hcur[col * ST + row];
                    float omz = __fadd_rn(1.0f, -zg);
                    float hv  = __fadd_rn(__fmul_rn(omz, n), __fmul_rn(zg, ho));
                    hnxt[col * ST + row] = hv;
                }
            }
        }
        __syncthreads();   // hnxt complete; iT dead -> slog may reuse it

        // ===== logits = hnxt @ Wout^T + bout : 1 col x 16 rows per thread =====
        {
            const int colA = tid & 255;
            const int r0   = (tid >> 8) * 16;   // rows [0,16) or [16,32)
            ull aA[8];
#pragma unroll
            for (int p = 0; p < 8; ++p) aA[p] = 0ULL;
            const float* WA = Wout + (size_t)colA * H_;
#pragma unroll 1
            for (int k0 = 0; k0 < H_; k0 += 4){
                float4 wa = *(const float4*)(WA + k0);
#pragma unroll
                for (int j = 0; j < 4; ++j){
                    float wav = (j == 0) ? wa.x : (j == 1) ? wa.y : (j == 2) ? wa.z : wa.w;
                    ull da = dup2(wav);
                    const float* ab_ = hnxt + (size_t)(k0 + j) * ST + r0;
#pragma unroll
                    for (int p = 0; p < 8; ++p)
                        ffma2(aA[p], *(const ull*)(ab_ + 2 * p), da);
                }
            }
            const float boA = bout[colA];
#pragma unroll
            for (int p = 0; p < 8; ++p){
                float a0, a1; unpack2(aA[p], a0, a1);
                const int rA = r0 + 2 * p, rB = rA + 1;
                float lv0 = __fadd_rn(a0, boA), lv1 = __fadd_rn(a1, boA);
                slog[rA * V_ + colA] = lv0;
                slog[rB * V_ + colA] = lv1;
                if (lg){
                    lg[(size_t)(b0 + rA) * (L_ * V_) + (size_t)t * V_ + colA] = lv0;
                    lg[(size_t)(b0 + rB) * (L_ * V_) + (size_t)t * V_ + colA] = lv1;
                }
            }
        }
        __syncthreads();   // slog complete

        // ===== argmax (first index on ties) : 16 warps x 2 rows =====
#pragma unroll
        for (int rr2 = 0; rr2 < 2; ++rr2){
            const int row = wid * 2 + rr2;
            float bv = -1e30f; int bi = 0;
#pragma unroll
            for (int j = 0; j < 8; ++j){
                const int idx = lane + 32 * j;
                float v = slog[row * V_ + idx];
                if (v > bv){ bv = v; bi = idx; }
            }
#pragma unroll
            for (int off = 16; off > 0; off >>= 1){
                float ov = __shfl_down_sync(0xffffffffu, bv, off);
                int   oi = __shfl_down_sync(0xffffffffu, bi, off);
                if (ov > bv || (ov == bv && oi < bi)){ bv = ov; bi = oi; }
            }
            if (lane == 0){
                stok[row] = bi;
                if (tokf) tokf[(size_t)(b0 + row) * L_ + t] = (float)bi;
                if (toki) toki[(size_t)(b0 + row) * L_ + t] = bi;
            }
        }
        __syncthreads();   // stok visible; slog dead -> iT may be rewritten

        // ===== gather next input (transposed): iT[e][row] = emb[stok[row]][e] =====
        for (int q = tid; q < MT * (E_ / 4); q += NT){
            const int row = q & 31;
            const int ch  = q >> 5;
            float4 v = *(const float4*)(emb + (size_t)stok[row] * E_ + ch * 4);
            iT[(4 * ch + 0) * ST + row] = v.x;
            iT[(4 * ch + 1) * ST + row] = v.y;
            iT[(4 * ch + 2) * ST + row] = v.z;
            iT[(4 * ch + 3) * ST + row] = v.w;
        }

        float* tmp = hcur; hcur = hnxt; hnxt = tmp;
    }
}

extern "C" void kernel_launch(void* const* d_in, const int* in_sizes, int n_in,
                              void* d_out, int out_size) {
    const float* x    = (const float*)d_in[0];
    const float* emb  = (const float*)d_in[1];
    const float* sos  = (const float*)d_in[2];
    const float* Wi2h = (const float*)d_in[3];
    const float* bi2h = (const float*)d_in[4];
    const float* Wih  = (const float*)d_in[5];
    const float* Whh  = (const float*)d_in[6];
    const float* bih  = (const float*)d_in[7];
    const float* bhh  = (const float*)d_in[8];
    const float* Wout = (const float*)d_in[9];
    const float* bout = (const float*)d_in[10];

    const long long TOKN = (long long)B_ * L_;        // 262144
    const long long LGN  = TOKN * V_;                 // 67108864
    const long long os   = (long long)out_size;

    float* tokf = nullptr;
    int*   toki = nullptr;
    float* lg   = nullptr;

    if (os == TOKN + LGN){           // (tokens, logits) concatenated as float32
        tokf = (float*)d_out;
        lg   = (float*)d_out + TOKN;
    } else if (os == LGN){           // logits only
        lg   = (float*)d_out;
    } else if (os == TOKN){          // tokens only (int32)
        toki = (int*)d_out;
    } else {                         // best guess
        tokf = (float*)d_out;
        lg   = (float*)d_out + TOKN;
    }

    const size_t smem = (size_t)(2 * H_ * ST + OVL) * sizeof(float) + MT * sizeof(int);
    cudaFuncSetAttribute(rnn_decoder_kernel,
                         cudaFuncAttributeMaxDynamicSharedMemorySize, (int)smem);
    rnn_decoder_kernel<<<B_ / MT, NT, smem>>>(
        x, emb, sos, Wi2h, bi2h, Wih, Whh, bih, bhh, Wout, bout,
        tokf, toki, lg);
}

// round 6
// speedup vs baseline: 3.5696x; 2.0931x over previous
#include <cuda_runtime.h>
#include <math.h>

// ---------------- problem dims ----------------
constexpr int B_  = 8192;
constexpr int L_  = 32;
constexpr int V_  = 256;
constexpr int DIN = 256;
constexpr int H_  = 512;
constexpr int E_  = 256;

constexpr int MT  = 32;    // batch rows per CTA
constexpr int NT  = 512;   // threads per CTA
constexpr int ST  = 36;    // transposed activation row stride (16B-aligned rows)

typedef unsigned long long ull;

// ---------------- transposed + lane-duplicated weight scratch ----------------
// layout: WT[k][2j] = WT[k][2j+1] = W[j][k]  (row length = 2*J floats)
__device__ float g_WihT [E_  * 2 * (3 * H_)];   // [256][3072]
__device__ float g_WhhT [H_  * 2 * (3 * H_)];   // [512][3072]
__device__ float g_WoutT[H_  * 2 * V_];         // [512][512]
__device__ float g_Wi2hT[DIN * 2 * H_];         // [256][1024]

__global__ void transpose_dup_kernel(const float* __restrict__ W,
                                     float* __restrict__ out, int J, int K){
    int k = blockIdx.x * 32 + threadIdx.x;
    int j = blockIdx.y * 8  + threadIdx.y;
    if (k < K && j < J){
        float v = W[(size_t)j * K + k];
        out[(size_t)k * (2 * J) + 2 * j]     = v;
        out[(size_t)k * (2 * J) + 2 * j + 1] = v;
    }
}

// ---------------- packed f32x2 FMA: two INDEPENDENT sequential chains ----------------
__device__ __forceinline__ void ffma2(ull &d, ull a, ull b){
    asm("fma.rn.f32x2 %0, %1, %2, %0;" : "+l"(d) : "l"(a), "l"(b));
}
__device__ __forceinline__ void unpack2(ull v, float &lo, float &hi){
    asm("mov.b64 {%0, %1}, %2;" : "=f"(lo), "=f"(hi) : "l"(v));
}

// ---------------- XLA:CPU exp/sigmoid/tanh (bit-exact emulation) ----------------
__device__ __forceinline__ float xla_exp(float x){
    float c  = fminf(fmaxf(x, -88.3762626647949f), 88.3762626647950f);
    float fx = floorf(__fmaf_rn(c, 1.44269504088896341f, 0.5f));
    float t1 = __fmul_rn(0.693359375f, fx);
    float t2 = __fmul_rn(-2.12194440e-4f, fx);
    float r  = __fadd_rn(c, -t1);
    r        = __fadd_rn(r, -t2);
    float r2 = __fmul_rn(r, r);
    float y  = 1.9875691500e-4f;
    y = __fmaf_rn(y, r, 1.3981999507e-3f);
    y = __fmaf_rn(y, r, 8.3334519073e-3f);
    y = __fmaf_rn(y, r, 4.1665795894e-2f);
    y = __fmaf_rn(y, r, 1.6666665459e-1f);
    y = __fmaf_rn(y, r, 5.0000001201e-1f);
    y = __fmaf_rn(y, r2, r);
    y = __fadd_rn(y, 1.0f);
    int n = (int)fx;
    float p2n = __int_as_float((n + 127) << 23);
    return __fmul_rn(y, p2n);
}
__device__ __forceinline__ float xla_sigmoid(float x){
    float e = xla_exp(-x);
    return __fdiv_rn(1.0f, __fadd_rn(1.0f, e));
}
__device__ __forceinline__ float xla_tanh(float x){
    float ax = fabsf(x);
    float xc = fminf(fmaxf(x, -9.0f), 9.0f);
    float x2 = __fmul_rn(xc, xc);
    float np = -2.76076847742355e-16f;
    np = __fmaf_rn(np, x2, 2.00018790482477e-13f);
    np = __fmaf_rn(np, x2, -8.60467152213735e-11f);
    np = __fmaf_rn(np, x2, 5.12229709037114e-08f);
    np = __fmaf_rn(np, x2, 1.48572235717979e-05f);
    np = __fmaf_rn(np, x2, 6.37261928875436e-04f);
    np = __fmaf_rn(np, x2, 4.89352455891786e-03f);
    np = __fmul_rn(np, xc);
    float dp = 1.19825839466702e-06f;
    dp = __fmaf_rn(dp, x2, 1.18534705686654e-04f);
    dp = __fmaf_rn(dp, x2, 2.26843463243900e-03f);
    dp = __fmaf_rn(dp, x2, 4.89352518554385e-03f);
    float res = __fdiv_rn(np, dp);
    return (ax < 0.0004f) ? x : res;
}

// 3-gate chains (strict ascending-k, one chain per (gate,row) output — bit-exact)
// weights from duplicated-transposed WT (LDG.64 {w,w} coalesced),
// activations broadcast LDS.128 pairs.
template<int KK, int WROWLEN>
__device__ __forceinline__ void chain3T(ull (&acc)[3][4],
    const float* __restrict__ wT, int col2,
    const float* __restrict__ actT, int row0)
{
#pragma unroll 1
    for (int k0 = 0; k0 < KK; k0 += 4){
#pragma unroll
        for (int j = 0; j < 4; ++j){
            const float* wr_ = wT + (size_t)(k0 + j) * WROWLEN + col2;
            ull d0 = *(const ull*)(wr_);
            ull d1 = *(const ull*)(wr_ + 2 * H_);
            ull d2 = *(const ull*)(wr_ + 4 * H_);
            const float* ab_ = actT + (size_t)(k0 + j) * ST + row0;
            ulonglong2 a01 = *(const ulonglong2*)(ab_);
            ulonglong2 a23 = *(const ulonglong2*)(ab_ + 4);
            ffma2(acc[0][0], a01.x, d0); ffma2(acc[0][1], a01.y, d0);
            ffma2(acc[0][2], a23.x, d0); ffma2(acc[0][3], a23.y, d0);
            ffma2(acc[1][0], a01.x, d1); ffma2(acc[1][1], a01.y, d1);
            ffma2(acc[1][2], a23.x, d1); ffma2(acc[1][3], a23.y, d1);
            ffma2(acc[2][0], a01.x, d2); ffma2(acc[2][1], a01.y, d2);
            ffma2(acc[2][2], a23.x, d2); ffma2(acc[2][3], a23.y, d2);
        }
    }
}

template<int KK, int WROWLEN>
__device__ __forceinline__ void chain1T(ull (&acc)[4],
    const float* __restrict__ wT, int col2,
    const float* __restrict__ actT, int row0)
{
#pragma unroll 1
    for (int k0 = 0; k0 < KK; k0 += 4){
#pragma unroll
        for (int j = 0; j < 4; ++j){
            ull d0 = *(const ull*)(wT + (size_t)(k0 + j) * WROWLEN + col2);
            const float* ab_ = actT + (size_t)(k0 + j) * ST + row0;
            ulonglong2 a01 = *(const ulonglong2*)(ab_);
            ulonglong2 a23 = *(const ulonglong2*)(ab_ + 4);
            ffma2(acc[0], a01.x, d0); ffma2(acc[1], a01.y, d0);
            ffma2(acc[2], a23.x, d0); ffma2(acc[3], a23.y, d0);
        }
    }
}

// smem overlay region size (floats): holds iT [256][ST] OR slog [32][256]
constexpr int OVL = (E_ * ST > MT * V_) ? E_ * ST : MT * V_;

__global__ void __launch_bounds__(NT, 1)
rnn_decoder_kernel(
    const float* __restrict__ x,    const float* __restrict__ emb,
    const float* __restrict__ sos,
    const float* __restrict__ bi2h,
    const float* __restrict__ bih,  const float* __restrict__ bhh,
    const float* __restrict__ bout,
    float* __restrict__ tokf, int* __restrict__ toki, float* __restrict__ lg)
{
    extern __shared__ float sm[];
    float* hT0  = sm;                    // [512][ST] transposed hidden (buffer A)
    float* hT1  = hT0 + H_ * ST;         // [512][ST] buffer B
    float* iT   = hT1 + H_ * ST;         // overlay: transposed input emb [256][ST]
    float* slog = iT;                    // overlay: logits [32][256] (disjoint lifetime)
    int*   stok = (int*)(iT + OVL);      // [32]

    const int tid  = threadIdx.x;
    const int b0   = blockIdx.x * MT;
    const int cx   = tid & 127;          // gate-phase column within 128-col block
    const int row0 = (tid >> 7) * 8;     // gate-phase: 8 rows (4 pairs) per thread
    const int lane = tid & 31;
    const int wid  = tid >> 5;

    // ---- load x tile transposed into iT: iT[k][row] = x[b0+row][k] ----
    for (int q = tid; q < MT * (DIN / 4); q += NT){
        const int ch  = q & 63;
        const int row = q >> 6;
        float4 v = *(const float4*)(x + (size_t)(b0 + row) * DIN + ch * 4);
        iT[(4 * ch + 0) * ST + row] = v.x;
        iT[(4 * ch + 1) * ST + row] = v.y;
        iT[(4 * ch + 2) * ST + row] = v.z;
        iT[(4 * ch + 3) * ST + row] = v.w;
    }
    __syncthreads();

    float* hcur = hT0;
    float* hnxt = hT1;

    // ---- h0 = x @ Wi2h^T + bi2h ----
#pragma unroll 1
    for (int c = 0; c < H_; c += 128){
        const int col = c + cx;
        ull acc[4] = {};
        chain1T<DIN, 2 * H_>(acc, g_Wi2hT, 2 * col, iT, row0);
        const float b = bi2h[col];
#pragma unroll
        for (int p = 0; p < 4; ++p){
            float lo, hi; unpack2(acc[p], lo, hi);
            hcur[col * ST + row0 + 2 * p + 0] = __fadd_rn(lo, b);
            hcur[col * ST + row0 + 2 * p + 1] = __fadd_rn(hi, b);
        }
    }
    __syncthreads();   // h0 done reading iT

    // ---- i0 = sos broadcast (transposed) ----
    for (int q = tid; q < E_ * MT; q += NT){
        const int e = q >> 5, r = q & 31;
        iT[e * ST + r] = sos[e];
    }

    // ---- time loop ----
#pragma unroll 1
    for (int t = 0; t < L_; ++t){
        __syncthreads();   // iT + hcur ready

        // ===== GRU gates (exact sequential-k chain order) =====
#pragma unroll 1
        for (int c = 0; c < H_; c += 128){
            const int col = c + cx;
            ull gi[3][4] = {};
            ull gh[3][4] = {};
            chain3T<E_, 2 * 3 * H_>(gi, g_WihT, 2 * col, iT,   row0);
            chain3T<H_, 2 * 3 * H_>(gh, g_WhhT, 2 * col, hcur, row0);
            const float bir = bih[col], biz = bih[col + H_], bin = bih[col + 2 * H_];
            const float bhr = bhh[col], bhz = bhh[col + H_], bhn = bhh[col + 2 * H_];
#pragma unroll
            for (int p = 0; p < 4; ++p){
                float giR0, giR1, giZ0, giZ1, giN0, giN1;
                float ghR0, ghR1, ghZ0, ghZ1, ghN0, ghN1;
                unpack2(gi[0][p], giR0, giR1); unpack2(gi[1][p], giZ0, giZ1); unpack2(gi[2][p], giN0, giN1);
                unpack2(gh[0][p], ghR0, ghR1); unpack2(gh[1][p], ghZ0, ghZ1); unpack2(gh[2][p], ghN0, ghN1);
#pragma unroll
                for (int s = 0; s < 2; ++s){
                    const int row = row0 + 2 * p + s;
                    float dIR = s ? giR1 : giR0, dIZ = s ? giZ1 : giZ0, dIN = s ? giN1 : giN0;
                    float dHR = s ? ghR1 : ghR0, dHZ = s ? ghZ1 : ghZ0, dHN = s ? ghN1 : ghN0;
                    float ir = __fadd_rn(dIR, bir), hr = __fadd_rn(dHR, bhr);
                    float iz = __fadd_rn(dIZ, biz), hz = __fadd_rn(dHZ, bhz);
                    float in_ = __fadd_rn(dIN, bin), hn = __fadd_rn(dHN, bhn);
                    float rg = xla_sigmoid(__fadd_rn(ir, hr));
                    float zg = xla_sigmoid(__fadd_rn(iz, hz));
                    float npre = __fadd_rn(in_, __fmul_rn(rg, hn));
                    float n  = xla_tanh(npre);
                    float ho = hcur[col * ST + row];
                    float omz = __fadd_rn(1.0f, -zg);
                    float hv  = __fadd_rn(__fmul_rn(omz, n), __fmul_rn(zg, ho));
                    hnxt[col * ST + row] = hv;
                }
            }
        }
        __syncthreads();   // hnxt complete; iT dead -> slog may reuse it

        // ===== logits = hnxt @ Wout^T + bout : 1 col x 16 rows per thread =====
        {
            const int colA = tid & 255;
            const int r0   = (tid >> 8) * 16;   // rows [0,16) or [16,32)
            ull aA[8];
#pragma unroll
            for (int p = 0; p < 8; ++p) aA[p] = 0ULL;
#pragma unroll 1
            for (int k0 = 0; k0 < H_; k0 += 4){
#pragma unroll
                for (int j = 0; j < 4; ++j){
                    ull da = *(const ull*)(g_WoutT + (size_t)(k0 + j) * (2 * V_) + 2 * colA);
                    const float* ab_ = hnxt + (size_t)(k0 + j) * ST + r0;
                    ulonglong2 a01 = *(const ulonglong2*)(ab_);
                    ulonglong2 a23 = *(const ulonglong2*)(ab_ + 4);
                    ulonglong2 a45 = *(const ulonglong2*)(ab_ + 8);
                    ulonglong2 a67 = *(const ulonglong2*)(ab_ + 12);
                    ffma2(aA[0], a01.x, da); ffma2(aA[1], a01.y, da);
                    ffma2(aA[2], a23.x, da); ffma2(aA[3], a23.y, da);
                    ffma2(aA[4], a45.x, da); ffma2(aA[5], a45.y, da);
                    ffma2(aA[6], a67.x, da); ffma2(aA[7], a67.y, da);
                }
            }
            const float boA = bout[colA];
#pragma unroll
            for (int p = 0; p < 8; ++p){
                float a0, a1; unpack2(aA[p], a0, a1);
                const int rA = r0 + 2 * p, rB = rA + 1;
                float lv0 = __fadd_rn(a0, boA), lv1 = __fadd_rn(a1, boA);
                slog[rA * V_ + colA] = lv0;
                slog[rB * V_ + colA] = lv1;
                if (lg){
                    lg[(size_t)(b0 + rA) * (L_ * V_) + (size_t)t * V_ + colA] = lv0;
                    lg[(size_t)(b0 + rB) * (L_ * V_) + (size_t)t * V_ + colA] = lv1;
                }
            }
        }
        __syncthreads();   // slog complete

        // ===== argmax (first index on ties) : 16 warps x 2 rows =====
#pragma unroll
        for (int rr2 = 0; rr2 < 2; ++rr2){
            const int row = wid * 2 + rr2;
            float bv = -1e30f; int bi = 0;
#pragma unroll
            for (int j = 0; j < 8; ++j){
                const int idx = lane + 32 * j;
                float v = slog[row * V_ + idx];
                if (v > bv){ bv = v; bi = idx; }
            }
#pragma unroll
            for (int off = 16; off > 0; off >>= 1){
                float ov = __shfl_down_sync(0xffffffffu, bv, off);
                int   oi = __shfl_down_sync(0xffffffffu, bi, off);
                if (ov > bv || (ov == bv && oi < bi)){ bv = ov; bi = oi; }
            }
            if (lane == 0){
                stok[row] = bi;
                if (tokf) tokf[(size_t)(b0 + row) * L_ + t] = (float)bi;
                if (toki) toki[(size_t)(b0 + row) * L_ + t] = bi;
            }
        }
        __syncthreads();   // stok visible; slog dead -> iT may be rewritten

        // ===== gather next input (transposed): iT[e][row] = emb[stok[row]][e] =====
        for (int q = tid; q < MT * (E_ / 4); q += NT){
            const int row = q & 31;
            const int ch  = q >> 5;
            float4 v = *(const float4*)(emb + (size_t)stok[row] * E_ + ch * 4);
            iT[(4 * ch + 0) * ST + row] = v.x;
            iT[(4 * ch + 1) * ST + row] = v.y;
            iT[(4 * ch + 2) * ST + row] = v.z;
            iT[(4 * ch + 3) * ST + row] = v.w;
        }

        float* tmp = hcur; hcur = hnxt; hnxt = tmp;
    }
}

extern "C" void kernel_launch(void* const* d_in, const int* in_sizes, int n_in,
                              void* d_out, int out_size) {
    const float* x    = (const float*)d_in[0];
    const float* emb  = (const float*)d_in[1];
    const float* sos  = (const float*)d_in[2];
    const float* Wi2h = (const float*)d_in[3];
    const float* bi2h = (const float*)d_in[4];
    const float* Wih  = (const float*)d_in[5];
    const float* Whh  = (const float*)d_in[6];
    const float* bih  = (const float*)d_in[7];
    const float* bhh  = (const float*)d_in[8];
    const float* Wout = (const float*)d_in[9];
    const float* bout = (const float*)d_in[10];

    // ---- stage transposed + duplicated weights into device scratch ----
    float *dWihT, *dWhhT, *dWoutT, *dWi2hT;
    cudaGetSymbolAddress((void**)&dWihT,  g_WihT);
    cudaGetSymbolAddress((void**)&dWhhT,  g_WhhT);
    cudaGetSymbolAddress((void**)&dWoutT, g_WoutT);
    cudaGetSymbolAddress((void**)&dWi2hT, g_Wi2hT);

    dim3 tb(32, 8);
    transpose_dup_kernel<<<dim3((256 + 31) / 32, (1536 + 7) / 8), tb>>>(Wih,  dWihT,  1536, 256);
    transpose_dup_kernel<<<dim3((512 + 31) / 32, (1536 + 7) / 8), tb>>>(Whh,  dWhhT,  1536, 512);
    transpose_dup_kernel<<<dim3((512 + 31) / 32, (256  + 7) / 8), tb>>>(Wout, dWoutT, 256,  512);
    transpose_dup_kernel<<<dim3((256 + 31) / 32, (512  + 7) / 8), tb>>>(Wi2h, dWi2hT, 512,  256);

    const long long TOKN = (long long)B_ * L_;        // 262144
    const long long LGN  = TOKN * V_;                 // 67108864
    const long long os   = (long long)out_size;

    float* tokf = nullptr;
    int*   toki = nullptr;
    float* lg   = nullptr;

    if (os == TOKN + LGN){           // (tokens, logits) concatenated as float32
        tokf = (float*)d_out;
        lg   = (float*)d_out + TOKN;
    } else if (os == LGN){           // logits only
        lg   = (float*)d_out;
    } else if (os == TOKN){          // tokens only (int32)
        toki = (int*)d_out;
    } else {                         // best guess
        tokf = (float*)d_out;
        lg   = (float*)d_out + TOKN;
    }

    const size_t smem = (size_t)(2 * H_ * ST + OVL) * sizeof(float) + MT * sizeof(int);
    cudaFuncSetAttribute(rnn_decoder_kernel,
                         cudaFuncAttributeMaxDynamicSharedMemorySize, (int)smem);
    rnn_decoder_kernel<<<B_ / MT, NT, smem>>>(
        x, emb, sos, bi2h, bih, bhh, bout,
        tokf, toki, lg);
}

// round 7
// speedup vs baseline: 3.7118x; 1.0398x over previous
#include <cuda_runtime.h>
#include <math.h>

// ---------------- problem dims ----------------
constexpr int B_  = 8192;
constexpr int L_  = 32;
constexpr int V_  = 256;
constexpr int DIN = 256;
constexpr int H_  = 512;
constexpr int E_  = 256;

constexpr int MT  = 32;    // batch rows per CTA
constexpr int NT  = 512;   // threads per CTA
constexpr int ST  = 36;    // transposed activation row stride (16B-aligned rows)

typedef unsigned long long ull;

// ---------------- paired-k, lane-duplicated weight scratch ----------------
// For k-pair p and column j, 16 bytes: {W[j][2p], W[j][2p], W[j][2p+1], W[j][2p+1]}
// Row length RL = 4*J floats.
__device__ float g_WihT [(E_  / 2) * 4 * (3 * H_)];   // 128 x 6144
__device__ float g_WhhT [(H_  / 2) * 4 * (3 * H_)];   // 256 x 6144
__device__ float g_WoutT[(H_  / 2) * 4 * V_];         // 256 x 1024
__device__ float g_Wi2hT[(DIN / 2) * 4 * H_];         // 128 x 2048

__global__ void stage_weights_kernel(
    const float* __restrict__ Wih,  const float* __restrict__ Whh,
    const float* __restrict__ Wout, const float* __restrict__ Wi2h,
    float* __restrict__ o_ih, float* __restrict__ o_hh,
    float* __restrict__ o_out, float* __restrict__ o_i2h)
{
    const long N0 = 1536L * 256, N1 = 1536L * 512, N2 = 256L * 512, N3 = 512L * 256;
    const long NTOT = N0 + N1 + N2 + N3;
    for (long e = (long)blockIdx.x * blockDim.x + threadIdx.x; e < NTOT;
         e += (long)gridDim.x * blockDim.x){
        const float* W; float* o; int J, K; long r = e;
        if (r < N0)            { W = Wih;  o = o_ih;  J = 1536; K = 256; }
        else if ((r -= N0) < N1){ W = Whh;  o = o_hh;  J = 1536; K = 512; }
        else if ((r -= N1) < N2){ W = Wout; o = o_out; J = 256;  K = 512; }
        else { r -= N2;          W = Wi2h; o = o_i2h; J = 512;  K = 256; }
        int j = (int)(r / K), k = (int)(r % K);
        float v = W[r];
        size_t base = (size_t)(k >> 1) * (4 * J) + 4 * j + 2 * (k & 1);
        o[base] = v; o[base + 1] = v;
    }
}

// ---------------- packed f32x2 FMA: two INDEPENDENT sequential chains ----------------
__device__ __forceinline__ void ffma2(ull &d, ull a, ull b){
    asm("fma.rn.f32x2 %0, %1, %2, %0;" : "+l"(d) : "l"(a), "l"(b));
}
__device__ __forceinline__ void unpack2(ull v, float &lo, float &hi){
    asm("mov.b64 {%0, %1}, %2;" : "=f"(lo), "=f"(hi) : "l"(v));
}

// ---------------- XLA:CPU exp/sigmoid/tanh (bit-exact emulation) ----------------
__device__ __forceinline__ float xla_exp(float x){
    float c  = fminf(fmaxf(x, -88.3762626647949f), 88.3762626647950f);
    float fx = floorf(__fmaf_rn(c, 1.44269504088896341f, 0.5f));
    float t1 = __fmul_rn(0.693359375f, fx);
    float t2 = __fmul_rn(-2.12194440e-4f, fx);
    float r  = __fadd_rn(c, -t1);
    r        = __fadd_rn(r, -t2);
    float r2 = __fmul_rn(r, r);
    float y  = 1.9875691500e-4f;
    y = __fmaf_rn(y, r, 1.3981999507e-3f);
    y = __fmaf_rn(y, r, 8.3334519073e-3f);
    y = __fmaf_rn(y, r, 4.1665795894e-2f);
    y = __fmaf_rn(y, r, 1.6666665459e-1f);
    y = __fmaf_rn(y, r, 5.0000001201e-1f);
    y = __fmaf_rn(y, r2, r);
    y = __fadd_rn(y, 1.0f);
    int n = (int)fx;
    float p2n = __int_as_float((n + 127) << 23);
    return __fmul_rn(y, p2n);
}
__device__ __forceinline__ float xla_sigmoid(float x){
    float e = xla_exp(-x);
    return __fdiv_rn(1.0f, __fadd_rn(1.0f, e));
}
__device__ __forceinline__ float xla_tanh(float x){
    float ax = fabsf(x);
    float xc = fminf(fmaxf(x, -9.0f), 9.0f);
    float x2 = __fmul_rn(xc, xc);
    float np = -2.76076847742355e-16f;
    np = __fmaf_rn(np, x2, 2.00018790482477e-13f);
    np = __fmaf_rn(np, x2, -8.60467152213735e-11f);
    np = __fmaf_rn(np, x2, 5.12229709037114e-08f);
    np = __fmaf_rn(np, x2, 1.48572235717979e-05f);
    np = __fmaf_rn(np, x2, 6.37261928875436e-04f);
    np = __fmaf_rn(np, x2, 4.89352455891786e-03f);
    np = __fmul_rn(np, xc);
    float dp = 1.19825839466702e-06f;
    dp = __fmaf_rn(dp, x2, 1.18534705686654e-04f);
    dp = __fmaf_rn(dp, x2, 2.26843463243900e-03f);
    dp = __fmaf_rn(dp, x2, 4.89352518554385e-03f);
    float res = __fdiv_rn(np, dp);
    return (ax < 0.0004f) ? x : res;
}

// ---- 3-gate chains, paired-k weights (LDG.128), register-double-buffered prefetch ----
// Bit-exact: strict ascending-k, one accumulator per (gate, row) output.
template<int KK, int RL>
__device__ __forceinline__ void chain3P(ull (&acc)[3][4],
    const float* __restrict__ wT, int col,
    const float* __restrict__ actT, int row0)
{
    const float* w0p = wT + 4 * col;
    const float* w1p = wT + 4 * (col + H_);
    const float* w2p = wT + 4 * (col + 2 * H_);
    constexpr int NP = KK / 2;     // k-pairs
    ulonglong2 w[2][3];
    w[0][0] = *(const ulonglong2*)(w0p);
    w[0][1] = *(const ulonglong2*)(w1p);
    w[0][2] = *(const ulonglong2*)(w2p);
    w[1][0] = *(const ulonglong2*)(w0p + RL);
    w[1][1] = *(const ulonglong2*)(w1p + RL);
    w[1][2] = *(const ulonglong2*)(w2p + RL);
#pragma unroll 1
    for (int p0 = 0; p0 < NP; p0 += 2){
        const int pn = (p0 + 2 < NP) ? p0 + 2 : p0;     // tail: redundant reload
        ulonglong2 nw[2][3];
        nw[0][0] = *(const ulonglong2*)(w0p + (size_t)pn * RL);
        nw[0][1] = *(const ulonglong2*)(w1p + (size_t)pn * RL);
        nw[0][2] = *(const ulonglong2*)(w2p + (size_t)pn * RL);
        nw[1][0] = *(const ulonglong2*)(w0p + (size_t)(pn + 1) * RL);
        nw[1][1] = *(const ulonglong2*)(w1p + (size_t)(pn + 1) * RL);
        nw[1][2] = *(const ulonglong2*)(w2p + (size_t)(pn + 1) * RL);
#pragma unroll
        for (int pp = 0; pp < 2; ++pp){
#pragma unroll
            for (int s = 0; s < 2; ++s){
                const int k = 2 * (p0 + pp) + s;
                ull d0 = s ? w[pp][0].y : w[pp][0].x;
                ull d1 = s ? w[pp][1].y : w[pp][1].x;
                ull d2 = s ? w[pp][2].y : w[pp][2].x;
                const float* ab_ = actT + (size_t)k * ST + row0;
                ulonglong2 a01 = *(const ulonglong2*)(ab_);
                ulonglong2 a23 = *(const ulonglong2*)(ab_ + 4);
                ffma2(acc[0][0], a01.x, d0); ffma2(acc[0][1], a01.y, d0);
                ffma2(acc[0][2], a23.x, d0); ffma2(acc[0][3], a23.y, d0);
                ffma2(acc[1][0], a01.x, d1); ffma2(acc[1][1], a01.y, d1);
                ffma2(acc[1][2], a23.x, d1); ffma2(acc[1][3], a23.y, d1);
                ffma2(acc[2][0], a01.x, d2); ffma2(acc[2][1], a01.y, d2);
                ffma2(acc[2][2], a23.x, d2); ffma2(acc[2][3], a23.y, d2);
            }
        }
        w[0][0] = nw[0][0]; w[0][1] = nw[0][1]; w[0][2] = nw[0][2];
        w[1][0] = nw[1][0]; w[1][1] = nw[1][1]; w[1][2] = nw[1][2];
    }
}

template<int KK, int RL>
__device__ __forceinline__ void chain1P(ull (&acc)[4],
    const float* __restrict__ wT, int col,
    const float* __restrict__ actT, int row0)
{
    const float* wp = wT + 4 * col;
    constexpr int NP = KK / 2;
    ulonglong2 w0 = *(const ulonglong2*)(wp);
    ulonglong2 w1 = *(const ulonglong2*)(wp + RL);
#pragma unroll 1
    for (int p0 = 0; p0 < NP; p0 += 2){
        const int pn = (p0 + 2 < NP) ? p0 + 2 : p0;
        ulonglong2 nw0 = *(const ulonglong2*)(wp + (size_t)pn * RL);
        ulonglong2 nw1 = *(const ulonglong2*)(wp + (size_t)(pn + 1) * RL);
#pragma unroll
        for (int pp = 0; pp < 2; ++pp){
            ulonglong2 wv = pp ? w1 : w0;
#pragma unroll
            for (int s = 0; s < 2; ++s){
                const int k = 2 * (p0 + pp) + s;
                ull d0 = s ? wv.y : wv.x;
                const float* ab_ = actT + (size_t)k * ST + row0;
                ulonglong2 a01 = *(const ulonglong2*)(ab_);
                ulonglong2 a23 = *(const ulonglong2*)(ab_ + 4);
                ffma2(acc[0], a01.x, d0); ffma2(acc[1], a01.y, d0);
                ffma2(acc[2], a23.x, d0); ffma2(acc[3], a23.y, d0);
            }
        }
        w0 = nw0; w1 = nw1;
    }
}

// smem overlay region size (floats): holds iT [256][ST] OR slog [32][256]
constexpr int OVL = (E_ * ST > MT * V_) ? E_ * ST : MT * V_;

__global__ void __launch_bounds__(NT, 1)
rnn_decoder_kernel(
    const float* __restrict__ x,    const float* __restrict__ emb,
    const float* __restrict__ sos,
    const float* __restrict__ bi2h,
    const float* __restrict__ bih,  const float* __restrict__ bhh,
    const float* __restrict__ bout,
    float* __restrict__ tokf, int* __restrict__ toki, float* __restrict__ lg)
{
    extern __shared__ float sm[];
    float* hT0  = sm;                    // [512][ST] transposed hidden (buffer A)
    float* hT1  = hT0 + H_ * ST;         // [512][ST] buffer B
    float* iT   = hT1 + H_ * ST;         // overlay: transposed input emb [256][ST]
    float* slog = iT;                    // overlay: logits [32][256]
    int*   stok = (int*)(iT + OVL);      // [32]

    const int tid  = threadIdx.x;
    const int b0   = blockIdx.x * MT;
    const int cx   = tid & 127;          // gate-phase column within 128-col block
    const int row0 = (tid >> 7) * 8;     // gate-phase: 8 rows (4 pairs) per thread
    const int lane = tid & 31;
    const int wid  = tid >> 5;

    // ---- load x tile transposed into iT ----
    for (int q = tid; q < MT * (DIN / 4); q += NT){
        const int ch  = q & 63;
        const int row = q >> 6;
        float4 v = *(const float4*)(x + (size_t)(b0 + row) * DIN + ch * 4);
        iT[(4 * ch + 0) * ST + row] = v.x;
        iT[(4 * ch + 1) * ST + row] = v.y;
        iT[(4 * ch + 2) * ST + row] = v.z;
        iT[(4 * ch + 3) * ST + row] = v.w;
    }
    __syncthreads();

    float* hcur = hT0;
    float* hnxt = hT1;

    // ---- h0 = x @ Wi2h^T + bi2h ----
#pragma unroll 1
    for (int c = 0; c < H_; c += 128){
        const int col = c + cx;
        ull acc[4] = {};
        chain1P<DIN, 4 * H_>(acc, g_Wi2hT, col, iT, row0);
        const float b = bi2h[col];
#pragma unroll
        for (int p = 0; p < 4; ++p){
            float lo, hi; unpack2(acc[p], lo, hi);
            hcur[col * ST + row0 + 2 * p + 0] = __fadd_rn(lo, b);
            hcur[col * ST + row0 + 2 * p + 1] = __fadd_rn(hi, b);
        }
    }
    __syncthreads();   // h0 done reading iT

    // ---- i0 = sos broadcast (transposed) ----
    for (int q = tid; q < E_ * MT; q += NT){
        const int e = q >> 5, r = q & 31;
        iT[e * ST + r] = sos[e];
    }

    // ---- time loop ----
#pragma unroll 1
    for (int t = 0; t < L_; ++t){
        __syncthreads();   // iT + hcur ready

        // ===== GRU gates (exact sequential-k chain order) =====
#pragma unroll 1
        for (int c = 0; c < H_; c += 128){
            const int col = c + cx;
            ull gi[3][4] = {};
            ull gh[3][4] = {};
            chain3P<E_, 4 * 3 * H_>(gi, g_WihT, col, iT,   row0);
            chain3P<H_, 4 * 3 * H_>(gh, g_WhhT, col, hcur, row0);
            const float bir = bih[col], biz = bih[col + H_], bin = bih[col + 2 * H_];
            const float bhr = bhh[col], bhz = bhh[col + H_], bhn = bhh[col + 2 * H_];
#pragma unroll
            for (int p = 0; p < 4; ++p){
                float giR0, giR1, giZ0, giZ1, giN0, giN1;
                float ghR0, ghR1, ghZ0, ghZ1, ghN0, ghN1;
                unpack2(gi[0][p], giR0, giR1); unpack2(gi[1][p], giZ0, giZ1); unpack2(gi[2][p], giN0, giN1);
                unpack2(gh[0][p], ghR0, ghR1); unpack2(gh[1][p], ghZ0, ghZ1); unpack2(gh[2][p], ghN0, ghN1);
#pragma unroll
                for (int s = 0; s < 2; ++s){
                    const int row = row0 + 2 * p + s;
                    float dIR = s ? giR1 : giR0, dIZ = s ? giZ1 : giZ0, dIN = s ? giN1 : giN0;
                    float dHR = s ? ghR1 : ghR0, dHZ = s ? ghZ1 : ghZ0, dHN = s ? ghN1 : ghN0;
                    float ir = __fadd_rn(dIR, bir), hr = __fadd_rn(dHR, bhr);
                    float iz = __fadd_rn(dIZ, biz), hz = __fadd_rn(dHZ, bhz);
                    float in_ = __fadd_rn(dIN, bin), hn = __fadd_rn(dHN, bhn);
                    float rg = xla_sigmoid(__fadd_rn(ir, hr));
                    float zg = xla_sigmoid(__fadd_rn(iz, hz));
                    float npre = __fadd_rn(in_, __fmul_rn(rg, hn));
                    float n  = xla_tanh(npre);
                    float ho = hcur[col * ST + row];
                    float omz = __fadd_rn(1.0f, -zg);
                    float hv  = __fadd_rn(__fmul_rn(omz, n), __fmul_rn(zg, ho));
                    hnxt[col * ST + row] = hv;
                }
            }
        }
        __syncthreads();   // hnxt complete; iT dead -> slog reuses it

        // ===== logits = hnxt @ Wout^T + bout : 1 col x 16 rows per thread =====
        {
            const int colA = tid & 255;
            const int r0   = (tid >> 8) * 16;   // rows [0,16) or [16,32)
            ull aA[8];
#pragma unroll
            for (int p = 0; p < 8; ++p) aA[p] = 0ULL;
            const float* wp = g_WoutT + 4 * colA;   // RL = 4*V = 1024
            ulonglong2 w0 = *(const ulonglong2*)(wp);
            ulonglong2 w1 = *(const ulonglong2*)(wp + 1024);
#pragma unroll 1
            for (int p0 = 0; p0 < H_ / 2; p0 += 2){
                const int pn = (p0 + 2 < H_ / 2) ? p0 + 2 : p0;
                ulonglong2 nw0 = *(const ulonglong2*)(wp + (size_t)pn * 1024);
                ulonglong2 nw1 = *(const ulonglong2*)(wp + (size_t)(pn + 1) * 1024);
#pragma unroll
                for (int pp = 0; pp < 2; ++pp){
                    ulonglong2 wv = pp ? w1 : w0;
#pragma unroll
                    for (int s = 0; s < 2; ++s){
                        const int k = 2 * (p0 + pp) + s;
                        ull da = s ? wv.y : wv.x;
                        const float* ab_ = hnxt + (size_t)k * ST + r0;
                        ulonglong2 a01 = *(const ulonglong2*)(ab_);
                        ulonglong2 a23 = *(const ulonglong2*)(ab_ + 4);
                        ulonglong2 a45 = *(const ulonglong2*)(ab_ + 8);
                        ulonglong2 a67 = *(const ulonglong2*)(ab_ + 12);
                        ffma2(aA[0], a01.x, da); ffma2(aA[1], a01.y, da);
                        ffma2(aA[2], a23.x, da); ffma2(aA[3], a23.y, da);
                        ffma2(aA[4], a45.x, da); ffma2(aA[5], a45.y, da);
                        ffma2(aA[6], a67.x, da); ffma2(aA[7], a67.y, da);
                    }
                }
                w0 = nw0; w1 = nw1;
            }
            const float boA = bout[colA];
#pragma unroll
            for (int p = 0; p < 8; ++p){
                float a0, a1; unpack2(aA[p], a0, a1);
                const int rA = r0 + 2 * p, rB = rA + 1;
                float lv0 = __fadd_rn(a0, boA), lv1 = __fadd_rn(a1, boA);
                slog[rA * V_ + colA] = lv0;
                slog[rB * V_ + colA] = lv1;
                if (lg){
                    lg[(size_t)(b0 + rA) * (L_ * V_) + (size_t)t * V_ + colA] = lv0;
                    lg[(size_t)(b0 + rB) * (L_ * V_) + (size_t)t * V_ + colA] = lv1;
                }
            }
        }
        __syncthreads();   // slog complete

        // ===== argmax (first index on ties) : 16 warps x 2 rows =====
#pragma unroll
        for (int rr2 = 0; rr2 < 2; ++rr2){
            const int row = wid * 2 + rr2;
            float bv = -1e30f; int bi = 0;
#pragma unroll
            for (int j = 0; j < 8; ++j){
                const int idx = lane + 32 * j;
                float v = slog[row * V_ + idx];
                if (v > bv){ bv = v; bi = idx; }
            }
#pragma unroll
            for (int off = 16; off > 0; off >>= 1){
                float ov = __shfl_down_sync(0xffffffffu, bv, off);
                int   oi = __shfl_down_sync(0xffffffffu, bi, off);
                if (ov > bv || (ov == bv && oi < bi)){ bv = ov; bi = oi; }
            }
            if (lane == 0){
                stok[row] = bi;
                if (tokf) tokf[(size_t)(b0 + row) * L_ + t] = (float)bi;
                if (toki) toki[(size_t)(b0 + row) * L_ + t] = bi;
            }
        }
        __syncthreads();   // stok visible; slog dead -> iT rewritten below

        // ===== gather next input (transposed): iT[e][row] = emb[stok[row]][e] =====
        for (int q = tid; q < MT * (E_ / 4); q += NT){
            const int row = q & 31;
            const int ch  = q >> 5;
            float4 v = *(const float4*)(emb + (size_t)stok[row] * E_ + ch * 4);
            iT[(4 * ch + 0) * ST + row] = v.x;
            iT[(4 * ch + 1) * ST + row] = v.y;
            iT[(4 * ch + 2) * ST + row] = v.z;
            iT[(4 * ch + 3) * ST + row] = v.w;
        }

        float* tmp = hcur; hcur = hnxt; hnxt = tmp;
    }
}

extern "C" void kernel_launch(void* const* d_in, const int* in_sizes, int n_in,
                              void* d_out, int out_size) {
    const float* x    = (const float*)d_in[0];
    const float* emb  = (const float*)d_in[1];
    const float* sos  = (const float*)d_in[2];
    const float* Wi2h = (const float*)d_in[3];
    const float* bi2h = (const float*)d_in[4];
    const float* Wih  = (const float*)d_in[5];
    const float* Whh  = (const float*)d_in[6];
    const float* bih  = (const float*)d_in[7];
    const float* bhh  = (const float*)d_in[8];
    const float* Wout = (const float*)d_in[9];
    const float* bout = (const float*)d_in[10];

    float *dWihT, *dWhhT, *dWoutT, *dWi2hT;
    cudaGetSymbolAddress((void**)&dWihT,  g_WihT);
    cudaGetSymbolAddress((void**)&dWhhT,  g_WhhT);
    cudaGetSymbolAddress((void**)&dWoutT, g_WoutT);
    cudaGetSymbolAddress((void**)&dWi2hT, g_Wi2hT);

    stage_weights_kernel<<<1024, 256>>>(Wih, Whh, Wout, Wi2h,
                                        dWihT, dWhhT, dWoutT, dWi2hT);

    const long long TOKN = (long long)B_ * L_;        // 262144
    const long long LGN  = TOKN * V_;                 // 67108864
    const long long os   = (long long)out_size;

    float* tokf = nullptr;
    int*   toki = nullptr;
    float* lg   = nullptr;

    if (os == TOKN + LGN){           // (tokens, logits) concatenated as float32
        tokf = (float*)d_out;
        lg   = (float*)d_out + TOKN;
    } else if (os == LGN){           // logits only
        lg   = (float*)d_out;
    } else if (os == TOKN){          // tokens only (int32)
        toki = (int*)d_out;
    } else {                         // best guess
        tokf = (float*)d_out;
        lg   = (float*)d_out + TOKN;
    }

    const size_t smem = (size_t)(2 * H_ * ST + OVL) * sizeof(float) + MT * sizeof(int);
    cudaFuncSetAttribute(rnn_decoder_kernel,
                         cudaFuncAttributeMaxDynamicSharedMemorySize, (int)smem);
    rnn_decoder_kernel<<<B_ / MT, NT, smem>>>(
        x, emb, sos, bi2h, bih, bhh, bout,
        tokf, toki, lg);
}

// round 8
// speedup vs baseline: 3.8971x; 1.0499x over previous
#include <cuda_runtime.h>
#include <math.h>

// ---------------- problem dims ----------------
constexpr int B_  = 8192;
constexpr int L_  = 32;
constexpr int V_  = 256;
constexpr int DIN = 256;
constexpr int H_  = 512;
constexpr int E_  = 256;

constexpr int MT  = 32;    // batch rows per CTA
constexpr int NT  = 512;   // threads per CTA
constexpr int ST  = 36;    // transposed activation row stride (16B-aligned rows)

typedef unsigned long long ull;

// ---------------- paired-k, lane-duplicated weight scratch ----------------
// For k-pair p and column j, 16 bytes: {W[j][2p], W[j][2p], W[j][2p+1], W[j][2p+1]}
__device__ float g_WihT [(E_  / 2) * 4 * (3 * H_)];   // 128 x 6144
__device__ float g_WhhT [(H_  / 2) * 4 * (3 * H_)];   // 256 x 6144
__device__ float g_WoutT[(H_  / 2) * 4 * V_];         // 256 x 1024
__device__ float g_Wi2hT[(DIN / 2) * 4 * H_];         // 128 x 2048

__global__ void stage_weights_kernel(
    const float* __restrict__ Wih,  const float* __restrict__ Whh,
    const float* __restrict__ Wout, const float* __restrict__ Wi2h,
    float* __restrict__ o_ih, float* __restrict__ o_hh,
    float* __restrict__ o_out, float* __restrict__ o_i2h)
{
    const long N0 = 1536L * 256, N1 = 1536L * 512, N2 = 256L * 512, N3 = 512L * 256;
    const long NTOT = N0 + N1 + N2 + N3;
    for (long e = (long)blockIdx.x * blockDim.x + threadIdx.x; e < NTOT;
         e += (long)gridDim.x * blockDim.x){
        const float* W; float* o; int J, K; long r = e;
        if (r < N0)            { W = Wih;  o = o_ih;  J = 1536; K = 256; }
        else if ((r -= N0) < N1){ W = Whh;  o = o_hh;  J = 1536; K = 512; }
        else if ((r -= N1) < N2){ W = Wout; o = o_out; J = 256;  K = 512; }
        else { r -= N2;          W = Wi2h; o = o_i2h; J = 512;  K = 256; }
        int j = (int)(r / K), k = (int)(r % K);
        float v = W[r];
        size_t base = (size_t)(k >> 1) * (4 * J) + 4 * j + 2 * (k & 1);
        o[base] = v; o[base + 1] = v;
    }
}

// ---------------- packed f32x2 FMA ----------------
__device__ __forceinline__ void ffma2(ull &d, ull a, ull b){
    asm("fma.rn.f32x2 %0, %1, %2, %0;" : "+l"(d) : "l"(a), "l"(b));
}
__device__ __forceinline__ void unpack2(ull v, float &lo, float &hi){
    asm("mov.b64 {%0, %1}, %2;" : "=f"(lo), "=f"(hi) : "l"(v));
}

// ---------------- XLA:CPU exp/sigmoid/tanh (bit-exact emulation) ----------------
__device__ __forceinline__ float xla_exp(float x){
    float c  = fminf(fmaxf(x, -88.3762626647949f), 88.3762626647950f);
    float fx = floorf(__fmaf_rn(c, 1.44269504088896341f, 0.5f));
    float t1 = __fmul_rn(0.693359375f, fx);
    float t2 = __fmul_rn(-2.12194440e-4f, fx);
    float r  = __fadd_rn(c, -t1);
    r        = __fadd_rn(r, -t2);
    float r2 = __fmul_rn(r, r);
    float y  = 1.9875691500e-4f;
    y = __fmaf_rn(y, r, 1.3981999507e-3f);
    y = __fmaf_rn(y, r, 8.3334519073e-3f);
    y = __fmaf_rn(y, r, 4.1665795894e-2f);
    y = __fmaf_rn(y, r, 1.6666665459e-1f);
    y = __fmaf_rn(y, r, 5.0000001201e-1f);
    y = __fmaf_rn(y, r2, r);
    y = __fadd_rn(y, 1.0f);
    int n = (int)fx;
    float p2n = __int_as_float((n + 127) << 23);
    return __fmul_rn(y, p2n);
}
__device__ __forceinline__ float xla_sigmoid(float x){
    float e = xla_exp(-x);
    return __fdiv_rn(1.0f, __fadd_rn(1.0f, e));
}
__device__ __forceinline__ float xla_tanh(float x){
    float ax = fabsf(x);
    float xc = fminf(fmaxf(x, -9.0f), 9.0f);
    float x2 = __fmul_rn(xc, xc);
    float np = -2.76076847742355e-16f;
    np = __fmaf_rn(np, x2, 2.00018790482477e-13f);
    np = __fmaf_rn(np, x2, -8.60467152213735e-11f);
    np = __fmaf_rn(np, x2, 5.12229709037114e-08f);
    np = __fmaf_rn(np, x2, 1.48572235717979e-05f);
    np = __fmaf_rn(np, x2, 6.37261928875436e-04f);
    np = __fmaf_rn(np, x2, 4.89352455891786e-03f);
    np = __fmul_rn(np, xc);
    float dp = 1.19825839466702e-06f;
    dp = __fmaf_rn(dp, x2, 1.18534705686654e-04f);
    dp = __fmaf_rn(dp, x2, 2.26843463243900e-03f);
    dp = __fmaf_rn(dp, x2, 4.89352518554385e-03f);
    float res = __fdiv_rn(np, dp);
    return (ax < 0.0004f) ? x : res;
}

// ---- 3-gate chain: depth-4 circular weight prefetch + activation pipeline ----
// Bit-exact: strict ascending-k, one accumulator per (gate, row) output.
template<int KK, int RL>
__device__ __forceinline__ void chain3C(ull (&acc)[3][4],
    const float* __restrict__ wT, int col,
    const float* __restrict__ actT, int row0)
{
    const float* w0p = wT + 4 * col;
    const float* w1p = wT + 4 * (col + H_);
    const float* w2p = wT + 4 * (col + 2 * H_);
    constexpr int NP = KK / 2;     // k-pairs (multiple of 4)
    ulonglong2 w[4][3];
#pragma unroll
    for (int j = 0; j < 4; ++j){
        w[j][0] = *(const ulonglong2*)(w0p + (size_t)j * RL);
        w[j][1] = *(const ulonglong2*)(w1p + (size_t)j * RL);
        w[j][2] = *(const ulonglong2*)(w2p + (size_t)j * RL);
    }
    const float* ab0 = actT + row0;
    ulonglong2 a01 = *(const ulonglong2*)(ab0);
    ulonglong2 a23 = *(const ulonglong2*)(ab0 + 4);
#pragma unroll 1
    for (int p0 = 0; p0 < NP; p0 += 4){
#pragma unroll
        for (int j = 0; j < 4; ++j){
            const int p = p0 + j;
#pragma unroll
            for (int s = 0; s < 2; ++s){
                const int k  = 2 * p + s;
                const int kn = (k + 1 < KK) ? k + 1 : 0;   // tail: harmless wrap
                const float* abn = actT + (size_t)kn * ST + row0;
                ulonglong2 na01 = *(const ulonglong2*)(abn);
                ulonglong2 na23 = *(const ulonglong2*)(abn + 4);
                ull d0 = s ? w[j][0].y : w[j][0].x;
                ull d1 = s ? w[j][1].y : w[j][1].x;
                ull d2 = s ? w[j][2].y : w[j][2].x;
                ffma2(acc[0][0], a01.x, d0); ffma2(acc[0][1], a01.y, d0);
                ffma2(acc[0][2], a23.x, d0); ffma2(acc[0][3], a23.y, d0);
                ffma2(acc[1][0], a01.x, d1); ffma2(acc[1][1], a01.y, d1);
                ffma2(acc[1][2], a23.x, d1); ffma2(acc[1][3], a23.y, d1);
                ffma2(acc[2][0], a01.x, d2); ffma2(acc[2][1], a01.y, d2);
                ffma2(acc[2][2], a23.x, d2); ffma2(acc[2][3], a23.y, d2);
                a01 = na01; a23 = na23;
            }
            const int pn = (p + 4 < NP) ? p + 4 : p;       // tail: redundant reload
            w[j][0] = *(const ulonglong2*)(w0p + (size_t)pn * RL);
            w[j][1] = *(const ulonglong2*)(w1p + (size_t)pn * RL);
            w[j][2] = *(const ulonglong2*)(w2p + (size_t)pn * RL);
        }
    }
}

// 1-gate variant (h0 GEMM, runs once) — depth-4 circular as well
template<int KK, int RL>
__device__ __forceinline__ void chain1C(ull (&acc)[4],
    const float* __restrict__ wT, int col,
    const float* __restrict__ actT, int row0)
{
    const float* wp = wT + 4 * col;
    constexpr int NP = KK / 2;
    ulonglong2 w[4];
#pragma unroll
    for (int j = 0; j < 4; ++j)
        w[j] = *(const ulonglong2*)(wp + (size_t)j * RL);
    const float* ab0 = actT + row0;
    ulonglong2 a01 = *(const ulonglong2*)(ab0);
    ulonglong2 a23 = *(const ulonglong2*)(ab0 + 4);
#pragma unroll 1
    for (int p0 = 0; p0 < NP; p0 += 4){
#pragma unroll
        for (int j = 0; j < 4; ++j){
            const int p = p0 + j;
#pragma unroll
            for (int s = 0; s < 2; ++s){
                const int k  = 2 * p + s;
                const int kn = (k + 1 < KK) ? k + 1 : 0;
                const float* abn = actT + (size_t)kn * ST + row0;
                ulonglong2 na01 = *(const ulonglong2*)(abn);
                ulonglong2 na23 = *(const ulonglong2*)(abn + 4);
                ull d0 = s ? w[j].y : w[j].x;
                ffma2(acc[0], a01.x, d0); ffma2(acc[1], a01.y, d0);
                ffma2(acc[2], a23.x, d0); ffma2(acc[3], a23.y, d0);
                a01 = na01; a23 = na23;
            }
            const int pn = (p + 4 < NP) ? p + 4 : p;
            w[j] = *(const ulonglong2*)(wp + (size_t)pn * RL);
        }
    }
}

// smem overlay region size (floats): holds iT [256][ST] OR slog [32][256]
constexpr int OVL = (E_ * ST > MT * V_) ? E_ * ST : MT * V_;

__global__ void __launch_bounds__(NT, 1)
rnn_decoder_kernel(
    const float* __restrict__ x,    const float* __restrict__ emb,
    const float* __restrict__ sos,
    const float* __restrict__ bi2h,
    const float* __restrict__ bih,  const float* __restrict__ bhh,
    const float* __restrict__ bout,
    float* __restrict__ tokf, int* __restrict__ toki, float* __restrict__ lg)
{
    extern __shared__ float sm[];
    float* hT0  = sm;                    // [512][ST] transposed hidden (buffer A)
    float* hT1  = hT0 + H_ * ST;         // [512][ST] buffer B
    float* iT   = hT1 + H_ * ST;         // overlay: transposed input emb [256][ST]
    float* slog = iT;                    // overlay: logits [32][256]
    int*   stok = (int*)(iT + OVL);      // [32]

    const int tid  = threadIdx.x;
    const int b0   = blockIdx.x * MT;
    const int cx   = tid & 127;          // gate-phase column within 128-col block
    const int row0 = (tid >> 7) * 8;     // gate-phase: 8 rows (4 pairs) per thread
    const int lane = tid & 31;
    const int wid  = tid >> 5;

    // ---- load x tile transposed into iT ----
    for (int q = tid; q < MT * (DIN / 4); q += NT){
        const int ch  = q & 63;
        const int row = q >> 6;
        float4 v = *(const float4*)(x + (size_t)(b0 + row) * DIN + ch * 4);
        iT[(4 * ch + 0) * ST + row] = v.x;
        iT[(4 * ch + 1) * ST + row] = v.y;
        iT[(4 * ch + 2) * ST + row] = v.z;
        iT[(4 * ch + 3) * ST + row] = v.w;
    }
    __syncthreads();

    float* hcur = hT0;
    float* hnxt = hT1;

    // ---- h0 = x @ Wi2h^T + bi2h ----
#pragma unroll 1
    for (int c = 0; c < H_; c += 128){
        const int col = c + cx;
        ull acc[4] = {};
        chain1C<DIN, 4 * H_>(acc, g_Wi2hT, col, iT, row0);
        const float b = bi2h[col];
#pragma unroll
        for (int p = 0; p < 4; ++p){
            float lo, hi; unpack2(acc[p], lo, hi);
            hcur[col * ST + row0 + 2 * p + 0] = __fadd_rn(lo, b);
            hcur[col * ST + row0 + 2 * p + 1] = __fadd_rn(hi, b);
        }
    }
    __syncthreads();   // h0 done reading iT

    // ---- i0 = sos broadcast (transposed) ----
    for (int q = tid; q < E_ * MT; q += NT){
        const int e = q >> 5, r = q & 31;
        iT[e * ST + r] = sos[e];
    }

    // ---- time loop ----
#pragma unroll 1
    for (int t = 0; t < L_; ++t){
        __syncthreads();   // iT + hcur ready

        // ===== GRU gates (exact sequential-k chain order) =====
#pragma unroll 1
        for (int c = 0; c < H_; c += 128){
            const int col = c + cx;
            ull gi[3][4] = {};
            ull gh[3][4] = {};
            chain3C<E_, 4 * 3 * H_>(gi, g_WihT, col, iT,   row0);
            chain3C<H_, 4 * 3 * H_>(gh, g_WhhT, col, hcur, row0);
            const float bir = bih[col], biz = bih[col + H_], bin = bih[col + 2 * H_];
            const float bhr = bhh[col], bhz = bhh[col + H_], bhn = bhh[col + 2 * H_];
#pragma unroll
            for (int p = 0; p < 4; ++p){
                float giR0, giR1, giZ0, giZ1, giN0, giN1;
                float ghR0, ghR1, ghZ0, ghZ1, ghN0, ghN1;
                unpack2(gi[0][p], giR0, giR1); unpack2(gi[1][p], giZ0, giZ1); unpack2(gi[2][p], giN0, giN1);
                unpack2(gh[0][p], ghR0, ghR1); unpack2(gh[1][p], ghZ0, ghZ1); unpack2(gh[2][p], ghN0, ghN1);
#pragma unroll
                for (int s = 0; s < 2; ++s){
                    const int row = row0 + 2 * p + s;
                    float dIR = s ? giR1 : giR0, dIZ = s ? giZ1 : giZ0, dIN = s ? giN1 : giN0;
                    float dHR = s ? ghR1 : ghR0, dHZ = s ? ghZ1 : ghZ0, dHN = s ? ghN1 : ghN0;
                    float ir = __fadd_rn(dIR, bir), hr = __fadd_rn(dHR, bhr);
                    float iz = __fadd_rn(dIZ, biz), hz = __fadd_rn(dHZ, bhz);
                    float in_ = __fadd_rn(dIN, bin), hn = __fadd_rn(dHN, bhn);
                    float rg = xla_sigmoid(__fadd_rn(ir, hr));
                    float zg = xla_sigmoid(__fadd_rn(iz, hz));
                    float npre = __fadd_rn(in_, __fmul_rn(rg, hn));
                    float n  = xla_tanh(npre);
                    float ho = hcur[col * ST + row];
                    float omz = __fadd_rn(1.0f, -zg);
                    float hv  = __fadd_rn(__fmul_rn(omz, n), __fmul_rn(zg, ho));
                    hnxt[col * ST + row] = hv;
                }
            }
        }
        __syncthreads();   // hnxt complete; iT dead -> slog reuses it

        // ===== logits = hnxt @ Wout^T + bout : 1 col x 16 rows per thread =====
        {
            const int colA = tid & 255;
            const int r0   = (tid >> 8) * 16;   // rows [0,16) or [16,32)
            ull aA[8];
#pragma unroll
            for (int p = 0; p < 8; ++p) aA[p] = 0ULL;
            const float* wp = g_WoutT + 4 * colA;   // RL = 4*V = 1024
            constexpr int NPL = H_ / 2;
            ulonglong2 w[4];
#pragma unroll
            for (int j = 0; j < 4; ++j)
                w[j] = *(const ulonglong2*)(wp + (size_t)j * 1024);
            const float* ab0 = hnxt + r0;
            ulonglong2 a01 = *(const ulonglong2*)(ab0);
            ulonglong2 a23 = *(const ulonglong2*)(ab0 + 4);
            ulonglong2 a45 = *(const ulonglong2*)(ab0 + 8);
            ulonglong2 a67 = *(const ulonglong2*)(ab0 + 12);
#pragma unroll 1
            for (int p0 = 0; p0 < NPL; p0 += 4){
#pragma unroll
                for (int j = 0; j < 4; ++j){
                    const int p = p0 + j;
#pragma unroll
                    for (int s = 0; s < 2; ++s){
                        const int k  = 2 * p + s;
                        const int kn = (k + 1 < H_) ? k + 1 : 0;
                        const float* abn = hnxt + (size_t)kn * ST + r0;
                        ulonglong2 na01 = *(const ulonglong2*)(abn);
                        ulonglong2 na23 = *(const ulonglong2*)(abn + 4);
                        ulonglong2 na45 = *(const ulonglong2*)(abn + 8);
                        ulonglong2 na67 = *(const ulonglong2*)(abn + 12);
                        ull da = s ? w[j].y : w[j].x;
                        ffma2(aA[0], a01.x, da); ffma2(aA[1], a01.y, da);
                        ffma2(aA[2], a23.x, da); ffma2(aA[3], a23.y, da);
                        ffma2(aA[4], a45.x, da); ffma2(aA[5], a45.y, da);
                        ffma2(aA[6], a67.x, da); ffma2(aA[7], a67.y, da);
                        a01 = na01; a23 = na23; a45 = na45; a67 = na67;
                    }
                    const int pn = (p + 4 < NPL) ? p + 4 : p;
                    w[j] = *(const ulonglong2*)(wp + (size_t)pn * 1024);
                }
            }
            const float boA = bout[colA];
#pragma unroll
            for (int p = 0; p < 8; ++p){
                float a0, a1; unpack2(aA[p], a0, a1);
                const int rA = r0 + 2 * p, rB = rA + 1;
                float lv0 = __fadd_rn(a0, boA), lv1 = __fadd_rn(a1, boA);
                slog[rA * V_ + colA] = lv0;
                slog[rB * V_ + colA] = lv1;
                if (lg){
                    lg[(size_t)(b0 + rA) * (L_ * V_) + (size_t)t * V_ + colA] = lv0;
                    lg[(size_t)(b0 + rB) * (L_ * V_) + (size_t)t * V_ + colA] = lv1;
                }
            }
        }
        __syncthreads();   // slog complete

        // ===== argmax (first index on ties) : 16 warps x 2 rows =====
#pragma unroll
        for (int rr2 = 0; rr2 < 2; ++rr2){
            const int row = wid * 2 + rr2;
            float bv = -1e30f; int bi = 0;
#pragma unroll
            for (int j = 0; j < 8; ++j){
                const int idx = lane + 32 * j;
                float v = slog[row * V_ + idx];
                if (v > bv){ bv = v; bi = idx; }
            }
#pragma unroll
            for (int off = 16; off > 0; off >>= 1){
                float ov = __shfl_down_sync(0xffffffffu, bv, off);
                int   oi = __shfl_down_sync(0xffffffffu, bi, off);
                if (ov > bv || (ov == bv && oi < bi)){ bv = ov; bi = oi; }
            }
            if (lane == 0){
                stok[row] = bi;
                if (tokf) tokf[(size_t)(b0 + row) * L_ + t] = (float)bi;
                if (toki) toki[(size_t)(b0 + row) * L_ + t] = bi;
            }
        }
        __syncthreads();   // stok visible; slog dead -> iT rewritten below

        // ===== gather next input (transposed): iT[e][row] = emb[stok[row]][e] =====
        for (int q = tid; q < MT * (E_ / 4); q += NT){
            const int row = q & 31;
            const int ch  = q >> 5;
            float4 v = *(const float4*)(emb + (size_t)stok[row] * E_ + ch * 4);
            iT[(4 * ch + 0) * ST + row] = v.x;
            iT[(4 * ch + 1) * ST + row] = v.y;
            iT[(4 * ch + 2) * ST + row] = v.z;
            iT[(4 * ch + 3) * ST + row] = v.w;
        }

        float* tmp = hcur; hcur = hnxt; hnxt = tmp;
    }
}

extern "C" void kernel_launch(void* const* d_in, const int* in_sizes, int n_in,
                              void* d_out, int out_size) {
    const float* x    = (const float*)d_in[0];
    const float* emb  = (const float*)d_in[1];
    const float* sos  = (const float*)d_in[2];
    const float* Wi2h = (const float*)d_in[3];
    const float* bi2h = (const float*)d_in[4];
    const float* Wih  = (const float*)d_in[5];
    const float* Whh  = (const float*)d_in[6];
    const float* bih  = (const float*)d_in[7];
    const float* bhh  = (const float*)d_in[8];
    const float* Wout = (const float*)d_in[9];
    const float* bout = (const float*)d_in[10];

    float *dWihT, *dWhhT, *dWoutT, *dWi2hT;
    cudaGetSymbolAddress((void**)&dWihT,  g_WihT);
    cudaGetSymbolAddress((void**)&dWhhT,  g_WhhT);
    cudaGetSymbolAddress((void**)&dWoutT, g_WoutT);
    cudaGetSymbolAddress((void**)&dWi2hT, g_Wi2hT);

    stage_weights_kernel<<<1024, 256>>>(Wih, Whh, Wout, Wi2h,
                                        dWihT, dWhhT, dWoutT, dWi2hT);

    const long long TOKN = (long long)B_ * L_;        // 262144
    const long long LGN  = TOKN * V_;                 // 67108864
    const long long os   = (long long)out_size;

    float* tokf = nullptr;
    int*   toki = nullptr;
    float* lg   = nullptr;

    if (os == TOKN + LGN){           // (tokens, logits) concatenated as float32
        tokf = (float*)d_out;
        lg   = (float*)d_out + TOKN;
    } else if (os == LGN){           // logits only
        lg   = (float*)d_out;
    } else if (os == TOKN){          // tokens only (int32)
        toki = (int*)d_out;
    } else {                         // best guess
        tokf = (float*)d_out;
        lg   = (float*)d_out + TOKN;
    }

    const size_t smem = (size_t)(2 * H_ * ST + OVL) * sizeof(float) + MT * sizeof(int);
    cudaFuncSetAttribute(rnn_decoder_kernel,
                         cudaFuncAttributeMaxDynamicSharedMemorySize, (int)smem);
    rnn_decoder_kernel<<<B_ / MT, NT, smem>>>(
        x, emb, sos, bi2h, bih, bhh, bout,
        tokf, toki, lg);
}

// round 9
// speedup vs baseline: 4.2019x; 1.0782x over previous
#include <cuda_runtime.h>
#include <math.h>

// ---------------- problem dims ----------------
constexpr int B_  = 8192;
constexpr int L_  = 32;
constexpr int V_  = 256;
constexpr int DIN = 256;
constexpr int H_  = 512;
constexpr int E_  = 256;

constexpr int MT  = 32;    // batch rows per CTA
constexpr int NT  = 512;   // threads per CTA
constexpr int ST  = 36;    // transposed activation row stride (16B-aligned rows)

typedef unsigned long long ull;

// ---------------- paired-k weight scratch (NOT duplicated) ----------------
// For k-pair p and column j, 8 bytes: {W[j][2p], W[j][2p+1]}. Row length RL = 2*J floats.
__device__ float g_WihT [(E_  / 2) * 2 * (3 * H_)];   // 128 x 3072
__device__ float g_WhhT [(H_  / 2) * 2 * (3 * H_)];   // 256 x 3072
__device__ float g_WoutT[(H_  / 2) * 2 * V_];         // 256 x 512
__device__ float g_Wi2hT[(DIN / 2) * 2 * H_];         // 128 x 1024

__global__ void stage_weights_kernel(
    const float* __restrict__ Wih,  const float* __restrict__ Whh,
    const float* __restrict__ Wout, const float* __restrict__ Wi2h,
    float* __restrict__ o_ih, float* __restrict__ o_hh,
    float* __restrict__ o_out, float* __restrict__ o_i2h)
{
    const long N0 = 1536L * 256, N1 = 1536L * 512, N2 = 256L * 512, N3 = 512L * 256;
    const long NTOT = N0 + N1 + N2 + N3;
    for (long e = (long)blockIdx.x * blockDim.x + threadIdx.x; e < NTOT;
         e += (long)gridDim.x * blockDim.x){
        const float* W; float* o; int J, K; long r = e;
        if (r < N0)            { W = Wih;  o = o_ih;  J = 1536; K = 256; }
        else if ((r -= N0) < N1){ W = Whh;  o = o_hh;  J = 1536; K = 512; }
        else if ((r -= N1) < N2){ W = Wout; o = o_out; J = 256;  K = 512; }
        else { r -= N2;          W = Wi2h; o = o_i2h; J = 512;  K = 256; }
        int j = (int)(r / K), k = (int)(r % K);
        o[(size_t)(k >> 1) * (2 * J) + 2 * j + (k & 1)] = W[r];
    }
}

// ---------------- packed f32x2 FMA ----------------
__device__ __forceinline__ void ffma2(ull &d, ull a, ull b){
    asm("fma.rn.f32x2 %0, %1, %2, %0;" : "+l"(d) : "l"(a), "l"(b));
}
__device__ __forceinline__ ull dup2(float w){
    ull r; asm("mov.b64 %0, {%1, %1};" : "=l"(r) : "f"(w)); return r;
}
__device__ __forceinline__ void unpack2(ull v, float &lo, float &hi){
    asm("mov.b64 {%0, %1}, %2;" : "=f"(lo), "=f"(hi) : "l"(v));
}

// ---------------- XLA:CPU exp/sigmoid/tanh (bit-exact emulation) ----------------
__device__ __forceinline__ float xla_exp(float x){
    float c  = fminf(fmaxf(x, -88.3762626647949f), 88.3762626647950f);
    float fx = floorf(__fmaf_rn(c, 1.44269504088896341f, 0.5f));
    float t1 = __fmul_rn(0.693359375f, fx);
    float t2 = __fmul_rn(-2.12194440e-4f, fx);
    float r  = __fadd_rn(c, -t1);
    r        = __fadd_rn(r, -t2);
    float r2 = __fmul_rn(r, r);
    float y  = 1.9875691500e-4f;
    y = __fmaf_rn(y, r, 1.3981999507e-3f);
    y = __fmaf_rn(y, r, 8.3334519073e-3f);
    y = __fmaf_rn(y, r, 4.1665795894e-2f);
    y = __fmaf_rn(y, r, 1.6666665459e-1f);
    y = __fmaf_rn(y, r, 5.0000001201e-1f);
    y = __fmaf_rn(y, r2, r);
    y = __fadd_rn(y, 1.0f);
    int n = (int)fx;
    float p2n = __int_as_float((n + 127) << 23);
    return __fmul_rn(y, p2n);
}
__device__ __forceinline__ float xla_sigmoid(float x){
    float e = xla_exp(-x);
    return __fdiv_rn(1.0f, __fadd_rn(1.0f, e));
}
__device__ __forceinline__ float xla_tanh(float x){
    float ax = fabsf(x);
    float xc = fminf(fmaxf(x, -9.0f), 9.0f);
    float x2 = __fmul_rn(xc, xc);
    float np = -2.76076847742355e-16f;
    np = __fmaf_rn(np, x2, 2.00018790482477e-13f);
    np = __fmaf_rn(np, x2, -8.60467152213735e-11f);
    np = __fmaf_rn(np, x2, 5.12229709037114e-08f);
    np = __fmaf_rn(np, x2, 1.48572235717979e-05f);
    np = __fmaf_rn(np, x2, 6.37261928875436e-04f);
    np = __fmaf_rn(np, x2, 4.89352455891786e-03f);
    np = __fmul_rn(np, xc);
    float dp = 1.19825839466702e-06f;
    dp = __fmaf_rn(dp, x2, 1.18534705686654e-04f);
    dp = __fmaf_rn(dp, x2, 2.26843463243900e-03f);
    dp = __fmaf_rn(dp, x2, 4.89352518554385e-03f);
    float res = __fdiv_rn(np, dp);
    return (ax < 0.0004f) ? x : res;
}

// ---- 3-gate chain: depth-4 circular LDG.64 weight prefetch + activation pipeline ----
// Bit-exact: strict ascending-k, one accumulator per (gate, row) output.
template<int KK, int RL>
__device__ __forceinline__ void chain3C(ull (&acc)[3][4],
    const float* __restrict__ wT, int col,
    const float* __restrict__ actT, int row0)
{
    const float* w0p = wT + 2 * col;
    const float* w1p = wT + 2 * (col + H_);
    const float* w2p = wT + 2 * (col + 2 * H_);
    constexpr int NP = KK / 2;     // k-pairs (multiple of 4)
    float2 w[4][3];
#pragma unroll
    for (int j = 0; j < 4; ++j){
        w[j][0] = *(const float2*)(w0p + (size_t)j * RL);
        w[j][1] = *(const float2*)(w1p + (size_t)j * RL);
        w[j][2] = *(const float2*)(w2p + (size_t)j * RL);
    }
    const float* ab0 = actT + row0;
    ulonglong2 a01 = *(const ulonglong2*)(ab0);
    ulonglong2 a23 = *(const ulonglong2*)(ab0 + 4);
#pragma unroll 1
    for (int p0 = 0; p0 < NP; p0 += 4){
#pragma unroll
        for (int j = 0; j < 4; ++j){
            const int p = p0 + j;
#pragma unroll
            for (int s = 0; s < 2; ++s){
                const int k  = 2 * p + s;
                const int kn = (k + 1 < KK) ? k + 1 : 0;   // tail: harmless wrap
                const float* abn = actT + (size_t)kn * ST + row0;
                ulonglong2 na01 = *(const ulonglong2*)(abn);
                ulonglong2 na23 = *(const ulonglong2*)(abn + 4);
                ull d0 = dup2(s ? w[j][0].y : w[j][0].x);
                ull d1 = dup2(s ? w[j][1].y : w[j][1].x);
                ull d2 = dup2(s ? w[j][2].y : w[j][2].x);
                ffma2(acc[0][0], a01.x, d0); ffma2(acc[0][1], a01.y, d0);
                ffma2(acc[0][2], a23.x, d0); ffma2(acc[0][3], a23.y, d0);
                ffma2(acc[1][0], a01.x, d1); ffma2(acc[1][1], a01.y, d1);
                ffma2(acc[1][2], a23.x, d1); ffma2(acc[1][3], a23.y, d1);
                ffma2(acc[2][0], a01.x, d2); ffma2(acc[2][1], a01.y, d2);
                ffma2(acc[2][2], a23.x, d2); ffma2(acc[2][3], a23.y, d2);
                a01 = na01; a23 = na23;
            }
            const int pn = (p + 4 < NP) ? p + 4 : p;       // tail: redundant reload
            w[j][0] = *(const float2*)(w0p + (size_t)pn * RL);
            w[j][1] = *(const float2*)(w1p + (size_t)pn * RL);
            w[j][2] = *(const float2*)(w2p + (size_t)pn * RL);
        }
    }
}

// 1-gate variant (h0 GEMM, runs once)
template<int KK, int RL>
__device__ __forceinline__ void chain1C(ull (&acc)[4],
    const float* __restrict__ wT, int col,
    const float* __restrict__ actT, int row0)
{
    const float* wp = wT + 2 * col;
    constexpr int NP = KK / 2;
    float2 w[4];
#pragma unroll
    for (int j = 0; j < 4; ++j)
        w[j] = *(const float2*)(wp + (size_t)j * RL);
    const float* ab0 = actT + row0;
    ulonglong2 a01 = *(const ulonglong2*)(ab0);
    ulonglong2 a23 = *(const ulonglong2*)(ab0 + 4);
#pragma unroll 1
    for (int p0 = 0; p0 < NP; p0 += 4){
#pragma unroll
        for (int j = 0; j < 4; ++j){
            const int p = p0 + j;
#pragma unroll
            for (int s = 0; s < 2; ++s){
                const int k  = 2 * p + s;
                const int kn = (k + 1 < KK) ? k + 1 : 0;
                const float* abn = actT + (size_t)kn * ST + row0;
                ulonglong2 na01 = *(const ulonglong2*)(abn);
                ulonglong2 na23 = *(const ulonglong2*)(abn + 4);
                ull d0 = dup2(s ? w[j].y : w[j].x);
                ffma2(acc[0], a01.x, d0); ffma2(acc[1], a01.y, d0);
                ffma2(acc[2], a23.x, d0); ffma2(acc[3], a23.y, d0);
                a01 = na01; a23 = na23;
            }
            const int pn = (p + 4 < NP) ? p + 4 : p;
            w[j] = *(const float2*)(wp + (size_t)pn * RL);
        }
    }
}

// smem overlay region size (floats): holds iT [256][ST] OR slog [32][256]
constexpr int OVL = (E_ * ST > MT * V_) ? E_ * ST : MT * V_;

__global__ void __launch_bounds__(NT, 1)
rnn_decoder_kernel(
    const float* __restrict__ x,    const float* __restrict__ emb,
    const float* __restrict__ sos,
    const float* __restrict__ bi2h,
    const float* __restrict__ bih,  const float* __restrict__ bhh,
    const float* __restrict__ bout,
    float* __restrict__ tokf, int* __restrict__ toki, float* __restrict__ lg)
{
    extern __shared__ float sm[];
    float* hT0  = sm;                    // [512][ST] transposed hidden (buffer A)
    float* hT1  = hT0 + H_ * ST;         // [512][ST] buffer B
    float* iT   = hT1 + H_ * ST;         // overlay: transposed input emb [256][ST]
    float* slog = iT;                    // overlay: logits [32][256]
    int*   stok = (int*)(iT + OVL);      // [32]

    const int tid  = threadIdx.x;
    const int b0   = blockIdx.x * MT;
    const int cx   = tid & 127;          // gate-phase column within 128-col block
    const int row0 = (tid >> 7) * 8;     // gate-phase: 8 rows (4 pairs) per thread
    const int lane = tid & 31;
    const int wid  = tid >> 5;

    // ---- load x tile transposed into iT ----
    for (int q = tid; q < MT * (DIN / 4); q += NT){
        const int ch  = q & 63;
        const int row = q >> 6;
        float4 v = *(const float4*)(x + (size_t)(b0 + row) * DIN + ch * 4);
        iT[(4 * ch + 0) * ST + row] = v.x;
        iT[(4 * ch + 1) * ST + row] = v.y;
        iT[(4 * ch + 2) * ST + row] = v.z;
        iT[(4 * ch + 3) * ST + row] = v.w;
    }
    __syncthreads();

    float* hcur = hT0;
    float* hnxt = hT1;

    // ---- h0 = x @ Wi2h^T + bi2h ----
#pragma unroll 1
    for (int c = 0; c < H_; c += 128){
        const int col = c + cx;
        ull acc[4] = {};
        chain1C<DIN, 2 * H_>(acc, g_Wi2hT, col, iT, row0);
        const float b = bi2h[col];
#pragma unroll
        for (int p = 0; p < 4; ++p){
            float lo, hi; unpack2(acc[p], lo, hi);
            hcur[col * ST + row0 + 2 * p + 0] = __fadd_rn(lo, b);
            hcur[col * ST + row0 + 2 * p + 1] = __fadd_rn(hi, b);
        }
    }
    __syncthreads();   // h0 done reading iT

    // ---- i0 = sos broadcast (transposed) ----
    for (int q = tid; q < E_ * MT; q += NT){
        const int e = q >> 5, r = q & 31;
        iT[e * ST + r] = sos[e];
    }

    // ---- time loop ----
#pragma unroll 1
    for (int t = 0; t < L_; ++t){
        __syncthreads();   // iT + hcur ready

        // ===== GRU gates (exact sequential-k chain order) =====
#pragma unroll 1
        for (int c = 0; c < H_; c += 128){
            const int col = c + cx;
            ull gi[3][4] = {};
            ull gh[3][4] = {};
            chain3C<E_, 2 * 3 * H_>(gi, g_WihT, col, iT,   row0);
            chain3C<H_, 2 * 3 * H_>(gh, g_WhhT, col, hcur, row0);
            const float bir = bih[col], biz = bih[col + H_], bin = bih[col + 2 * H_];
            const float bhr = bhh[col], bhz = bhh[col + H_], bhn = bhh[col + 2 * H_];
#pragma unroll
            for (int p = 0; p < 4; ++p){
                float giR0, giR1, giZ0, giZ1, giN0, giN1;
                float ghR0, ghR1, ghZ0, ghZ1, ghN0, ghN1;
                unpack2(gi[0][p], giR0, giR1); unpack2(gi[1][p], giZ0, giZ1); unpack2(gi[2][p], giN0, giN1);
                unpack2(gh[0][p], ghR0, ghR1); unpack2(gh[1][p], ghZ0, ghZ1); unpack2(gh[2][p], ghN0, ghN1);
#pragma unroll
                for (int s = 0; s < 2; ++s){
                    const int row = row0 + 2 * p + s;
                    float dIR = s ? giR1 : giR0, dIZ = s ? giZ1 : giZ0, dIN = s ? giN1 : giN0;
                    float dHR = s ? ghR1 : ghR0, dHZ = s ? ghZ1 : ghZ0, dHN = s ? ghN1 : ghN0;
                    float ir = __fadd_rn(dIR, bir), hr = __fadd_rn(dHR, bhr);
                    float iz = __fadd_rn(dIZ, biz), hz = __fadd_rn(dHZ, bhz);
                    float in_ = __fadd_rn(dIN, bin), hn = __fadd_rn(dHN, bhn);
                    float rg = xla_sigmoid(__fadd_rn(ir, hr));
                    float zg = xla_sigmoid(__fadd_rn(iz, hz));
                    float npre = __fadd_rn(in_, __fmul_rn(rg, hn));
                    float n  = xla_tanh(npre);
                    float ho = hcur[col * ST + row];
                    float omz = __fadd_rn(1.0f, -zg);
                    float hv  = __fadd_rn(__fmul_rn(omz, n), __fmul_rn(zg, ho));
                    hnxt[col * ST + row] = hv;
                }
            }
        }
        __syncthreads();   // hnxt complete; iT dead -> slog reuses it

        // ===== logits = hnxt @ Wout^T + bout : 1 col x 16 rows per thread =====
        {
            const int colA = tid & 255;
            const int r0   = (tid >> 8) * 16;   // rows [0,16) or [16,32)
            ull aA[8];
#pragma unroll
            for (int p = 0; p < 8; ++p) aA[p] = 0ULL;
            const float* wp = g_WoutT + 2 * colA;   // RL = 2*V = 512
            constexpr int NPL = H_ / 2;
            float2 w[4];
#pragma unroll
            for (int j = 0; j < 4; ++j)
                w[j] = *(const float2*)(wp + (size_t)j * 512);
            const float* ab0 = hnxt + r0;
            ulonglong2 a01 = *(const ulonglong2*)(ab0);
            ulonglong2 a23 = *(const ulonglong2*)(ab0 + 4);
            ulonglong2 a45 = *(const ulonglong2*)(ab0 + 8);
            ulonglong2 a67 = *(const ulonglong2*)(ab0 + 12);
#pragma unroll 1
            for (int p0 = 0; p0 < NPL; p0 += 4){
#pragma unroll
                for (int j = 0; j < 4; ++j){
                    const int p = p0 + j;
#pragma unroll
                    for (int s = 0; s < 2; ++s){
                        const int k  = 2 * p + s;
                        const int kn = (k + 1 < H_) ? k + 1 : 0;
                        const float* abn = hnxt + (size_t)kn * ST + r0;
                        ulonglong2 na01 = *(const ulonglong2*)(abn);
                        ulonglong2 na23 = *(const ulonglong2*)(abn + 4);
                        ulonglong2 na45 = *(const ulonglong2*)(abn + 8);
                        ulonglong2 na67 = *(const ulonglong2*)(abn + 12);
                        ull da = dup2(s ? w[j].y : w[j].x);
                        ffma2(aA[0], a01.x, da); ffma2(aA[1], a01.y, da);
                        ffma2(aA[2], a23.x, da); ffma2(aA[3], a23.y, da);
                        ffma2(aA[4], a45.x, da); ffma2(aA[5], a45.y, da);
                        ffma2(aA[6], a67.x, da); ffma2(aA[7], a67.y, da);
                        a01 = na01; a23 = na23; a45 = na45; a67 = na67;
                    }
                    const int pn = (p + 4 < NPL) ? p + 4 : p;
                    w[j] = *(const float2*)(wp + (size_t)pn * 512);
                }
            }
            const float boA = bout[colA];
#pragma unroll
            for (int p = 0; p < 8; ++p){
                float a0, a1; unpack2(aA[p], a0, a1);
                const int rA = r0 + 2 * p, rB = rA + 1;
                float lv0 = __fadd_rn(a0, boA), lv1 = __fadd_rn(a1, boA);
                slog[rA * V_ + colA] = lv0;
                slog[rB * V_ + colA] = lv1;
                if (lg){
                    lg[(size_t)(b0 + rA) * (L_ * V_) + (size_t)t * V_ + colA] = lv0;
                    lg[(size_t)(b0 + rB) * (L_ * V_) + (size_t)t * V_ + colA] = lv1;
                }
            }
        }
        __syncthreads();   // slog complete

        // ===== argmax (first index on ties) : 16 warps x 2 rows =====
#pragma unroll
        for (int rr2 = 0; rr2 < 2; ++rr2){
            const int row = wid * 2 + rr2;
            float bv = -1e30f; int bi = 0;
#pragma unroll
            for (int j = 0; j < 8; ++j){
                const int idx = lane + 32 * j;
                float v = slog[row * V_ + idx];
                if (v > bv){ bv = v; bi = idx; }
            }
#pragma unroll
            for (int off = 16; off > 0; off >>= 1){
                float ov = __shfl_down_sync(0xffffffffu, bv, off);
                int   oi = __shfl_down_sync(0xffffffffu, bi, off);
                if (ov > bv || (ov == bv && oi < bi)){ bv = ov; bi = oi; }
            }
            if (lane == 0){
                stok[row] = bi;
                if (tokf) tokf[(size_t)(b0 + row) * L_ + t] = (float)bi;
                if (toki) toki[(size_t)(b0 + row) * L_ + t] = bi;
            }
        }
        __syncthreads();   // stok visible; slog dead -> iT rewritten below

        // ===== gather next input (transposed): iT[e][row] = emb[stok[row]][e] =====
        for (int q = tid; q < MT * (E_ / 4); q += NT){
            const int row = q & 31;
            const int ch  = q >> 5;
            float4 v = *(const float4*)(emb + (size_t)stok[row] * E_ + ch * 4);
            iT[(4 * ch + 0) * ST + row] = v.x;
            iT[(4 * ch + 1) * ST + row] = v.y;
            iT[(4 * ch + 2) * ST + row] = v.z;
            iT[(4 * ch + 3) * ST + row] = v.w;
        }

        float* tmp = hcur; hcur = hnxt; hnxt = tmp;
    }
}

extern "C" void kernel_launch(void* const* d_in, const int* in_sizes, int n_in,
                              void* d_out, int out_size) {
    const float* x    = (const float*)d_in[0];
    const float* emb  = (const float*)d_in[1];
    const float* sos  = (const float*)d_in[2];
    const float* Wi2h = (const float*)d_in[3];
    const float* bi2h = (const float*)d_in[4];
    const float* Wih  = (const float*)d_in[5];
    const float* Whh  = (const float*)d_in[6];
    const float* bih  = (const float*)d_in[7];
    const float* bhh  = (const float*)d_in[8];
    const float* Wout = (const float*)d_in[9];
    const float* bout = (const float*)d_in[10];

    float *dWihT, *dWhhT, *dWoutT, *dWi2hT;
    cudaGetSymbolAddress((void**)&dWihT,  g_WihT);
    cudaGetSymbolAddress((void**)&dWhhT,  g_WhhT);
    cudaGetSymbolAddress((void**)&dWoutT, g_WoutT);
    cudaGetSymbolAddress((void**)&dWi2hT, g_Wi2hT);

    stage_weights_kernel<<<1024, 256>>>(Wih, Whh, Wout, Wi2h,
                                        dWihT, dWhhT, dWoutT, dWi2hT);

    const long long TOKN = (long long)B_ * L_;        // 262144
    const long long LGN  = TOKN * V_;                 // 67108864
    const long long os   = (long long)out_size;

    float* tokf = nullptr;
    int*   toki = nullptr;
    float* lg   = nullptr;

    if (os == TOKN + LGN){           // (tokens, logits) concatenated as float32
        tokf = (float*)d_out;
        lg   = (float*)d_out + TOKN;
    } else if (os == LGN){           // logits only
        lg   = (float*)d_out;
    } else if (os == TOKN){          // tokens only (int32)
        toki = (int*)d_out;
    } else {                         // best guess
        tokf = (float*)d_out;
        lg   = (float*)d_out + TOKN;
    }

    const size_t smem = (size_t)(2 * H_ * ST + OVL) * sizeof(float) + MT * sizeof(int);
    cudaFuncSetAttribute(rnn_decoder_kernel,
                         cudaFuncAttributeMaxDynamicSharedMemorySize, (int)smem);
    rnn_decoder_kernel<<<B_ / MT, NT, smem>>>(
        x, emb, sos, bi2h, bih, bhh, bout,
        tokf, toki, lg);
}

// round 10
// speedup vs baseline: 4.3765x; 1.0415x over previous
#include <cuda_runtime.h>
#include <math.h>

// ---------------- problem dims ----------------
constexpr int B_  = 8192;
constexpr int L_  = 32;
constexpr int V_  = 256;
constexpr int DIN = 256;
constexpr int H_  = 512;
constexpr int E_  = 256;

constexpr int MT  = 32;    // batch rows per CTA
constexpr int NT  = 512;   // threads per CTA
constexpr int ST  = 36;    // transposed activation row stride (16B-aligned rows)

typedef unsigned long long ull;

// ---------------- paired-k weight scratch (NOT duplicated), padded +4 pair-rows ----------------
// For k-pair p and column j, 8 bytes: {W[j][2p], W[j][2p+1]}. Row length RL = 2*J floats.
// The +4 pad rows absorb unconditional prefetch over-reads (values never used).
__device__ float g_WihT [(E_  / 2 + 4) * 2 * (3 * H_)];   // (128+4) x 3072
__device__ float g_WhhT [(H_  / 2 + 4) * 2 * (3 * H_)];   // (256+4) x 3072
__device__ float g_WoutT[(H_  / 2 + 4) * 2 * V_];         // (256+4) x 512
__device__ float g_Wi2hT[(DIN / 2 + 4) * 2 * H_];         // (128+4) x 1024

__global__ void stage_weights_kernel(
    const float* __restrict__ Wih,  const float* __restrict__ Whh,
    const float* __restrict__ Wout, const float* __restrict__ Wi2h,
    float* __restrict__ o_ih, float* __restrict__ o_hh,
    float* __restrict__ o_out, float* __restrict__ o_i2h)
{
    const long N0 = 1536L * 256, N1 = 1536L * 512, N2 = 256L * 512, N3 = 512L * 256;
    const long NTOT = N0 + N1 + N2 + N3;
    for (long e = (long)blockIdx.x * blockDim.x + threadIdx.x; e < NTOT;
         e += (long)gridDim.x * blockDim.x){
        const float* W; float* o; int J, K; long r = e;
        if (r < N0)            { W = Wih;  o = o_ih;  J = 1536; K = 256; }
        else if ((r -= N0) < N1){ W = Whh;  o = o_hh;  J = 1536; K = 512; }
        else if ((r -= N1) < N2){ W = Wout; o = o_out; J = 256;  K = 512; }
        else { r -= N2;          W = Wi2h; o = o_i2h; J = 512;  K = 256; }
        int j = (int)(r / K), k = (int)(r % K);
        o[(size_t)(k >> 1) * (2 * J) + 2 * j + (k & 1)] = W[r];
    }
}

// ---------------- packed f32x2 FMA ----------------
__device__ __forceinline__ void ffma2(ull &d, ull a, ull b){
    asm("fma.rn.f32x2 %0, %1, %2, %0;" : "+l"(d) : "l"(a), "l"(b));
}
__device__ __forceinline__ ull dup2(float w){
    ull r; asm("mov.b64 %0, {%1, %1};" : "=l"(r) : "f"(w)); return r;
}
__device__ __forceinline__ void unpack2(ull v, float &lo, float &hi){
    asm("mov.b64 {%0, %1}, %2;" : "=f"(lo), "=f"(hi) : "l"(v));
}

// ---------------- XLA:CPU exp/sigmoid/tanh (bit-exact emulation) ----------------
__device__ __forceinline__ float xla_exp(float x){
    float c  = fminf(fmaxf(x, -88.3762626647949f), 88.3762626647950f);
    float fx = floorf(__fmaf_rn(c, 1.44269504088896341f, 0.5f));
    float t1 = __fmul_rn(0.693359375f, fx);
    float t2 = __fmul_rn(-2.12194440e-4f, fx);
    float r  = __fadd_rn(c, -t1);
    r        = __fadd_rn(r, -t2);
    float r2 = __fmul_rn(r, r);
    float y  = 1.9875691500e-4f;
    y = __fmaf_rn(y, r, 1.3981999507e-3f);
    y = __fmaf_rn(y, r, 8.3334519073e-3f);
    y = __fmaf_rn(y, r, 4.1665795894e-2f);
    y = __fmaf_rn(y, r, 1.6666665459e-1f);
    y = __fmaf_rn(y, r, 5.0000001201e-1f);
    y = __fmaf_rn(y, r2, r);
    y = __fadd_rn(y, 1.0f);
    int n = (int)fx;
    float p2n = __int_as_float((n + 127) << 23);
    return __fmul_rn(y, p2n);
}
__device__ __forceinline__ float xla_sigmoid(float x){
    float e = xla_exp(-x);
    return __fdiv_rn(1.0f, __fadd_rn(1.0f, e));
}
__device__ __forceinline__ float xla_tanh(float x){
    float ax = fabsf(x);
    float xc = fminf(fmaxf(x, -9.0f), 9.0f);
    float x2 = __fmul_rn(xc, xc);
    float np = -2.76076847742355e-16f;
    np = __fmaf_rn(np, x2, 2.00018790482477e-13f);
    np = __fmaf_rn(np, x2, -8.60467152213735e-11f);
    np = __fmaf_rn(np, x2, 5.12229709037114e-08f);
    np = __fmaf_rn(np, x2, 1.48572235717979e-05f);
    np = __fmaf_rn(np, x2, 6.37261928875436e-04f);
    np = __fmaf_rn(np, x2, 4.89352455891786e-03f);
    np = __fmul_rn(np, xc);
    float dp = 1.19825839466702e-06f;
    dp = __fmaf_rn(dp, x2, 1.18534705686654e-04f);
    dp = __fmaf_rn(dp, x2, 2.26843463243900e-03f);
    dp = __fmaf_rn(dp, x2, 4.89352518554385e-03f);
    float res = __fdiv_rn(np, dp);
    return (ax < 0.0004f) ? x : res;
}

// ---- 3-gate chain: depth-4 circular LDG.64 weight prefetch + activation pipeline ----
// Bit-exact: strict ascending-k, one accumulator per (gate, row) output.
// Prefetches are UNCONDITIONAL (pad rows absorb over-reads; values never used).
template<int KK, int RL>
__device__ __forceinline__ void chain3C(ull (&acc)[3][4],
    const float* __restrict__ wT, int col,
    const float* __restrict__ actT, int row0)
{
    const float* w0p = wT + 2 * col;
    const float* w1p = wT + 2 * (col + H_);
    const float* w2p = wT + 2 * (col + 2 * H_);
    constexpr int NP = KK / 2;     // k-pairs (multiple of 4)
    float2 w[4][3];
#pragma unroll
    for (int j = 0; j < 4; ++j){
        w[j][0] = *(const float2*)(w0p + (size_t)j * RL);
        w[j][1] = *(const float2*)(w1p + (size_t)j * RL);
        w[j][2] = *(const float2*)(w2p + (size_t)j * RL);
    }
    const float* ab = actT + row0;
    ulonglong2 a01 = *(const ulonglong2*)(ab);
    ulonglong2 a23 = *(const ulonglong2*)(ab + 4);
#pragma unroll 1
    for (int p0 = 0; p0 < NP; p0 += 4){
#pragma unroll
        for (int j = 0; j < 4; ++j){
            const int p = p0 + j;
#pragma unroll
            for (int s = 0; s < 2; ++s){
                const int k = 2 * p + s;
                const float* abn = actT + (size_t)(k + 1) * ST + row0;   // pad row absorbs k=KK
                ulonglong2 na01 = *(const ulonglong2*)(abn);
                ulonglong2 na23 = *(const ulonglong2*)(abn + 4);
                ull d0 = dup2(s ? w[j][0].y : w[j][0].x);
                ull d1 = dup2(s ? w[j][1].y : w[j][1].x);
                ull d2 = dup2(s ? w[j][2].y : w[j][2].x);
                ffma2(acc[0][0], a01.x, d0); ffma2(acc[0][1], a01.y, d0);
                ffma2(acc[0][2], a23.x, d0); ffma2(acc[0][3], a23.y, d0);
                ffma2(acc[1][0], a01.x, d1); ffma2(acc[1][1], a01.y, d1);
                ffma2(acc[1][2], a23.x, d1); ffma2(acc[1][3], a23.y, d1);
                ffma2(acc[2][0], a01.x, d2); ffma2(acc[2][1], a01.y, d2);
                ffma2(acc[2][2], a23.x, d2); ffma2(acc[2][3], a23.y, d2);
                a01 = na01; a23 = na23;
            }
            const int pn = p + 4;                                        // pad rows absorb p>=NP
            w[j][0] = *(const float2*)(w0p + (size_t)pn * RL);
            w[j][1] = *(const float2*)(w1p + (size_t)pn * RL);
            w[j][2] = *(const float2*)(w2p + (size_t)pn * RL);
        }
    }
}

// 1-gate variant (h0 GEMM, runs once)
template<int KK, int RL>
__device__ __forceinline__ void chain1C(ull (&acc)[4],
    const float* __restrict__ wT, int col,
    const float* __restrict__ actT, int row0)
{
    const float* wp = wT + 2 * col;
    constexpr int NP = KK / 2;
    float2 w[4];
#pragma unroll
    for (int j = 0; j < 4; ++j)
        w[j] = *(const float2*)(wp + (size_t)j * RL);
    const float* ab = actT + row0;
    ulonglong2 a01 = *(const ulonglong2*)(ab);
    ulonglong2 a23 = *(const ulonglong2*)(ab + 4);
#pragma unroll 1
    for (int p0 = 0; p0 < NP; p0 += 4){
#pragma unroll
        for (int j = 0; j < 4; ++j){
            const int p = p0 + j;
#pragma unroll
            for (int s = 0; s < 2; ++s){
                const int k = 2 * p + s;
                const float* abn = actT + (size_t)(k + 1) * ST + row0;
                ulonglong2 na01 = *(const ulonglong2*)(abn);
                ulonglong2 na23 = *(const ulonglong2*)(abn + 4);
                ull d0 = dup2(s ? w[j].y : w[j].x);
                ffma2(acc[0], a01.x, d0); ffma2(acc[1], a01.y, d0);
                ffma2(acc[2], a23.x, d0); ffma2(acc[3], a23.y, d0);
                a01 = na01; a23 = na23;
            }
            w[j] = *(const float2*)(wp + (size_t)(p + 4) * RL);
        }
    }
}

// smem sizes: activation buffers have +1 pad k-row for unconditional prefetch
constexpr int HROWS = H_ + 1;   // 513
constexpr int IROWS = E_ + 1;   // 257
constexpr int OVL = (IROWS * ST > MT * V_) ? IROWS * ST : MT * V_;

__global__ void __launch_bounds__(NT, 1)
rnn_decoder_kernel(
    const float* __restrict__ x,    const float* __restrict__ emb,
    const float* __restrict__ sos,
    const float* __restrict__ bi2h,
    const float* __restrict__ bih,  const float* __restrict__ bhh,
    const float* __restrict__ bout,
    float* __restrict__ tokf, int* __restrict__ toki, float* __restrict__ lg)
{
    extern __shared__ float sm[];
    float* hT0  = sm;                    // [513][ST] transposed hidden (buffer A, +pad row)
    float* hT1  = hT0 + HROWS * ST;      // [513][ST] buffer B
    float* iT   = hT1 + HROWS * ST;      // overlay: transposed input emb [257][ST]
    float* slog = iT;                    // overlay: logits [32][256]
    int*   stok = (int*)(iT + OVL);      // [32]

    const int tid  = threadIdx.x;
    const int b0   = blockIdx.x * MT;
    const int cx   = tid & 127;          // gate-phase column within 128-col block
    const int row0 = (tid >> 7) * 8;     // gate-phase: 8 rows (4 pairs) per thread
    const int lane = tid & 31;
    const int wid  = tid >> 5;

    // ---- load x tile transposed into iT ----
    for (int q = tid; q < MT * (DIN / 4); q += NT){
        const int ch  = q & 63;
        const int row = q >> 6;
        float4 v = *(const float4*)(x + (size_t)(b0 + row) * DIN + ch * 4);
        iT[(4 * ch + 0) * ST + row] = v.x;
        iT[(4 * ch + 1) * ST + row] = v.y;
        iT[(4 * ch + 2) * ST + row] = v.z;
        iT[(4 * ch + 3) * ST + row] = v.w;
    }
    __syncthreads();

    float* hcur = hT0;
    float* hnxt = hT1;

    // ---- h0 = x @ Wi2h^T + bi2h ----
#pragma unroll 1
    for (int c = 0; c < H_; c += 128){
        const int col = c + cx;
        ull acc[4] = {};
        chain1C<DIN, 2 * H_>(acc, g_Wi2hT, col, iT, row0);
        const float b = bi2h[col];
#pragma unroll
        for (int p = 0; p < 4; ++p){
            float lo, hi; unpack2(acc[p], lo, hi);
            hcur[col * ST + row0 + 2 * p + 0] = __fadd_rn(lo, b);
            hcur[col * ST + row0 + 2 * p + 1] = __fadd_rn(hi, b);
        }
    }
    __syncthreads();   // h0 done reading iT

    // ---- i0 = sos broadcast (transposed) ----
    for (int q = tid; q < E_ * MT; q += NT){
        const int e = q >> 5, r = q & 31;
        iT[e * ST + r] = sos[e];
    }

    // ---- time loop ----
#pragma unroll 1
    for (int t = 0; t < L_; ++t){
        __syncthreads();   // iT + hcur ready

        // ===== GRU gates (exact sequential-k chain order) =====
#pragma unroll 1
        for (int c = 0; c < H_; c += 128){
            const int col = c + cx;
            ull gi[3][4] = {};
            ull gh[3][4] = {};
            chain3C<E_, 2 * 3 * H_>(gi, g_WihT, col, iT,   row0);
            chain3C<H_, 2 * 3 * H_>(gh, g_WhhT, col, hcur, row0);
            const float bir = bih[col], biz = bih[col + H_], bin = bih[col + 2 * H_];
            const float bhr = bhh[col], bhz = bhh[col + H_], bhn = bhh[col + 2 * H_];
#pragma unroll
            for (int p = 0; p < 4; ++p){
                float giR0, giR1, giZ0, giZ1, giN0, giN1;
                float ghR0, ghR1, ghZ0, ghZ1, ghN0, ghN1;
                unpack2(gi[0][p], giR0, giR1); unpack2(gi[1][p], giZ0, giZ1); unpack2(gi[2][p], giN0, giN1);
                unpack2(gh[0][p], ghR0, ghR1); unpack2(gh[1][p], ghZ0, ghZ1); unpack2(gh[2][p], ghN0, ghN1);
#pragma unroll
                for (int s = 0; s < 2; ++s){
                    const int row = row0 + 2 * p + s;
                    float dIR = s ? giR1 : giR0, dIZ = s ? giZ1 : giZ0, dIN = s ? giN1 : giN0;
                    float dHR = s ? ghR1 : ghR0, dHZ = s ? ghZ1 : ghZ0, dHN = s ? ghN1 : ghN0;
                    float ir = __fadd_rn(dIR, bir), hr = __fadd_rn(dHR, bhr);
                    float iz = __fadd_rn(dIZ, biz), hz = __fadd_rn(dHZ, bhz);
                    float in_ = __fadd_rn(dIN, bin), hn = __fadd_rn(dHN, bhn);
                    float rg = xla_sigmoid(__fadd_rn(ir, hr));
                    float zg = xla_sigmoid(__fadd_rn(iz, hz));
                    float npre = __fadd_rn(in_, __fmul_rn(rg, hn));
                    float n  = xla_tanh(npre);
                    float ho = hcur[col * ST + row];
                    float omz = __fadd_rn(1.0f, -zg);
                    float hv  = __fadd_rn(__fmul_rn(omz, n), __fmul_rn(zg, ho));
                    hnxt[col * ST + row] = hv;
                }
            }
        }
        __syncthreads();   // hnxt complete; iT dead -> slog reuses it

        // ===== logits = hnxt @ Wout^T + bout : 1 col x 16 rows per thread =====
        {
            const int colA = tid & 255;
            const int r0   = (tid >> 8) * 16;   // rows [0,16) or [16,32)
            ull aA[8];
#pragma unroll
            for (int p = 0; p < 8; ++p) aA[p] = 0ULL;
            const float* wp = g_WoutT + 2 * colA;   // RL = 2*V = 512
            constexpr int NPL = H_ / 2;
            float2 w[4];
#pragma unroll
            for (int j = 0; j < 4; ++j)
                w[j] = *(const float2*)(wp + (size_t)j * 512);
            const float* ab = hnxt + r0;
            ulonglong2 a01 = *(const ulonglong2*)(ab);
            ulonglong2 a23 = *(const ulonglong2*)(ab + 4);
            ulonglong2 a45 = *(const ulonglong2*)(ab + 8);
            ulonglong2 a67 = *(const ulonglong2*)(ab + 12);
#pragma unroll 1
            for (int p0 = 0; p0 < NPL; p0 += 4){
#pragma unroll
                for (int j = 0; j < 4; ++j){
                    const int p = p0 + j;
#pragma unroll
                    for (int s = 0; s < 2; ++s){
                        const int k = 2 * p + s;
                        const float* abn = hnxt + (size_t)(k + 1) * ST + r0;  // pad row at k=512
                        ulonglong2 na01 = *(const ulonglong2*)(abn);
                        ulonglong2 na23 = *(const ulonglong2*)(abn + 4);
                        ulonglong2 na45 = *(const ulonglong2*)(abn + 8);
                        ulonglong2 na67 = *(const ulonglong2*)(abn + 12);
                        ull da = dup2(s ? w[j].y : w[j].x);
                        ffma2(aA[0], a01.x, da); ffma2(aA[1], a01.y, da);
                        ffma2(aA[2], a23.x, da); ffma2(aA[3], a23.y, da);
                        ffma2(aA[4], a45.x, da); ffma2(aA[5], a45.y, da);
                        ffma2(aA[6], a67.x, da); ffma2(aA[7], a67.y, da);
                        a01 = na01; a23 = na23; a45 = na45; a67 = na67;
                    }
                    w[j] = *(const float2*)(wp + (size_t)(p + 4) * 512);      // pad rows absorb
                }
            }
            const float boA = bout[colA];
#pragma unroll
            for (int p = 0; p < 8; ++p){
                float a0, a1; unpack2(aA[p], a0, a1);
                const int rA = r0 + 2 * p, rB = rA + 1;
                float lv0 = __fadd_rn(a0, boA), lv1 = __fadd_rn(a1, boA);
                slog[rA * V_ + colA] = lv0;
                slog[rB * V_ + colA] = lv1;
                if (lg){
                    lg[(size_t)(b0 + rA) * (L_ * V_) + (size_t)t * V_ + colA] = lv0;
                    lg[(size_t)(b0 + rB) * (L_ * V_) + (size_t)t * V_ + colA] = lv1;
                }
            }
        }
        __syncthreads();   // slog complete

        // ===== argmax (first index on ties) : 16 warps x 2 rows =====
#pragma unroll
        for (int rr2 = 0; rr2 < 2; ++rr2){
            const int row = wid * 2 + rr2;
            float bv = -1e30f; int bi = 0;
#pragma unroll
            for (int j = 0; j < 8; ++j){
                const int idx = lane + 32 * j;
                float v = slog[row * V_ + idx];
                if (v > bv){ bv = v; bi = idx; }
            }
#pragma unroll
            for (int off = 16; off > 0; off >>= 1){
                float ov = __shfl_down_sync(0xffffffffu, bv, off);
                int   oi = __shfl_down_sync(0xffffffffu, bi, off);
                if (ov > bv || (ov == bv && oi < bi)){ bv = ov; bi = oi; }
            }
            if (lane == 0){
                stok[row] = bi;
                if (tokf) tokf[(size_t)(b0 + row) * L_ + t] = (float)bi;
                if (toki) toki[(size_t)(b0 + row) * L_ + t] = bi;
            }
        }
        __syncthreads();   // stok visible; slog dead -> iT rewritten below

        // ===== gather next input (transposed): iT[e][row] = emb[stok[row]][e] =====
        for (int q = tid; q < MT * (E_ / 4); q += NT){
            const int row = q & 31;
            const int ch  = q >> 5;
            float4 v = *(const float4*)(emb + (size_t)stok[row] * E_ + ch * 4);
            iT[(4 * ch + 0) * ST + row] = v.x;
            iT[(4 * ch + 1) * ST + row] = v.y;
            iT[(4 * ch + 2) * ST + row] = v.z;
            iT[(4 * ch + 3) * ST + row] = v.w;
        }

        float* tmp = hcur; hcur = hnxt; hnxt = tmp;
    }
}

extern "C" void kernel_launch(void* const* d_in, const int* in_sizes, int n_in,
                              void* d_out, int out_size) {
    const float* x    = (const float*)d_in[0];
    const float* emb  = (const float*)d_in[1];
    const float* sos  = (const float*)d_in[2];
    const float* Wi2h = (const float*)d_in[3];
    const float* bi2h = (const float*)d_in[4];
    const float* Wih  = (const float*)d_in[5];
    const float* Whh  = (const float*)d_in[6];
    const float* bih  = (const float*)d_in[7];
    const float* bhh  = (const float*)d_in[8];
    const float* Wout = (const float*)d_in[9];
    const float* bout = (const float*)d_in[10];

    float *dWihT, *dWhhT, *dWoutT, *dWi2hT;
    cudaGetSymbolAddress((void**)&dWihT,  g_WihT);
    cudaGetSymbolAddress((void**)&dWhhT,  g_WhhT);
    cudaGetSymbolAddress((void**)&dWoutT, g_WoutT);
    cudaGetSymbolAddress((void**)&dWi2hT, g_Wi2hT);

    stage_weights_kernel<<<1024, 256>>>(Wih, Whh, Wout, Wi2h,
                                        dWihT, dWhhT, dWoutT, dWi2hT);

    const long long TOKN = (long long)B_ * L_;        // 262144
    const long long LGN  = TOKN * V_;                 // 67108864
    const long long os   = (long long)out_size;

    float* tokf = nullptr;
    int*   toki = nullptr;
    float* lg   = nullptr;

    if (os == TOKN + LGN){           // (tokens, logits) concatenated as float32
        tokf = (float*)d_out;
        lg   = (float*)d_out + TOKN;
    } else if (os == LGN){           // logits only
        lg   = (float*)d_out;
    } else if (os == TOKN){          // tokens only (int32)
        toki = (int*)d_out;
    } else {                         // best guess
        tokf = (float*)d_out;
        lg   = (float*)d_out + TOKN;
    }

    const size_t smem = (size_t)(2 * HROWS * ST + OVL) * sizeof(float) + MT * sizeof(int);
    cudaFuncSetAttribute(rnn_decoder_kernel,
                         cudaFuncAttributeMaxDynamicSharedMemorySize, (int)smem);
    rnn_decoder_kernel<<<B_ / MT, NT, smem>>>(
        x, emb, sos, bi2h, bih, bhh, bout,
        tokf, toki, lg);
}

// round 11
// speedup vs baseline: 4.5044x; 1.0292x over previous
#include <cuda_runtime.h>
#include <math.h>

// ---------------- problem dims ----------------
constexpr int B_  = 8192;
constexpr int L_  = 32;
constexpr int V_  = 256;
constexpr int DIN = 256;
constexpr int H_  = 512;
constexpr int E_  = 256;

constexpr int MT  = 16;    // batch rows per CTA (halved: 2 CTAs/SM)
constexpr int NT  = 256;   // threads per CTA
constexpr int ST  = 20;    // transposed activation row stride (16B-aligned for row0 in {0,8})

typedef unsigned long long ull;

// ---------------- paired-k weight scratch (NOT duplicated), padded +4 pair-rows ----------------
// For k-pair p and column j, 8 bytes: {W[j][2p], W[j][2p+1]}. Row length RL = 2*J floats.
__device__ float g_WihT [(E_  / 2 + 4) * 2 * (3 * H_)];   // (128+4) x 3072
__device__ float g_WhhT [(H_  / 2 + 4) * 2 * (3 * H_)];   // (256+4) x 3072
__device__ float g_WoutT[(H_  / 2 + 4) * 2 * V_];         // (256+4) x 512
__device__ float g_Wi2hT[(DIN / 2 + 4) * 2 * H_];         // (128+4) x 1024

__global__ void stage_weights_kernel(
    const float* __restrict__ Wih,  const float* __restrict__ Whh,
    const float* __restrict__ Wout, const float* __restrict__ Wi2h,
    float* __restrict__ o_ih, float* __restrict__ o_hh,
    float* __restrict__ o_out, float* __restrict__ o_i2h)
{
    const long N0 = 1536L * 256, N1 = 1536L * 512, N2 = 256L * 512, N3 = 512L * 256;
    const long NTOT = N0 + N1 + N2 + N3;
    for (long e = (long)blockIdx.x * blockDim.x + threadIdx.x; e < NTOT;
         e += (long)gridDim.x * blockDim.x){
        const float* W; float* o; int J, K; long r = e;
        if (r < N0)            { W = Wih;  o = o_ih;  J = 1536; K = 256; }
        else if ((r -= N0) < N1){ W = Whh;  o = o_hh;  J = 1536; K = 512; }
        else if ((r -= N1) < N2){ W = Wout; o = o_out; J = 256;  K = 512; }
        else { r -= N2;          W = Wi2h; o = o_i2h; J = 512;  K = 256; }
        int j = (int)(r / K), k = (int)(r % K);
        o[(size_t)(k >> 1) * (2 * J) + 2 * j + (k & 1)] = W[r];
    }
}

// ---------------- packed f32x2 FMA ----------------
__device__ __forceinline__ void ffma2(ull &d, ull a, ull b){
    asm("fma.rn.f32x2 %0, %1, %2, %0;" : "+l"(d) : "l"(a), "l"(b));
}
__device__ __forceinline__ ull dup2(float w){
    ull r; asm("mov.b64 %0, {%1, %1};" : "=l"(r) : "f"(w)); return r;
}
__device__ __forceinline__ void unpack2(ull v, float &lo, float &hi){
    asm("mov.b64 {%0, %1}, %2;" : "=f"(lo), "=f"(hi) : "l"(v));
}

// ---------------- XLA:CPU exp/sigmoid/tanh (bit-exact emulation) ----------------
__device__ __forceinline__ float xla_exp(float x){
    float c  = fminf(fmaxf(x, -88.3762626647949f), 88.3762626647950f);
    float fx = floorf(__fmaf_rn(c, 1.44269504088896341f, 0.5f));
    float t1 = __fmul_rn(0.693359375f, fx);
    float t2 = __fmul_rn(-2.12194440e-4f, fx);
    float r  = __fadd_rn(c, -t1);
    r        = __fadd_rn(r, -t2);
    float r2 = __fmul_rn(r, r);
    float y  = 1.9875691500e-4f;
    y = __fmaf_rn(y, r, 1.3981999507e-3f);
    y = __fmaf_rn(y, r, 8.3334519073e-3f);
    y = __fmaf_rn(y, r, 4.1665795894e-2f);
    y = __fmaf_rn(y, r, 1.6666665459e-1f);
    y = __fmaf_rn(y, r, 5.0000001201e-1f);
    y = __fmaf_rn(y, r2, r);
    y = __fadd_rn(y, 1.0f);
    int n = (int)fx;
    float p2n = __int_as_float((n + 127) << 23);
    return __fmul_rn(y, p2n);
}
__device__ __forceinline__ float xla_sigmoid(float x){
    float e = xla_exp(-x);
    return __fdiv_rn(1.0f, __fadd_rn(1.0f, e));
}
__device__ __forceinline__ float xla_tanh(float x){
    float ax = fabsf(x);
    float xc = fminf(fmaxf(x, -9.0f), 9.0f);
    float x2 = __fmul_rn(xc, xc);
    float np = -2.76076847742355e-16f;
    np = __fmaf_rn(np, x2, 2.00018790482477e-13f);
    np = __fmaf_rn(np, x2, -8.60467152213735e-11f);
    np = __fmaf_rn(np, x2, 5.12229709037114e-08f);
    np = __fmaf_rn(np, x2, 1.48572235717979e-05f);
    np = __fmaf_rn(np, x2, 6.37261928875436e-04f);
    np = __fmaf_rn(np, x2, 4.89352455891786e-03f);
    np = __fmul_rn(np, xc);
    float dp = 1.19825839466702e-06f;
    dp = __fmaf_rn(dp, x2, 1.18534705686654e-04f);
    dp = __fmaf_rn(dp, x2, 2.26843463243900e-03f);
    dp = __fmaf_rn(dp, x2, 4.89352518554385e-03f);
    float res = __fdiv_rn(np, dp);
    return (ax < 0.0004f) ? x : res;
}

// ---- 3-gate chain: depth-4 circular LDG.64 weight prefetch + activation pipeline ----
// Bit-exact: strict ascending-k, one accumulator per (gate, row) output.
template<int KK, int RL>
__device__ __forceinline__ void chain3C(ull (&acc)[3][4],
    const float* __restrict__ wT, int col,
    const float* __restrict__ actT, int row0)
{
    const float* w0p = wT + 2 * col;
    const float* w1p = wT + 2 * (col + H_);
    const float* w2p = wT + 2 * (col + 2 * H_);
    constexpr int NP = KK / 2;
    float2 w[4][3];
#pragma unroll
    for (int j = 0; j < 4; ++j){
        w[j][0] = *(const float2*)(w0p + (size_t)j * RL);
        w[j][1] = *(const float2*)(w1p + (size_t)j * RL);
        w[j][2] = *(const float2*)(w2p + (size_t)j * RL);
    }
    const float* ab = actT + row0;
    ulonglong2 a01 = *(const ulonglong2*)(ab);
    ulonglong2 a23 = *(const ulonglong2*)(ab + 4);
#pragma unroll 1
    for (int p0 = 0; p0 < NP; p0 += 4){
#pragma unroll
        for (int j = 0; j < 4; ++j){
            const int p = p0 + j;
#pragma unroll
            for (int s = 0; s < 2; ++s){
                const int k = 2 * p + s;
                const float* abn = actT + (size_t)(k + 1) * ST + row0;   // pad row absorbs k=KK
                ulonglong2 na01 = *(const ulonglong2*)(abn);
                ulonglong2 na23 = *(const ulonglong2*)(abn + 4);
                ull d0 = dup2(s ? w[j][0].y : w[j][0].x);
                ull d1 = dup2(s ? w[j][1].y : w[j][1].x);
                ull d2 = dup2(s ? w[j][2].y : w[j][2].x);
                ffma2(acc[0][0], a01.x, d0); ffma2(acc[0][1], a01.y, d0);
                ffma2(acc[0][2], a23.x, d0); ffma2(acc[0][3], a23.y, d0);
                ffma2(acc[1][0], a01.x, d1); ffma2(acc[1][1], a01.y, d1);
                ffma2(acc[1][2], a23.x, d1); ffma2(acc[1][3], a23.y, d1);
                ffma2(acc[2][0], a01.x, d2); ffma2(acc[2][1], a01.y, d2);
                ffma2(acc[2][2], a23.x, d2); ffma2(acc[2][3], a23.y, d2);
                a01 = na01; a23 = na23;
            }
            const int pn = p + 4;                                        // pad rows absorb p>=NP
            w[j][0] = *(const float2*)(w0p + (size_t)pn * RL);
            w[j][1] = *(const float2*)(w1p + (size_t)pn * RL);
            w[j][2] = *(const float2*)(w2p + (size_t)pn * RL);
        }
    }
}

// 1-gate variant (h0 GEMM, runs once)
template<int KK, int RL>
__device__ __forceinline__ void chain1C(ull (&acc)[4],
    const float* __restrict__ wT, int col,
    const float* __restrict__ actT, int row0)
{
    const float* wp = wT + 2 * col;
    constexpr int NP = KK / 2;
    float2 w[4];
#pragma unroll
    for (int j = 0; j < 4; ++j)
        w[j] = *(const float2*)(wp + (size_t)j * RL);
    const float* ab = actT + row0;
    ulonglong2 a01 = *(const ulonglong2*)(ab);
    ulonglong2 a23 = *(const ulonglong2*)(ab + 4);
#pragma unroll 1
    for (int p0 = 0; p0 < NP; p0 += 4){
#pragma unroll
        for (int j = 0; j < 4; ++j){
            const int p = p0 + j;
#pragma unroll
            for (int s = 0; s < 2; ++s){
                const int k = 2 * p + s;
                const float* abn = actT + (size_t)(k + 1) * ST + row0;
                ulonglong2 na01 = *(const ulonglong2*)(abn);
                ulonglong2 na23 = *(const ulonglong2*)(abn + 4);
                ull d0 = dup2(s ? w[j].y : w[j].x);
                ffma2(acc[0], a01.x, d0); ffma2(acc[1], a01.y, d0);
                ffma2(acc[2], a23.x, d0); ffma2(acc[3], a23.y, d0);
                a01 = na01; a23 = na23;
            }
            w[j] = *(const float2*)(wp + (size_t)(p + 4) * RL);
        }
    }
}

// smem sizes: +1 pad k-row for unconditional activation prefetch
constexpr int HROWS = H_ + 1;   // 513
constexpr int IROWS = E_ + 1;   // 257
constexpr int OVL = (IROWS * ST > MT * V_) ? IROWS * ST : MT * V_;

__global__ void __launch_bounds__(NT, 2)
rnn_decoder_kernel(
    const float* __restrict__ x,    const float* __restrict__ emb,
    const float* __restrict__ sos,
    const float* __restrict__ bi2h,
    const float* __restrict__ bih,  const float* __restrict__ bhh,
    const float* __restrict__ bout,
    float* __restrict__ tokf, int* __restrict__ toki, float* __restrict__ lg)
{
    extern __shared__ float sm[];
    float* hT0  = sm;                    // [513][ST] transposed hidden (buffer A)
    float* hT1  = hT0 + HROWS * ST;      // [513][ST] buffer B
    float* iT   = hT1 + HROWS * ST;      // overlay: transposed input emb [257][ST]
    float* slog = iT;                    // overlay: logits [16][256]
    int*   stok = (int*)(iT + OVL);      // [16]

    const int tid  = threadIdx.x;
    const int b0   = blockIdx.x * MT;
    const int cx   = tid & 127;          // gate-phase column within 128-col block
    const int row0 = (tid >> 7) * 8;     // gate-phase: 2 groups x 8 rows
    const int lane = tid & 31;
    const int wid  = tid >> 5;

    // ---- load x tile transposed into iT: iT[k][row] = x[b0+row][k] ----
    for (int q = tid; q < MT * (DIN / 4); q += NT){
        const int ch  = q & 63;
        const int row = q >> 6;          // 0..15
        float4 v = *(const float4*)(x + (size_t)(b0 + row) * DIN + ch * 4);
        iT[(4 * ch + 0) * ST + row] = v.x;
        iT[(4 * ch + 1) * ST + row] = v.y;
        iT[(4 * ch + 2) * ST + row] = v.z;
        iT[(4 * ch + 3) * ST + row] = v.w;
    }
    __syncthreads();

    float* hcur = hT0;
    float* hnxt = hT1;

    // ---- h0 = x @ Wi2h^T + bi2h ----
#pragma unroll 1
    for (int c = 0; c < H_; c += 128){
        const int col = c + cx;
        ull acc[4] = {};
        chain1C<DIN, 2 * H_>(acc, g_Wi2hT, col, iT, row0);
        const float b = bi2h[col];
#pragma unroll
        for (int p = 0; p < 4; ++p){
            float lo, hi; unpack2(acc[p], lo, hi);
            hcur[col * ST + row0 + 2 * p + 0] = __fadd_rn(lo, b);
            hcur[col * ST + row0 + 2 * p + 1] = __fadd_rn(hi, b);
        }
    }
    __syncthreads();   // h0 done reading iT

    // ---- i0 = sos broadcast (transposed) ----
    for (int q = tid; q < E_ * MT; q += NT){
        const int e = q >> 4, r = q & (MT - 1);
        iT[e * ST + r] = sos[e];
    }

    // ---- time loop ----
#pragma unroll 1
    for (int t = 0; t < L_; ++t){
        __syncthreads();   // iT + hcur ready

        // ===== GRU gates (exact sequential-k chain order) =====
#pragma unroll 1
        for (int c = 0; c < H_; c += 128){
            const int col = c + cx;
            ull gi[3][4] = {};
            ull gh[3][4] = {};
            chain3C<E_, 2 * 3 * H_>(gi, g_WihT, col, iT,   row0);
            chain3C<H_, 2 * 3 * H_>(gh, g_WhhT, col, hcur, row0);
            const float bir = bih[col], biz = bih[col + H_], bin = bih[col + 2 * H_];
            const float bhr = bhh[col], bhz = bhh[col + H_], bhn = bhh[col + 2 * H_];
#pragma unroll
            for (int p = 0; p < 4; ++p){
                float giR0, giR1, giZ0, giZ1, giN0, giN1;
                float ghR0, ghR1, ghZ0, ghZ1, ghN0, ghN1;
                unpack2(gi[0][p], giR0, giR1); unpack2(gi[1][p], giZ0, giZ1); unpack2(gi[2][p], giN0, giN1);
                unpack2(gh[0][p], ghR0, ghR1); unpack2(gh[1][p], ghZ0, ghZ1); unpack2(gh[2][p], ghN0, ghN1);
#pragma unroll
                for (int s = 0; s < 2; ++s){
                    const int row = row0 + 2 * p + s;
                    float dIR = s ? giR1 : giR0, dIZ = s ? giZ1 : giZ0, dIN = s ? giN1 : giN0;
                    float dHR = s ? ghR1 : ghR0, dHZ = s ? ghZ1 : ghZ0, dHN = s ? ghN1 : ghN0;
                    float ir = __fadd_rn(dIR, bir), hr = __fadd_rn(dHR, bhr);
                    float iz = __fadd_rn(dIZ, biz), hz = __fadd_rn(dHZ, bhz);
                    float in_ = __fadd_rn(dIN, bin), hn = __fadd_rn(dHN, bhn);
                    float rg = xla_sigmoid(__fadd_rn(ir, hr));
                    float zg = xla_sigmoid(__fadd_rn(iz, hz));
                    float npre = __fadd_rn(in_, __fmul_rn(rg, hn));
                    float n  = xla_tanh(npre);
                    float ho = hcur[col * ST + row];
                    float omz = __fadd_rn(1.0f, -zg);
                    float hv  = __fadd_rn(__fmul_rn(omz, n), __fmul_rn(zg, ho));
                    hnxt[col * ST + row] = hv;
                }
            }
        }
        __syncthreads();   // hnxt complete; iT dead -> slog reuses it

        // ===== logits = hnxt @ Wout^T + bout : 1 col x 16 rows per thread =====
        {
            const int colA = tid & 255;
            const int r0   = (tid >> 8) * 16;   // 0 for NT=256
            ull aA[8];
#pragma unroll
            for (int p = 0; p < 8; ++p) aA[p] = 0ULL;
            const float* wp = g_WoutT + 2 * colA;   // RL = 2*V = 512
            constexpr int NPL = H_ / 2;
            float2 w[4];
#pragma unroll
            for (int j = 0; j < 4; ++j)
                w[j] = *(const float2*)(wp + (size_t)j * 512);
            const float* ab = hnxt + r0;
            ulonglong2 a01 = *(const ulonglong2*)(ab);
            ulonglong2 a23 = *(const ulonglong2*)(ab + 4);
            ulonglong2 a45 = *(const ulonglong2*)(ab + 8);
            ulonglong2 a67 = *(const ulonglong2*)(ab + 12);
#pragma unroll 1
            for (int p0 = 0; p0 < NPL; p0 += 4){
#pragma unroll
                for (int j = 0; j < 4; ++j){
                    const int p = p0 + j;
#pragma unroll
                    for (int s = 0; s < 2; ++s){
                        const int k = 2 * p + s;
                        const float* abn = hnxt + (size_t)(k + 1) * ST + r0;  // pad row at k=512
                        ulonglong2 na01 = *(const ulonglong2*)(abn);
                        ulonglong2 na23 = *(const ulonglong2*)(abn + 4);
                        ulonglong2 na45 = *(const ulonglong2*)(abn + 8);
                        ulonglong2 na67 = *(const ulonglong2*)(abn + 12);
                        ull da = dup2(s ? w[j].y : w[j].x);
                        ffma2(aA[0], a01.x, da); ffma2(aA[1], a01.y, da);
                        ffma2(aA[2], a23.x, da); ffma2(aA[3], a23.y, da);
                        ffma2(aA[4], a45.x, da); ffma2(aA[5], a45.y, da);
                        ffma2(aA[6], a67.x, da); ffma2(aA[7], a67.y, da);
                        a01 = na01; a23 = na23; a45 = na45; a67 = na67;
                    }
                    w[j] = *(const float2*)(wp + (size_t)(p + 4) * 512);
                }
            }
            const float boA = bout[colA];
#pragma unroll
            for (int p = 0; p < 8; ++p){
                float a0, a1; unpack2(aA[p], a0, a1);
                const int rA = r0 + 2 * p, rB = rA + 1;
                float lv0 = __fadd_rn(a0, boA), lv1 = __fadd_rn(a1, boA);
                slog[rA * V_ + colA] = lv0;
                slog[rB * V_ + colA] = lv1;
                if (lg){
                    lg[(size_t)(b0 + rA) * (L_ * V_) + (size_t)t * V_ + colA] = lv0;
                    lg[(size_t)(b0 + rB) * (L_ * V_) + (size_t)t * V_ + colA] = lv1;
                }
            }
        }
        __syncthreads();   // slog complete

        // ===== argmax (first index on ties) : 8 warps x 2 rows =====
#pragma unroll
        for (int rr2 = 0; rr2 < 2; ++rr2){
            const int row = wid * 2 + rr2;
            float bv = -1e30f; int bi = 0;
#pragma unroll
            for (int j = 0; j < 8; ++j){
                const int idx = lane + 32 * j;
                float v = slog[row * V_ + idx];
                if (v > bv){ bv = v; bi = idx; }
            }
#pragma unroll
            for (int off = 16; off > 0; off >>= 1){
                float ov = __shfl_down_sync(0xffffffffu, bv, off);
                int   oi = __shfl_down_sync(0xffffffffu, bi, off);
                if (ov > bv || (ov == bv && oi < bi)){ bv = ov; bi = oi; }
            }
            if (lane == 0){
                stok[row] = bi;
                if (tokf) tokf[(size_t)(b0 + row) * L_ + t] = (float)bi;
                if (toki) toki[(size_t)(b0 + row) * L_ + t] = bi;
            }
        }
        __syncthreads();   // stok visible; slog dead -> iT rewritten below

        // ===== gather next input (transposed): iT[e][row] = emb[stok[row]][e] =====
        for (int q = tid; q < MT * (E_ / 4); q += NT){
            const int row = q & (MT - 1);
            const int ch  = q >> 4;
            float4 v = *(const float4*)(emb + (size_t)stok[row] * E_ + ch * 4);
            iT[(4 * ch + 0) * ST + row] = v.x;
            iT[(4 * ch + 1) * ST + row] = v.y;
            iT[(4 * ch + 2) * ST + row] = v.z;
            iT[(4 * ch + 3) * ST + row] = v.w;
        }

        float* tmp = hcur; hcur = hnxt; hnxt = tmp;
    }
}

extern "C" void kernel_launch(void* const* d_in, const int* in_sizes, int n_in,
                              void* d_out, int out_size) {
    const float* x    = (const float*)d_in[0];
    const float* emb  = (const float*)d_in[1];
    const float* sos  = (const float*)d_in[2];
    const float* Wi2h = (const float*)d_in[3];
    const float* bi2h = (const float*)d_in[4];
    const float* Wih  = (const float*)d_in[5];
    const float* Whh  = (const float*)d_in[6];
    const float* bih  = (const float*)d_in[7];
    const float* bhh  = (const float*)d_in[8];
    const float* Wout = (const float*)d_in[9];
    const float* bout = (const float*)d_in[10];

    float *dWihT, *dWhhT, *dWoutT, *dWi2hT;
    cudaGetSymbolAddress((void**)&dWihT,  g_WihT);
    cudaGetSymbolAddress((void**)&dWhhT,  g_WhhT);
    cudaGetSymbolAddress((void**)&dWoutT, g_WoutT);
    cudaGetSymbolAddress((void**)&dWi2hT, g_Wi2hT);

    stage_weights_kernel<<<1024, 256>>>(Wih, Whh, Wout, Wi2h,
                                        dWihT, dWhhT, dWoutT, dWi2hT);

    const long long TOKN = (long long)B_ * L_;        // 262144
    const long long LGN  = TOKN * V_;                 // 67108864
    const long long os   = (long long)out_size;

    float* tokf = nullptr;
    int*   toki = nullptr;
    float* lg   = nullptr;

    if (os == TOKN + LGN){           // (tokens, logits) concatenated as float32
        tokf = (float*)d_out;
        lg   = (float*)d_out + TOKN;
    } else if (os == LGN){           // logits only
        lg   = (float*)d_out;
    } else if (os == TOKN){          // tokens only (int32)
        toki = (int*)d_out;
    } else {                         // best guess
        tokf = (float*)d_out;
        lg   = (float*)d_out + TOKN;
    }

    const size_t smem = (size_t)(2 * HROWS * ST + OVL) * sizeof(float) + MT * sizeof(int);
    cudaFuncSetAttribute(rnn_decoder_kernel,
                         cudaFuncAttributeMaxDynamicSharedMemorySize, (int)smem);
    rnn_decoder_kernel<<<B_ / MT, NT, smem>>>(
        x, emb, sos, bi2h, bih, bhh, bout,
        tokf, toki, lg);
}

// round 12
// speedup vs baseline: 4.8849x; 1.0845x over previous
#include <cuda_runtime.h>
#include <math.h>

// ---------------- problem dims ----------------
constexpr int B_  = 8192;
constexpr int L_  = 32;
constexpr int V_  = 256;
constexpr int DIN = 256;
constexpr int H_  = 512;
constexpr int E_  = 256;

constexpr int NT  = 256;   // threads per CTA
constexpr int NB16 = 272;  // CTAs with MT=16
constexpr int NB12 = 320;  // CTAs with MT=12   (272*16 + 320*12 = 8192)
constexpr int GRID = NB16 + NB12;   // 592 -> ~2 balanced waves on 296 dual-slots

typedef unsigned long long ull;

// ---------------- paired-k weight scratch (NOT duplicated), padded +4 pair-rows ----------------
__device__ float g_WihT [(E_  / 2 + 4) * 2 * (3 * H_)];
__device__ float g_WhhT [(H_  / 2 + 4) * 2 * (3 * H_)];
__device__ float g_WoutT[(H_  / 2 + 4) * 2 * V_];
__device__ float g_Wi2hT[(DIN / 2 + 4) * 2 * H_];

__global__ void stage_weights_kernel(
    const float* __restrict__ Wih,  const float* __restrict__ Whh,
    const float* __restrict__ Wout, const float* __restrict__ Wi2h,
    float* __restrict__ o_ih, float* __restrict__ o_hh,
    float* __restrict__ o_out, float* __restrict__ o_i2h)
{
    const long N0 = 1536L * 256, N1 = 1536L * 512, N2 = 256L * 512, N3 = 512L * 256;
    const long NTOT = N0 + N1 + N2 + N3;
    for (long e = (long)blockIdx.x * blockDim.x + threadIdx.x; e < NTOT;
         e += (long)gridDim.x * blockDim.x){
        const float* W; float* o; int J, K; long r = e;
        if (r < N0)            { W = Wih;  o = o_ih;  J = 1536; K = 256; }
        else if ((r -= N0) < N1){ W = Whh;  o = o_hh;  J = 1536; K = 512; }
        else if ((r -= N1) < N2){ W = Wout; o = o_out; J = 256;  K = 512; }
        else { r -= N2;          W = Wi2h; o = o_i2h; J = 512;  K = 256; }
        int j = (int)(r / K), k = (int)(r % K);
        o[(size_t)(k >> 1) * (2 * J) + 2 * j + (k & 1)] = W[r];
    }
}

// ---------------- packed f32x2 FMA ----------------
__device__ __forceinline__ void ffma2(ull &d, ull a, ull b){
    asm("fma.rn.f32x2 %0, %1, %2, %0;" : "+l"(d) : "l"(a), "l"(b));
}
__device__ __forceinline__ ull dup2(float w){
    ull r; asm("mov.b64 %0, {%1, %1};" : "=l"(r) : "f"(w)); return r;
}
__device__ __forceinline__ void unpack2(ull v, float &lo, float &hi){
    asm("mov.b64 {%0, %1}, %2;" : "=f"(lo), "=f"(hi) : "l"(v));
}

// ---------------- XLA:CPU exp/sigmoid/tanh (bit-exact emulation) ----------------
__device__ __forceinline__ float xla_exp(float x){
    float c  = fminf(fmaxf(x, -88.3762626647949f), 88.3762626647950f);
    float fx = floorf(__fmaf_rn(c, 1.44269504088896341f, 0.5f));
    float t1 = __fmul_rn(0.693359375f, fx);
    float t2 = __fmul_rn(-2.12194440e-4f, fx);
    float r  = __fadd_rn(c, -t1);
    r        = __fadd_rn(r, -t2);
    float r2 = __fmul_rn(r, r);
    float y  = 1.9875691500e-4f;
    y = __fmaf_rn(y, r, 1.3981999507e-3f);
    y = __fmaf_rn(y, r, 8.3334519073e-3f);
    y = __fmaf_rn(y, r, 4.1665795894e-2f);
    y = __fmaf_rn(y, r, 1.6666665459e-1f);
    y = __fmaf_rn(y, r, 5.0000001201e-1f);
    y = __fmaf_rn(y, r2, r);
    y = __fadd_rn(y, 1.0f);
    int n = (int)fx;
    float p2n = __int_as_float((n + 127) << 23);
    return __fmul_rn(y, p2n);
}
__device__ __forceinline__ float xla_sigmoid(float x){
    float e = xla_exp(-x);
    return __fdiv_rn(1.0f, __fadd_rn(1.0f, e));
}
__device__ __forceinline__ float xla_tanh(float x){
    float ax = fabsf(x);
    float xc = fminf(fmaxf(x, -9.0f), 9.0f);
    float x2 = __fmul_rn(xc, xc);
    float np = -2.76076847742355e-16f;
    np = __fmaf_rn(np, x2, 2.00018790482477e-13f);
    np = __fmaf_rn(np, x2, -8.60467152213735e-11f);
    np = __fmaf_rn(np, x2, 5.12229709037114e-08f);
    np = __fmaf_rn(np, x2, 1.48572235717979e-05f);
    np = __fmaf_rn(np, x2, 6.37261928875436e-04f);
    np = __fmaf_rn(np, x2, 4.89352455891786e-03f);
    np = __fmul_rn(np, xc);
    float dp = 1.19825839466702e-06f;
    dp = __fmaf_rn(dp, x2, 1.18534705686654e-04f);
    dp = __fmaf_rn(dp, x2, 2.26843463243900e-03f);
    dp = __fmaf_rn(dp, x2, 4.89352518554385e-03f);
    float res = __fdiv_rn(np, dp);
    return (ax < 0.0004f) ? x : res;
}

// ---- activation loads: P row-pairs starting at base (base 8B-aligned) ----
template<int P>
__device__ __forceinline__ void load_act(ull (&a)[P], const float* base){
    if constexpr (P == 4){
        ulonglong2 v0 = *(const ulonglong2*)(base);
        ulonglong2 v1 = *(const ulonglong2*)(base + 4);
        a[0] = v0.x; a[1] = v0.y; a[2] = v1.x; a[3] = v1.y;
    } else {  // P == 3 : row0 may be 24B-aligned -> LDS.64 each
        a[0] = *(const ull*)(base);
        a[1] = *(const ull*)(base + 2);
        a[2] = *(const ull*)(base + 4);
    }
}

// ---- 3-gate chain: depth-4 circular LDG.64 weight prefetch + activation pipeline ----
// Bit-exact: strict ascending-k, one accumulator per (gate, row) output.
template<int P, int STT, int KK, int RL>
__device__ __forceinline__ void chain3CT(ull (&acc)[3][P],
    const float* __restrict__ wT, int col,
    const float* __restrict__ actT, int row0)
{
    const float* w0p = wT + 2 * col;
    const float* w1p = wT + 2 * (col + H_);
    const float* w2p = wT + 2 * (col + 2 * H_);
    constexpr int NP = KK / 2;
    float2 w[4][3];
#pragma unroll
    for (int j = 0; j < 4; ++j){
        w[j][0] = *(const float2*)(w0p + (size_t)j * RL);
        w[j][1] = *(const float2*)(w1p + (size_t)j * RL);
        w[j][2] = *(const float2*)(w2p + (size_t)j * RL);
    }
    ull a[P];
    load_act<P>(a, actT + row0);
#pragma unroll 1
    for (int p0 = 0; p0 < NP; p0 += 4){
#pragma unroll
        for (int j = 0; j < 4; ++j){
            const int p = p0 + j;
#pragma unroll
            for (int s = 0; s < 2; ++s){
                const int k = 2 * p + s;
                ull na[P];
                load_act<P>(na, actT + (size_t)(k + 1) * STT + row0);   // pad row absorbs k=KK
                ull d0 = dup2(s ? w[j][0].y : w[j][0].x);
                ull d1 = dup2(s ? w[j][1].y : w[j][1].x);
                ull d2 = dup2(s ? w[j][2].y : w[j][2].x);
#pragma unroll
                for (int pp = 0; pp < P; ++pp) ffma2(acc[0][pp], a[pp], d0);
#pragma unroll
                for (int pp = 0; pp < P; ++pp) ffma2(acc[1][pp], a[pp], d1);
#pragma unroll
                for (int pp = 0; pp < P; ++pp) ffma2(acc[2][pp], a[pp], d2);
#pragma unroll
                for (int pp = 0; pp < P; ++pp) a[pp] = na[pp];
            }
            const int pn = p + 4;                                        // pad rows absorb p>=NP
            w[j][0] = *(const float2*)(w0p + (size_t)pn * RL);
            w[j][1] = *(const float2*)(w1p + (size_t)pn * RL);
            w[j][2] = *(const float2*)(w2p + (size_t)pn * RL);
        }
    }
}

// 1-gate variant (h0 GEMM, runs once)
template<int P, int STT, int KK, int RL>
__device__ __forceinline__ void chain1CT(ull (&acc)[P],
    const float* __restrict__ wT, int col,
    const float* __restrict__ actT, int row0)
{
    const float* wp = wT + 2 * col;
    constexpr int NP = KK / 2;
    float2 w[4];
#pragma unroll
    for (int j = 0; j < 4; ++j)
        w[j] = *(const float2*)(wp + (size_t)j * RL);
    ull a[P];
    load_act<P>(a, actT + row0);
#pragma unroll 1
    for (int p0 = 0; p0 < NP; p0 += 4){
#pragma unroll
        for (int j = 0; j < 4; ++j){
            const int p = p0 + j;
#pragma unroll
            for (int s = 0; s < 2; ++s){
                const int k = 2 * p + s;
                ull na[P];
                load_act<P>(na, actT + (size_t)(k + 1) * STT + row0);
                ull d0 = dup2(s ? w[j].y : w[j].x);
#pragma unroll
                for (int pp = 0; pp < P; ++pp) ffma2(acc[pp], a[pp], d0);
#pragma unroll
                for (int pp = 0; pp < P; ++pp) a[pp] = na[pp];
            }
            w[j] = *(const float2*)(wp + (size_t)(p + 4) * RL);
        }
    }
}

constexpr int HROWS = H_ + 1;   // +1 pad k-row for unconditional prefetch
constexpr int IROWS = E_ + 1;

template<int A, int Bc> struct MaxI { static constexpr int v = (A > Bc) ? A : Bc; };

// ---------------- the per-tile decoder ----------------
template<int MTT>
__device__ __forceinline__ void run_tile(
    int b0,
    const float* __restrict__ x,    const float* __restrict__ emb,
    const float* __restrict__ sos,
    const float* __restrict__ bi2h,
    const float* __restrict__ bih,  const float* __restrict__ bhh,
    const float* __restrict__ bout,
    float* __restrict__ tokf, int* __restrict__ toki, float* __restrict__ lg)
{
    constexpr int STT = MTT + 4;            // 20 or 16
    constexpr int P   = MTT / 4;            // pairs per thread per group: 4 or 3
    constexpr int RPG = MTT / 2;            // rows per group: 8 or 6
    constexpr int NA  = MTT / 2;            // logits accs (rows/2): 8 or 6
    constexpr int OVL = MaxI<IROWS * STT, MTT * V_>::v;

    extern __shared__ float sm[];
    float* hT0  = sm;                        // [513][STT]
    float* hT1  = hT0 + HROWS * STT;         // [513][STT]
    float* iT   = hT1 + HROWS * STT;         // overlay: [257][STT] / logits [MTT][256]
    float* slog = iT;
    int*   stok = (int*)(iT + OVL);          // [MTT]

    const int tid  = threadIdx.x;
    const int cx   = tid & 127;              // column within 128-col chunk
    const int row0 = (tid >> 7) * RPG;       // 2 groups
    const int lane = tid & 31;
    const int wid  = tid >> 5;

    // ---- load x tile transposed into iT ----
    for (int q = tid; q < MTT * (DIN / 4); q += NT){
        const int ch  = q & 63;
        const int row = q >> 6;
        float4 v = *(const float4*)(x + (size_t)(b0 + row) * DIN + ch * 4);
        iT[(4 * ch + 0) * STT + row] = v.x;
        iT[(4 * ch + 1) * STT + row] = v.y;
        iT[(4 * ch + 2) * STT + row] = v.z;
        iT[(4 * ch + 3) * STT + row] = v.w;
    }
    __syncthreads();

    float* hcur = hT0;
    float* hnxt = hT1;

    // ---- h0 = x @ Wi2h^T + bi2h ----
#pragma unroll 1
    for (int c = 0; c < H_; c += 128){
        const int col = c + cx;
        ull acc[P] = {};
        chain1CT<P, STT, DIN, 2 * H_>(acc, g_Wi2hT, col, iT, row0);
        const float b = bi2h[col];
#pragma unroll
        for (int p = 0; p < P; ++p){
            float lo, hi; unpack2(acc[p], lo, hi);
            hcur[col * STT + row0 + 2 * p + 0] = __fadd_rn(lo, b);
            hcur[col * STT + row0 + 2 * p + 1] = __fadd_rn(hi, b);
        }
    }
    __syncthreads();   // h0 done reading iT

    // ---- i0 = sos broadcast (transposed) ----
    for (int q = tid; q < E_ * MTT; q += NT){
        const int e = q / MTT, r = q % MTT;
        iT[e * STT + r] = sos[e];
    }

    // ---- time loop ----
#pragma unroll 1
    for (int t = 0; t < L_; ++t){
        __syncthreads();   // iT + hcur ready

        // ===== GRU gates (exact sequential-k chain order) =====
#pragma unroll 1
        for (int c = 0; c < H_; c += 128){
            const int col = c + cx;
            ull gi[3][P] = {};
            ull gh[3][P] = {};
            chain3CT<P, STT, E_, 2 * 3 * H_>(gi, g_WihT, col, iT,   row0);
            chain3CT<P, STT, H_, 2 * 3 * H_>(gh, g_WhhT, col, hcur, row0);
            const float bir = bih[col], biz = bih[col + H_], bin = bih[col + 2 * H_];
            const float bhr = bhh[col], bhz = bhh[col + H_], bhn = bhh[col + 2 * H_];
#pragma unroll
            for (int p = 0; p < P; ++p){
                float giR0, giR1, giZ0, giZ1, giN0, giN1;
                float ghR0, ghR1, ghZ0, ghZ1, ghN0, ghN1;
                unpack2(gi[0][p], giR0, giR1); unpack2(gi[1][p], giZ0, giZ1); unpack2(gi[2][p], giN0, giN1);
                unpack2(gh[0][p], ghR0, ghR1); unpack2(gh[1][p], ghZ0, ghZ1); unpack2(gh[2][p], ghN0, ghN1);
#pragma unroll
                for (int s = 0; s < 2; ++s){
                    const int row = row0 + 2 * p + s;
                    float dIR = s ? giR1 : giR0, dIZ = s ? giZ1 : giZ0, dIN = s ? giN1 : giN0;
                    float dHR = s ? ghR1 : ghR0, dHZ = s ? ghZ1 : ghZ0, dHN = s ? ghN1 : ghN0;
                    float ir = __fadd_rn(dIR, bir), hr = __fadd_rn(dHR, bhr);
                    float iz = __fadd_rn(dIZ, biz), hz = __fadd_rn(dHZ, bhz);
                    float in_ = __fadd_rn(dIN, bin), hn = __fadd_rn(dHN, bhn);
                    float rg = xla_sigmoid(__fadd_rn(ir, hr));
                    float zg = xla_sigmoid(__fadd_rn(iz, hz));
                    float npre = __fadd_rn(in_, __fmul_rn(rg, hn));
                    float n  = xla_tanh(npre);
                    float ho = hcur[col * STT + row];
                    float omz = __fadd_rn(1.0f, -zg);
                    float hv  = __fadd_rn(__fmul_rn(omz, n), __fmul_rn(zg, ho));
                    hnxt[col * STT + row] = hv;
                }
            }
        }
        __syncthreads();   // hnxt complete; iT dead -> slog reuses it

        // ===== logits = hnxt @ Wout^T + bout : 1 col x MTT rows per thread =====
        {
            const int colA = tid & 255;
            ull aA[NA];
#pragma unroll
            for (int p = 0; p < NA; ++p) aA[p] = 0ULL;
            const float* wp = g_WoutT + 2 * colA;   // RL = 2*V = 512
            constexpr int NPL = H_ / 2;
            float2 w[4];
#pragma unroll
            for (int j = 0; j < 4; ++j)
                w[j] = *(const float2*)(wp + (size_t)j * 512);
            ull av[NA];
            {
                const float* ab = hnxt;
#pragma unroll
                for (int h2 = 0; h2 < NA / 2; ++h2){
                    ulonglong2 v = *(const ulonglong2*)(ab + 4 * h2);
                    av[2 * h2] = v.x; av[2 * h2 + 1] = v.y;
                }
            }
#pragma unroll 1
            for (int p0 = 0; p0 < NPL; p0 += 4){
#pragma unroll
                for (int j = 0; j < 4; ++j){
                    const int p = p0 + j;
#pragma unroll
                    for (int s = 0; s < 2; ++s){
                        const int k = 2 * p + s;
                        ull nav[NA];
                        {
                            const float* abn = hnxt + (size_t)(k + 1) * STT;
#pragma unroll
                            for (int h2 = 0; h2 < NA / 2; ++h2){
                                ulonglong2 v = *(const ulonglong2*)(abn + 4 * h2);
                                nav[2 * h2] = v.x; nav[2 * h2 + 1] = v.y;
                            }
                        }
                        ull da = dup2(s ? w[j].y : w[j].x);
#pragma unroll
                        for (int p2 = 0; p2 < NA; ++p2) ffma2(aA[p2], av[p2], da);
#pragma unroll
                        for (int p2 = 0; p2 < NA; ++p2) av[p2] = nav[p2];
                    }
                    w[j] = *(const float2*)(wp + (size_t)(p + 4) * 512);
                }
            }
            const float boA = bout[colA];
#pragma unroll
            for (int p = 0; p < NA; ++p){
                float a0, a1; unpack2(aA[p], a0, a1);
                const int rA = 2 * p, rB = rA + 1;
                float lv0 = __fadd_rn(a0, boA), lv1 = __fadd_rn(a1, boA);
                slog[rA * V_ + colA] = lv0;
                slog[rB * V_ + colA] = lv1;
                if (lg){
                    lg[(size_t)(b0 + rA) * (L_ * V_) + (size_t)t * V_ + colA] = lv0;
                    lg[(size_t)(b0 + rB) * (L_ * V_) + (size_t)t * V_ + colA] = lv1;
                }
            }
        }
        __syncthreads();   // slog complete

        // ===== argmax (first index on ties) : 8 warps x 2 rows =====
#pragma unroll
        for (int rr2 = 0; rr2 < 2; ++rr2){
            const int row = wid * 2 + rr2;
            if (row < MTT){
                float bv = -1e30f; int bi = 0;
#pragma unroll
                for (int j = 0; j < 8; ++j){
                    const int idx = lane + 32 * j;
                    float v = slog[row * V_ + idx];
                    if (v > bv){ bv = v; bi = idx; }
                }
#pragma unroll
                for (int off = 16; off > 0; off >>= 1){
                    float ov = __shfl_down_sync(0xffffffffu, bv, off);
                    int   oi = __shfl_down_sync(0xffffffffu, bi, off);
                    if (ov > bv || (ov == bv && oi < bi)){ bv = ov; bi = oi; }
                }
                if (lane == 0){
                    stok[row] = bi;
                    if (tokf) tokf[(size_t)(b0 + row) * L_ + t] = (float)bi;
                    if (toki) toki[(size_t)(b0 + row) * L_ + t] = bi;
                }
            }
        }
        __syncthreads();   // stok visible; slog dead -> iT rewritten below

        // ===== gather next input (transposed): iT[e][row] = emb[stok[row]][e] =====
        for (int q = tid; q < MTT * (E_ / 4); q += NT){
            const int row = q >> 6;
            const int ch  = q & 63;
            float4 v = *(const float4*)(emb + (size_t)stok[row] * E_ + ch * 4);
            iT[(4 * ch + 0) * STT + row] = v.x;
            iT[(4 * ch + 1) * STT + row] = v.y;
            iT[(4 * ch + 2) * STT + row] = v.z;
            iT[(4 * ch + 3) * STT + row] = v.w;
        }

        float* tmp = hcur; hcur = hnxt; hnxt = tmp;
    }
}

__global__ void __launch_bounds__(NT, 2)
rnn_decoder_kernel(
    const float* __restrict__ x,    const float* __restrict__ emb,
    const float* __restrict__ sos,
    const float* __restrict__ bi2h,
    const float* __restrict__ bih,  const float* __restrict__ bhh,
    const float* __restrict__ bout,
    float* __restrict__ tokf, int* __restrict__ toki, float* __restrict__ lg)
{
    const int bid = blockIdx.x;
    if (bid < NB16){
        run_tile<16>(bid * 16, x, emb, sos, bi2h, bih, bhh, bout, tokf, toki, lg);
    } else {
        run_tile<12>(NB16 * 16 + (bid - NB16) * 12, x, emb, sos, bi2h, bih, bhh, bout, tokf, toki, lg);
    }
}

extern "C" void kernel_launch(void* const* d_in, const int* in_sizes, int n_in,
                              void* d_out, int out_size) {
    const float* x    = (const float*)d_in[0];
    const float* emb  = (const float*)d_in[1];
    const float* sos  = (const float*)d_in[2];
    const float* Wi2h = (const float*)d_in[3];
    const float* bi2h = (const float*)d_in[4];
    const float* Wih  = (const float*)d_in[5];
    const float* Whh  = (const float*)d_in[6];
    const float* bih  = (const float*)d_in[7];
    const float* bhh  = (const float*)d_in[8];
    const float* Wout = (const float*)d_in[9];
    const float* bout = (const float*)d_in[10];

    float *dWihT, *dWhhT, *dWoutT, *dWi2hT;
    cudaGetSymbolAddress((void**)&dWihT,  g_WihT);
    cudaGetSymbolAddress((void**)&dWhhT,  g_WhhT);
    cudaGetSymbolAddress((void**)&dWoutT, g_WoutT);
    cudaGetSymbolAddress((void**)&dWi2hT, g_Wi2hT);

    stage_weights_kernel<<<1024, 256>>>(Wih, Whh, Wout, Wi2h,
                                        dWihT, dWhhT, dWoutT, dWi2hT);

    const long long TOKN = (long long)B_ * L_;        // 262144
    const long long LGN  = TOKN * V_;                 // 67108864
    const long long os   = (long long)out_size;

    float* tokf = nullptr;
    int*   toki = nullptr;
    float* lg   = nullptr;

    if (os == TOKN + LGN){           // (tokens, logits) concatenated as float32
        tokf = (float*)d_out;
        lg   = (float*)d_out + TOKN;
    } else if (os == LGN){           // logits only
        lg   = (float*)d_out;
    } else if (os == TOKN){          // tokens only (int32)
        toki = (int*)d_out;
    } else {                         // best guess
        tokf = (float*)d_out;
        lg   = (float*)d_out + TOKN;
    }

    // smem sized for the larger (MT=16) tile: [513][20]*2 + overlay + stok
    constexpr int ST16  = 20;
    constexpr int OVL16 = (IROWS * ST16 > 16 * V_) ? IROWS * ST16 : 16 * V_;
    const size_t smem = (size_t)(2 * HROWS * ST16 + OVL16) * sizeof(float) + 16 * sizeof(int);
    cudaFuncSetAttribute(rnn_decoder_kernel,
                         cudaFuncAttributeMaxDynamicSharedMemorySize, (int)smem);
    rnn_decoder_kernel<<<GRID, NT, smem>>>(
        x, emb, sos, bi2h, bih, bhh, bout,
        tokf, toki, lg);
}

// round 13
// speedup vs baseline: 5.3896x; 1.1033x over previous
#include <cuda_runtime.h>
#include <math.h>

// ---------------- problem dims ----------------
constexpr int B_  = 8192;
constexpr int L_  = 32;
constexpr int V_  = 256;
constexpr int DIN = 256;
constexpr int H_  = 512;
constexpr int E_  = 256;

constexpr int NT  = 256;   // threads per CTA
constexpr int GRID = 592;  // 2 clean waves on 296 dual-slots; 272*16 + 320*12 = 8192

typedef unsigned long long ull;

// ---------------- paired-k weight scratch (NOT duplicated), padded +4 pair-rows ----------------
__device__ float g_WihT [(E_  / 2 + 4) * 2 * (3 * H_)];
__device__ float g_WhhT [(H_  / 2 + 4) * 2 * (3 * H_)];
__device__ float g_WoutT[(H_  / 2 + 4) * 2 * V_];
__device__ float g_Wi2hT[(DIN / 2 + 4) * 2 * H_];

__global__ void stage_weights_kernel(
    const float* __restrict__ Wih,  const float* __restrict__ Whh,
    const float* __restrict__ Wout, const float* __restrict__ Wi2h,
    float* __restrict__ o_ih, float* __restrict__ o_hh,
    float* __restrict__ o_out, float* __restrict__ o_i2h)
{
    const long N0 = 1536L * 256, N1 = 1536L * 512, N2 = 256L * 512, N3 = 512L * 256;
    const long NTOT = N0 + N1 + N2 + N3;
    for (long e = (long)blockIdx.x * blockDim.x + threadIdx.x; e < NTOT;
         e += (long)gridDim.x * blockDim.x){
        const float* W; float* o; int J, K; long r = e;
        if (r < N0)            { W = Wih;  o = o_ih;  J = 1536; K = 256; }
        else if ((r -= N0) < N1){ W = Whh;  o = o_hh;  J = 1536; K = 512; }
        else if ((r -= N1) < N2){ W = Wout; o = o_out; J = 256;  K = 512; }
        else { r -= N2;          W = Wi2h; o = o_i2h; J = 512;  K = 256; }
        int j = (int)(r / K), k = (int)(r % K);
        o[(size_t)(k >> 1) * (2 * J) + 2 * j + (k & 1)] = W[r];
    }
}

// ---------------- packed f32x2 FMA ----------------
__device__ __forceinline__ void ffma2(ull &d, ull a, ull b){
    asm("fma.rn.f32x2 %0, %1, %2, %0;" : "+l"(d) : "l"(a), "l"(b));
}
__device__ __forceinline__ ull dup2(float w){
    ull r; asm("mov.b64 %0, {%1, %1};" : "=l"(r) : "f"(w)); return r;
}
__device__ __forceinline__ void unpack2(ull v, float &lo, float &hi){
    asm("mov.b64 {%0, %1}, %2;" : "=f"(lo), "=f"(hi) : "l"(v));
}

// ---------------- XLA:CPU exp/sigmoid/tanh (bit-exact emulation) ----------------
__device__ __forceinline__ float xla_exp(float x){
    float c  = fminf(fmaxf(x, -88.3762626647949f), 88.3762626647950f);
    float fx = floorf(__fmaf_rn(c, 1.44269504088896341f, 0.5f));
    float t1 = __fmul_rn(0.693359375f, fx);
    float t2 = __fmul_rn(-2.12194440e-4f, fx);
    float r  = __fadd_rn(c, -t1);
    r        = __fadd_rn(r, -t2);
    float r2 = __fmul_rn(r, r);
    float y  = 1.9875691500e-4f;
    y = __fmaf_rn(y, r, 1.3981999507e-3f);
    y = __fmaf_rn(y, r, 8.3334519073e-3f);
    y = __fmaf_rn(y, r, 4.1665795894e-2f);
    y = __fmaf_rn(y, r, 1.6666665459e-1f);
    y = __fmaf_rn(y, r, 5.0000001201e-1f);
    y = __fmaf_rn(y, r2, r);
    y = __fadd_rn(y, 1.0f);
    int n = (int)fx;
    float p2n = __int_as_float((n + 127) << 23);
    return __fmul_rn(y, p2n);
}
__device__ __forceinline__ float xla_sigmoid(float x){
    float e = xla_exp(-x);
    return __fdiv_rn(1.0f, __fadd_rn(1.0f, e));
}
__device__ __forceinline__ float xla_tanh(float x){
    float ax = fabsf(x);
    float xc = fminf(fmaxf(x, -9.0f), 9.0f);
    float x2 = __fmul_rn(xc, xc);
    float np = -2.76076847742355e-16f;
    np = __fmaf_rn(np, x2, 2.00018790482477e-13f);
    np = __fmaf_rn(np, x2, -8.60467152213735e-11f);
    np = __fmaf_rn(np, x2, 5.12229709037114e-08f);
    np = __fmaf_rn(np, x2, 1.48572235717979e-05f);
    np = __fmaf_rn(np, x2, 6.37261928875436e-04f);
    np = __fmaf_rn(np, x2, 4.89352455891786e-03f);
    np = __fmul_rn(np, xc);
    float dp = 1.19825839466702e-06f;
    dp = __fmaf_rn(dp, x2, 1.18534705686654e-04f);
    dp = __fmaf_rn(dp, x2, 2.26843463243900e-03f);
    dp = __fmaf_rn(dp, x2, 4.89352518554385e-03f);
    float res = __fdiv_rn(np, dp);
    return (ax < 0.0004f) ? x : res;
}

// ---- activation loads: P row-pairs starting at base (base 16B-aligned for even P*2 rows) ----
template<int P>
__device__ __forceinline__ void load_act(ull (&a)[P], const float* base){
    if constexpr (P == 4){
        ulonglong2 v0 = *(const ulonglong2*)(base);
        ulonglong2 v1 = *(const ulonglong2*)(base + 4);
        a[0] = v0.x; a[1] = v0.y; a[2] = v1.x; a[3] = v1.y;
    } else if constexpr (P == 6){
        ulonglong2 v0 = *(const ulonglong2*)(base);
        ulonglong2 v1 = *(const ulonglong2*)(base + 4);
        ulonglong2 v2 = *(const ulonglong2*)(base + 8);
        a[0] = v0.x; a[1] = v0.y; a[2] = v1.x; a[3] = v1.y; a[4] = v2.x; a[5] = v2.y;
    } else {  // P == 3
        a[0] = *(const ull*)(base);
        a[1] = *(const ull*)(base + 2);
        a[2] = *(const ull*)(base + 4);
    }
}

constexpr int HROWS = H_ + 1;   // +1 pad k-row for unconditional prefetch
constexpr int IROWS = E_ + 1;

// ================== 2-group MT16 path (R12-proven) ==================
template<int P, int STT, int KK, int RL>
__device__ __forceinline__ void chain3CT(ull (&acc)[3][P],
    const float* __restrict__ wT, int col,
    const float* __restrict__ actT, int row0)
{
    const float* w0p = wT + 2 * col;
    const float* w1p = wT + 2 * (col + H_);
    const float* w2p = wT + 2 * (col + 2 * H_);
    constexpr int NP = KK / 2;
    float2 w[4][3];
#pragma unroll
    for (int j = 0; j < 4; ++j){
        w[j][0] = *(const float2*)(w0p + (size_t)j * RL);
        w[j][1] = *(const float2*)(w1p + (size_t)j * RL);
        w[j][2] = *(const float2*)(w2p + (size_t)j * RL);
    }
    ull a[P];
    load_act<P>(a, actT + row0);
#pragma unroll 1
    for (int p0 = 0; p0 < NP; p0 += 4){
#pragma unroll
        for (int j = 0; j < 4; ++j){
            const int p = p0 + j;
#pragma unroll
            for (int s = 0; s < 2; ++s){
                const int k = 2 * p + s;
                ull na[P];
                load_act<P>(na, actT + (size_t)(k + 1) * STT + row0);
                ull d0 = dup2(s ? w[j][0].y : w[j][0].x);
                ull d1 = dup2(s ? w[j][1].y : w[j][1].x);
                ull d2 = dup2(s ? w[j][2].y : w[j][2].x);
#pragma unroll
                for (int pp = 0; pp < P; ++pp) ffma2(acc[0][pp], a[pp], d0);
#pragma unroll
                for (int pp = 0; pp < P; ++pp) ffma2(acc[1][pp], a[pp], d1);
#pragma unroll
                for (int pp = 0; pp < P; ++pp) ffma2(acc[2][pp], a[pp], d2);
#pragma unroll
                for (int pp = 0; pp < P; ++pp) a[pp] = na[pp];
            }
            const int pn = p + 4;
            w[j][0] = *(const float2*)(w0p + (size_t)pn * RL);
            w[j][1] = *(const float2*)(w1p + (size_t)pn * RL);
            w[j][2] = *(const float2*)(w2p + (size_t)pn * RL);
        }
    }
}

template<int P, int STT, int KK, int RL>
__device__ __forceinline__ void chain1CT(ull (&acc)[P],
    const float* __restrict__ wT, int col,
    const float* __restrict__ actT, int row0)
{
    const float* wp = wT + 2 * col;
    constexpr int NP = KK / 2;
    float2 w[4];
#pragma unroll
    for (int j = 0; j < 4; ++j)
        w[j] = *(const float2*)(wp + (size_t)j * RL);
    ull a[P];
    load_act<P>(a, actT + row0);
#pragma unroll 1
    for (int p0 = 0; p0 < NP; p0 += 4){
#pragma unroll
        for (int j = 0; j < 4; ++j){
            const int p = p0 + j;
#pragma unroll
            for (int s = 0; s < 2; ++s){
                const int k = 2 * p + s;
                ull na[P];
                load_act<P>(na, actT + (size_t)(k + 1) * STT + row0);
                ull d0 = dup2(s ? w[j].y : w[j].x);
#pragma unroll
                for (int pp = 0; pp < P; ++pp) ffma2(acc[pp], a[pp], d0);
#pragma unroll
                for (int pp = 0; pp < P; ++pp) a[pp] = na[pp];
            }
            w[j] = *(const float2*)(wp + (size_t)(p + 4) * RL);
        }
    }
}

// ---- shared epilogue helpers ----
__device__ __forceinline__ void gru_epilogue_pair(
    float* hnxt, const float* hcur, int col, int STT, int row,
    float dIR, float dIZ, float dIN, float dHR, float dHZ, float dHN,
    float bir, float biz, float bin, float bhr, float bhz, float bhn)
{
    float ir = __fadd_rn(dIR, bir), hr = __fadd_rn(dHR, bhr);
    float iz = __fadd_rn(dIZ, biz), hz = __fadd_rn(dHZ, bhz);
    float in_ = __fadd_rn(dIN, bin), hn = __fadd_rn(dHN, bhn);
    float rg = xla_sigmoid(__fadd_rn(ir, hr));
    float zg = xla_sigmoid(__fadd_rn(iz, hz));
    float npre = __fadd_rn(in_, __fmul_rn(rg, hn));
    float n  = xla_tanh(npre);
    float ho = hcur[col * STT + row];
    float omz = __fadd_rn(1.0f, -zg);
    hnxt[col * STT + row] = __fadd_rn(__fmul_rn(omz, n), __fmul_rn(zg, ho));
}

// ---- logits + argmax + gather (shared; rows = MTT, NA = MTT/2) ----
template<int MTT, int STT>
__device__ __forceinline__ void logits_argmax_gather(
    int b0, int t, float* hnxt, float* slog, int* stok,
    const float* __restrict__ emb, const float* __restrict__ bout,
    float* __restrict__ tokf, int* __restrict__ toki, float* __restrict__ lg,
    float* iT)
{
    constexpr int NA = MTT / 2;
    const int tid  = threadIdx.x;
    const int lane = tid & 31;
    const int wid  = tid >> 5;
    {
        const int colA = tid & 255;
        ull aA[NA];
#pragma unroll
        for (int p = 0; p < NA; ++p) aA[p] = 0ULL;
        const float* wp = g_WoutT + 2 * colA;
        constexpr int NPL = H_ / 2;
        float2 w[4];
#pragma unroll
        for (int j = 0; j < 4; ++j)
            w[j] = *(const float2*)(wp + (size_t)j * 512);
        ull av[NA];
#pragma unroll
        for (int h2 = 0; h2 < NA / 2; ++h2){
            ulonglong2 v = *(const ulonglong2*)(hnxt + 4 * h2);
            av[2 * h2] = v.x; av[2 * h2 + 1] = v.y;
        }
#pragma unroll 1
        for (int p0 = 0; p0 < NPL; p0 += 4){
#pragma unroll
            for (int j = 0; j < 4; ++j){
                const int p = p0 + j;
#pragma unroll
                for (int s = 0; s < 2; ++s){
                    const int k = 2 * p + s;
                    ull nav[NA];
                    {
                        const float* abn = hnxt + (size_t)(k + 1) * STT;
#pragma unroll
                        for (int h2 = 0; h2 < NA / 2; ++h2){
                            ulonglong2 v = *(const ulonglong2*)(abn + 4 * h2);
                            nav[2 * h2] = v.x; nav[2 * h2 + 1] = v.y;
                        }
                    }
                    ull da = dup2(s ? w[j].y : w[j].x);
#pragma unroll
                    for (int p2 = 0; p2 < NA; ++p2) ffma2(aA[p2], av[p2], da);
#pragma unroll
                    for (int p2 = 0; p2 < NA; ++p2) av[p2] = nav[p2];
                }
                w[j] = *(const float2*)(wp + (size_t)(p + 4) * 512);
            }
        }
        const float boA = bout[colA];
#pragma unroll
        for (int p = 0; p < NA; ++p){
            float a0, a1; unpack2(aA[p], a0, a1);
            const int rA = 2 * p, rB = rA + 1;
            float lv0 = __fadd_rn(a0, boA), lv1 = __fadd_rn(a1, boA);
            slog[rA * V_ + colA] = lv0;
            slog[rB * V_ + colA] = lv1;
            if (lg){
                lg[(size_t)(b0 + rA) * (L_ * V_) + (size_t)t * V_ + colA] = lv0;
                lg[(size_t)(b0 + rB) * (L_ * V_) + (size_t)t * V_ + colA] = lv1;
            }
        }
    }
    __syncthreads();   // slog complete

#pragma unroll
    for (int rr2 = 0; rr2 < 2; ++rr2){
        const int row = wid * 2 + rr2;
        if (row < MTT){
            float bv = -1e30f; int bi = 0;
#pragma unroll
            for (int j = 0; j < 8; ++j){
                const int idx = lane + 32 * j;
                float v = slog[row * V_ + idx];
                if (v > bv){ bv = v; bi = idx; }
            }
#pragma unroll
            for (int off = 16; off > 0; off >>= 1){
                float ov = __shfl_down_sync(0xffffffffu, bv, off);
                int   oi = __shfl_down_sync(0xffffffffu, bi, off);
                if (ov > bv || (ov == bv && oi < bi)){ bv = ov; bi = oi; }
            }
            if (lane == 0){
                stok[row] = bi;
                if (tokf) tokf[(size_t)(b0 + row) * L_ + t] = (float)bi;
                if (toki) toki[(size_t)(b0 + row) * L_ + t] = bi;
            }
        }
    }
    __syncthreads();   // stok visible

    for (int q = threadIdx.x; q < MTT * (E_ / 4); q += NT){
        const int row = q >> 6;
        const int ch  = q & 63;
        float4 v = *(const float4*)(emb + (size_t)stok[row] * E_ + ch * 4);
        iT[(4 * ch + 0) * STT + row] = v.x;
        iT[(4 * ch + 1) * STT + row] = v.y;
        iT[(4 * ch + 2) * STT + row] = v.z;
        iT[(4 * ch + 3) * STT + row] = v.w;
    }
}

// ================== MT16, 2 groups x 8 rows (R12-proven) ==================
__device__ __forceinline__ void run_tile16(
    int b0,
    const float* __restrict__ x,    const float* __restrict__ emb,
    const float* __restrict__ sos,
    const float* __restrict__ bi2h,
    const float* __restrict__ bih,  const float* __restrict__ bhh,
    const float* __restrict__ bout,
    float* __restrict__ tokf, int* __restrict__ toki, float* __restrict__ lg)
{
    constexpr int MTT = 16, STT = 20, P = 4, RPG = 8;
    constexpr int OVL = (IROWS * STT > MTT * V_) ? IROWS * STT : MTT * V_;

    extern __shared__ float sm[];
    float* hT0  = sm;
    float* hT1  = hT0 + HROWS * STT;
    float* iT   = hT1 + HROWS * STT;
    float* slog = iT;
    int*   stok = (int*)(iT + OVL);

    const int tid  = threadIdx.x;
    const int cx   = tid & 127;
    const int row0 = (tid >> 7) * RPG;

    for (int q = tid; q < MTT * (DIN / 4); q += NT){
        const int ch  = q & 63;
        const int row = q >> 6;
        float4 v = *(const float4*)(x + (size_t)(b0 + row) * DIN + ch * 4);
        iT[(4 * ch + 0) * STT + row] = v.x;
        iT[(4 * ch + 1) * STT + row] = v.y;
        iT[(4 * ch + 2) * STT + row] = v.z;
        iT[(4 * ch + 3) * STT + row] = v.w;
    }
    __syncthreads();

    float* hcur = hT0;
    float* hnxt = hT1;

#pragma unroll 1
    for (int c = 0; c < H_; c += 128){
        const int col = c + cx;
        ull acc[P] = {};
        chain1CT<P, STT, DIN, 2 * H_>(acc, g_Wi2hT, col, iT, row0);
        const float b = bi2h[col];
#pragma unroll
        for (int p = 0; p < P; ++p){
            float lo, hi; unpack2(acc[p], lo, hi);
            hcur[col * STT + row0 + 2 * p + 0] = __fadd_rn(lo, b);
            hcur[col * STT + row0 + 2 * p + 1] = __fadd_rn(hi, b);
        }
    }
    __syncthreads();

    for (int q = tid; q < E_ * MTT; q += NT){
        const int e = q / MTT, r = q % MTT;
        iT[e * STT + r] = sos[e];
    }

#pragma unroll 1
    for (int t = 0; t < L_; ++t){
        __syncthreads();
#pragma unroll 1
        for (int c = 0; c < H_; c += 128){
            const int col = c + cx;
            ull gi[3][P] = {};
            ull gh[3][P] = {};
            chain3CT<P, STT, E_, 2 * 3 * H_>(gi, g_WihT, col, iT,   row0);
            chain3CT<P, STT, H_, 2 * 3 * H_>(gh, g_WhhT, col, hcur, row0);
            const float bir = bih[col], biz = bih[col + H_], bin = bih[col + 2 * H_];
            const float bhr = bhh[col], bhz = bhh[col + H_], bhn = bhh[col + 2 * H_];
#pragma unroll
            for (int p = 0; p < P; ++p){
                float giR0, giR1, giZ0, giZ1, giN0, giN1;
                float ghR0, ghR1, ghZ0, ghZ1, ghN0, ghN1;
                unpack2(gi[0][p], giR0, giR1); unpack2(gi[1][p], giZ0, giZ1); unpack2(gi[2][p], giN0, giN1);
                unpack2(gh[0][p], ghR0, ghR1); unpack2(gh[1][p], ghZ0, ghZ1); unpack2(gh[2][p], ghN0, ghN1);
                gru_epilogue_pair(hnxt, hcur, col, STT, row0 + 2 * p + 0,
                                  giR0, giZ0, giN0, ghR0, ghZ0, ghN0, bir, biz, bin, bhr, bhz, bhn);
                gru_epilogue_pair(hnxt, hcur, col, STT, row0 + 2 * p + 1,
                                  giR1, giZ1, giN1, ghR1, ghZ1, ghN1, bir, biz, bin, bhr, bhz, bhn);
            }
        }
        __syncthreads();

        logits_argmax_gather<MTT, STT>(b0, t, hnxt, slog, stok, emb, bout, tokf, toki, lg, iT);

        float* tmp = hcur; hcur = hnxt; hnxt = tmp;
    }
}

// ================== MT12, 1 group x 12 rows (NEW: single weight stream) ==================
template<int KK, int RL>
__device__ __forceinline__ void chain3G(ull (&acc)[3][6],
    const float* __restrict__ wT, int col,
    const float* __restrict__ actT /* STT = 16 */)
{
    const float* w0p = wT + 2 * col;
    const float* w1p = wT + 2 * (col + H_);
    const float* w2p = wT + 2 * (col + 2 * H_);
    constexpr int NP = KK / 2;
    float2 w[2][3];
#pragma unroll
    for (int j = 0; j < 2; ++j){
        w[j][0] = *(const float2*)(w0p + (size_t)j * RL);
        w[j][1] = *(const float2*)(w1p + (size_t)j * RL);
        w[j][2] = *(const float2*)(w2p + (size_t)j * RL);
    }
    ull a[6];
    load_act<6>(a, actT);
#pragma unroll 1
    for (int p0 = 0; p0 < NP; p0 += 2){
#pragma unroll
        for (int j = 0; j < 2; ++j){
            const int p = p0 + j;
#pragma unroll
            for (int s = 0; s < 2; ++s){
                const int k = 2 * p + s;
                ull na[6];
                load_act<6>(na, actT + (size_t)(k + 1) * 16);
                ull d0 = dup2(s ? w[j][0].y : w[j][0].x);
                ull d1 = dup2(s ? w[j][1].y : w[j][1].x);
                ull d2 = dup2(s ? w[j][2].y : w[j][2].x);
#pragma unroll
                for (int pp = 0; pp < 6; ++pp) ffma2(acc[0][pp], a[pp], d0);
#pragma unroll
                for (int pp = 0; pp < 6; ++pp) ffma2(acc[1][pp], a[pp], d1);
#pragma unroll
                for (int pp = 0; pp < 6; ++pp) ffma2(acc[2][pp], a[pp], d2);
#pragma unroll
                for (int pp = 0; pp < 6; ++pp) a[pp] = na[pp];
            }
            const int pn = p + 2;
            w[j][0] = *(const float2*)(w0p + (size_t)pn * RL);
            w[j][1] = *(const float2*)(w1p + (size_t)pn * RL);
            w[j][2] = *(const float2*)(w2p + (size_t)pn * RL);
        }
    }
}

template<int KK, int RL>
__device__ __forceinline__ void chain1G(ull (&acc)[6],
    const float* __restrict__ wT, int col,
    const float* __restrict__ actT)
{
    const float* wp = wT + 2 * col;
    constexpr int NP = KK / 2;
    float2 w[2];
    w[0] = *(const float2*)(wp);
    w[1] = *(const float2*)(wp + RL);
#pragma unroll 1
    for (int p0 = 0; p0 < NP; p0 += 2){
#pragma unroll
        for (int j = 0; j < 2; ++j){
            const int p = p0 + j;
#pragma unroll
            for (int s = 0; s < 2; ++s){
                const int k = 2 * p + s;
                ull na[6];
                load_act<6>(na, actT + (size_t)(k + 1) * 16);
                ull d0 = dup2(s ? w[j].y : w[j].x);
                static ull dummy;  // (unused)
                ull a0[6];
                load_act<6>(a0, actT + (size_t)k * 16);
#pragma unroll
                for (int pp = 0; pp < 6; ++pp) ffma2(acc[pp], a0[pp], d0);
                (void)na; (void)dummy;
            }
            w[j] = *(const float2*)(wp + (size_t)(p + 2) * RL);
        }
    }
}

__device__ __forceinline__ void run_tile12(
    int b0,
    const float* __restrict__ x,    const float* __restrict__ emb,
    const float* __restrict__ sos,
    const float* __restrict__ bi2h,
    const float* __restrict__ bih,  const float* __restrict__ bhh,
    const float* __restrict__ bout,
    float* __restrict__ tokf, int* __restrict__ toki, float* __restrict__ lg)
{
    constexpr int MTT = 12, STT = 16;
    constexpr int OVL = (IROWS * STT > MTT * V_) ? IROWS * STT : MTT * V_;

    extern __shared__ float sm[];
    float* hT0  = sm;
    float* hT1  = hT0 + HROWS * STT;
    float* iT   = hT1 + HROWS * STT;
    float* slog = iT;
    int*   stok = (int*)(iT + OVL);

    const int tid = threadIdx.x;

    for (int q = tid; q < MTT * (DIN / 4); q += NT){
        const int ch  = q & 63;
        const int row = q >> 6;
        float4 v = *(const float4*)(x + (size_t)(b0 + row) * DIN + ch * 4);
        iT[(4 * ch + 0) * STT + row] = v.x;
        iT[(4 * ch + 1) * STT + row] = v.y;
        iT[(4 * ch + 2) * STT + row] = v.z;
        iT[(4 * ch + 3) * STT + row] = v.w;
    }
    __syncthreads();

    float* hcur = hT0;
    float* hnxt = hT1;

#pragma unroll 1
    for (int c = 0; c < H_; c += 256){
        const int col = c + tid;
        ull acc[6] = {};
        chain1G<DIN, 2 * H_>(acc, g_Wi2hT, col, iT);
        const float b = bi2h[col];
#pragma unroll
        for (int p = 0; p < 6; ++p){
            float lo, hi; unpack2(acc[p], lo, hi);
            hcur[col * STT + 2 * p + 0] = __fadd_rn(lo, b);
            hcur[col * STT + 2 * p + 1] = __fadd_rn(hi, b);
        }
    }
    __syncthreads();

    for (int q = tid; q < E_ * MTT; q += NT){
        const int e = q / MTT, r = q % MTT;
        iT[e * STT + r] = sos[e];
    }

#pragma unroll 1
    for (int t = 0; t < L_; ++t){
        __syncthreads();
#pragma unroll 1
        for (int c = 0; c < H_; c += 256){
            const int col = c + tid;
            ull gi[3][6] = {};
            ull gh[3][6] = {};
            chain3G<E_, 2 * 3 * H_>(gi, g_WihT, col, iT);
            chain3G<H_, 2 * 3 * H_>(gh, g_WhhT, col, hcur);
            const float bir = bih[col], biz = bih[col + H_], bin = bih[col + 2 * H_];
            const float bhr = bhh[col], bhz = bhh[col + H_], bhn = bhh[col + 2 * H_];
#pragma unroll
            for (int p = 0; p < 6; ++p){
                float giR0, giR1, giZ0, giZ1, giN0, giN1;
                float ghR0, ghR1, ghZ0, ghZ1, ghN0, ghN1;
                unpack2(gi[0][p], giR0, giR1); unpack2(gi[1][p], giZ0, giZ1); unpack2(gi[2][p], giN0, giN1);
                unpack2(gh[0][p], ghR0, ghR1); unpack2(gh[1][p], ghZ0, ghZ1); unpack2(gh[2][p], ghN0, ghN1);
                gru_epilogue_pair(hnxt, hcur, col, STT, 2 * p + 0,
                                  giR0, giZ0, giN0, ghR0, ghZ0, ghN0, bir, biz, bin, bhr, bhz, bhn);
                gru_epilogue_pair(hnxt, hcur, col, STT, 2 * p + 1,
                                  giR1, giZ1, giN1, ghR1, ghZ1, ghN1, bir, biz, bin, bhr, bhz, bhn);
            }
        }
        __syncthreads();

        logits_argmax_gather<MTT, STT>(b0, t, hnxt, slog, stok, emb, bout, tokf, toki, lg, iT);

        float* tmp = hcur; hcur = hnxt; hnxt = tmp;
    }
}

// ================== dispatch: pair one MT16 with one MT12 per SM via bid%148 ==================
__global__ void __launch_bounds__(NT, 2)
rnn_decoder_kernel(
    const float* __restrict__ x,    const float* __restrict__ emb,
    const float* __restrict__ sos,
    const float* __restrict__ bi2h,
    const float* __restrict__ bih,  const float* __restrict__ bhh,
    const float* __restrict__ bout,
    float* __restrict__ tokf, int* __restrict__ toki, float* __restrict__ lg)
{
    const int bid = blockIdx.x;
    int n16, n12; bool is16;
    if (bid < 148)      { n16 = bid;              n12 = 0;                 is16 = true;  }
    else if (bid < 296) { n16 = 148;              n12 = bid - 148;         is16 = false; }
    else if (bid < 420) { n16 = 148 + bid - 296;  n12 = 148;               is16 = true;  }
    else                { n16 = 272;              n12 = 148 + (bid - 420); is16 = false; }
    const int b0 = n16 * 16 + n12 * 12;
    if (is16) run_tile16(b0, x, emb, sos, bi2h, bih, bhh, bout, tokf, toki, lg);
    else      run_tile12(b0, x, emb, sos, bi2h, bih, bhh, bout, tokf, toki, lg);
}

extern "C" void kernel_launch(void* const* d_in, const int* in_sizes, int n_in,
                              void* d_out, int out_size) {
    const float* x    = (const float*)d_in[0];
    const float* emb  = (const float*)d_in[1];
    const float* sos  = (const float*)d_in[2];
    const float* Wi2h = (const float*)d_in[3];
    const float* bi2h = (const float*)d_in[4];
    const float* Wih  = (const float*)d_in[5];
    const float* Whh  = (const float*)d_in[6];
    const float* bih  = (const float*)d_in[7];
    const float* bhh  = (const float*)d_in[8];
    const float* Wout = (const float*)d_in[9];
    const float* bout = (const float*)d_in[10];

    float *dWihT, *dWhhT, *dWoutT, *dWi2hT;
    cudaGetSymbolAddress((void**)&dWihT,  g_WihT);
    cudaGetSymbolAddress((void**)&dWhhT,  g_WhhT);
    cudaGetSymbolAddress((void**)&dWoutT, g_WoutT);
    cudaGetSymbolAddress((void**)&dWi2hT, g_Wi2hT);

    stage_weights_kernel<<<1024, 256>>>(Wih, Whh, Wout, Wi2h,
                                        dWihT, dWhhT, dWoutT, dWi2hT);

    const long long TOKN = (long long)B_ * L_;        // 262144
    const long long LGN  = TOKN * V_;                 // 67108864
    const long long os   = (long long)out_size;

    float* tokf = nullptr;
    int*   toki = nullptr;
    float* lg   = nullptr;

    if (os == TOKN + LGN){           // (tokens, logits) concatenated as float32
        tokf = (float*)d_out;
        lg   = (float*)d_out + TOKN;
    } else if (os == LGN){           // logits only
        lg   = (float*)d_out;
    } else if (os == TOKN){          // tokens only (int32)
        toki = (int*)d_out;
    } else {                         // best guess
        tokf = (float*)d_out;
        lg   = (float*)d_out + TOKN;
    }

    // smem sized for the larger (MT=16) tile
    constexpr int ST16  = 20;
    constexpr int OVL16 = (IROWS * ST16 > 16 * V_) ? IROWS * ST16 : 16 * V_;
    const size_t smem = (size_t)(2 * HROWS * ST16 + OVL16) * sizeof(float) + 16 * sizeof(int);
    cudaFuncSetAttribute(rnn_decoder_kernel,
                         cudaFuncAttributeMaxDynamicSharedMemorySize, (int)smem);
    rnn_decoder_kernel<<<GRID, NT, smem>>>(
        x, emb, sos, bi2h, bih, bhh, bout,
        tokf, toki, lg);
}

// round 14
// speedup vs baseline: 5.6858x; 1.0550x over previous
#include <cuda_runtime.h>
#include <math.h>

// ---------------- problem dims ----------------
constexpr int B_  = 8192;
constexpr int L_  = 32;
constexpr int V_  = 256;
constexpr int DIN = 256;
constexpr int H_  = 512;
constexpr int E_  = 256;

constexpr int NT  = 256;   // threads per CTA
constexpr int GRID = 592;  // 2 clean waves on 296 dual-slots; 272*16 + 320*12 = 8192

typedef unsigned long long ull;

// ---------------- paired-k weight scratch (NOT duplicated), padded +4 pair-rows ----------------
__device__ float g_WihT [(E_  / 2 + 4) * 2 * (3 * H_)];
__device__ float g_WhhT [(H_  / 2 + 4) * 2 * (3 * H_)];
__device__ float g_WoutT[(H_  / 2 + 4) * 2 * V_];
__device__ float g_Wi2hT[(DIN / 2 + 4) * 2 * H_];

__global__ void stage_weights_kernel(
    const float* __restrict__ Wih,  const float* __restrict__ Whh,
    const float* __restrict__ Wout, const float* __restrict__ Wi2h,
    float* __restrict__ o_ih, float* __restrict__ o_hh,
    float* __restrict__ o_out, float* __restrict__ o_i2h)
{
    const long N0 = 1536L * 256, N1 = 1536L * 512, N2 = 256L * 512, N3 = 512L * 256;
    const long NTOT = N0 + N1 + N2 + N3;
    for (long e = (long)blockIdx.x * blockDim.x + threadIdx.x; e < NTOT;
         e += (long)gridDim.x * blockDim.x){
        const float* W; float* o; int J, K; long r = e;
        if (r < N0)            { W = Wih;  o = o_ih;  J = 1536; K = 256; }
        else if ((r -= N0) < N1){ W = Whh;  o = o_hh;  J = 1536; K = 512; }
        else if ((r -= N1) < N2){ W = Wout; o = o_out; J = 256;  K = 512; }
        else { r -= N2;          W = Wi2h; o = o_i2h; J = 512;  K = 256; }
        int j = (int)(r / K), k = (int)(r % K);
        o[(size_t)(k >> 1) * (2 * J) + 2 * j + (k & 1)] = W[r];
    }
}

// ---------------- packed f32x2 FMA ----------------
__device__ __forceinline__ void ffma2(ull &d, ull a, ull b){
    asm("fma.rn.f32x2 %0, %1, %2, %0;" : "+l"(d) : "l"(a), "l"(b));
}
__device__ __forceinline__ ull dup2(float w){
    ull r; asm("mov.b64 %0, {%1, %1};" : "=l"(r) : "f"(w)); return r;
}
__device__ __forceinline__ void unpack2(ull v, float &lo, float &hi){
    asm("mov.b64 {%0, %1}, %2;" : "=f"(lo), "=f"(hi) : "l"(v));
}

// ---------------- XLA:CPU exp/sigmoid/tanh (bit-exact emulation) ----------------
__device__ __forceinline__ float xla_exp(float x){
    float c  = fminf(fmaxf(x, -88.3762626647949f), 88.3762626647950f);
    float fx = floorf(__fmaf_rn(c, 1.44269504088896341f, 0.5f));
    float t1 = __fmul_rn(0.693359375f, fx);
    float t2 = __fmul_rn(-2.12194440e-4f, fx);
    float r  = __fadd_rn(c, -t1);
    r        = __fadd_rn(r, -t2);
    float r2 = __fmul_rn(r, r);
    float y  = 1.9875691500e-4f;
    y = __fmaf_rn(y, r, 1.3981999507e-3f);
    y = __fmaf_rn(y, r, 8.3334519073e-3f);
    y = __fmaf_rn(y, r, 4.1665795894e-2f);
    y = __fmaf_rn(y, r, 1.6666665459e-1f);
    y = __fmaf_rn(y, r, 5.0000001201e-1f);
    y = __fmaf_rn(y, r2, r);
    y = __fadd_rn(y, 1.0f);
    int n = (int)fx;
    float p2n = __int_as_float((n + 127) << 23);
    return __fmul_rn(y, p2n);
}
__device__ __forceinline__ float xla_sigmoid(float x){
    float e = xla_exp(-x);
    return __fdiv_rn(1.0f, __fadd_rn(1.0f, e));
}
__device__ __forceinline__ float xla_tanh(float x){
    float ax = fabsf(x);
    float xc = fminf(fmaxf(x, -9.0f), 9.0f);
    float x2 = __fmul_rn(xc, xc);
    float np = -2.76076847742355e-16f;
    np = __fmaf_rn(np, x2, 2.00018790482477e-13f);
    np = __fmaf_rn(np, x2, -8.60467152213735e-11f);
    np = __fmaf_rn(np, x2, 5.12229709037114e-08f);
    np = __fmaf_rn(np, x2, 1.48572235717979e-05f);
    np = __fmaf_rn(np, x2, 6.37261928875436e-04f);
    np = __fmaf_rn(np, x2, 4.89352455891786e-03f);
    np = __fmul_rn(np, xc);
    float dp = 1.19825839466702e-06f;
    dp = __fmaf_rn(dp, x2, 1.18534705686654e-04f);
    dp = __fmaf_rn(dp, x2, 2.26843463243900e-03f);
    dp = __fmaf_rn(dp, x2, 4.89352518554385e-03f);
    float res = __fdiv_rn(np, dp);
    return (ax < 0.0004f) ? x : res;
}

// ---- activation loads: P row-pairs starting at base ----
template<int P>
__device__ __forceinline__ void load_act(ull (&a)[P], const float* base){
    if constexpr (P == 4){
        ulonglong2 v0 = *(const ulonglong2*)(base);
        ulonglong2 v1 = *(const ulonglong2*)(base + 4);
        a[0] = v0.x; a[1] = v0.y; a[2] = v1.x; a[3] = v1.y;
    } else if constexpr (P == 6){
        ulonglong2 v0 = *(const ulonglong2*)(base);
        ulonglong2 v1 = *(const ulonglong2*)(base + 4);
        ulonglong2 v2 = *(const ulonglong2*)(base + 8);
        a[0] = v0.x; a[1] = v0.y; a[2] = v1.x; a[3] = v1.y; a[4] = v2.x; a[5] = v2.y;
    } else {  // P == 3
        a[0] = *(const ull*)(base);
        a[1] = *(const ull*)(base + 2);
        a[2] = *(const ull*)(base + 4);
    }
}

constexpr int HROWS = H_ + 1;   // +1 pad k-row for unconditional prefetch
constexpr int IROWS = E_ + 1;

// ================== 2-group MT16 path (R12/R13-proven, unchanged) ==================
template<int P, int STT, int KK, int RL>
__device__ __forceinline__ void chain3CT(ull (&acc)[3][P],
    const float* __restrict__ wT, int col,
    const float* __restrict__ actT, int row0)
{
    const float* w0p = wT + 2 * col;
    const float* w1p = wT + 2 * (col + H_);
    const float* w2p = wT + 2 * (col + 2 * H_);
    constexpr int NP = KK / 2;
    float2 w[4][3];
#pragma unroll
    for (int j = 0; j < 4; ++j){
        w[j][0] = *(const float2*)(w0p + (size_t)j * RL);
        w[j][1] = *(const float2*)(w1p + (size_t)j * RL);
        w[j][2] = *(const float2*)(w2p + (size_t)j * RL);
    }
    ull a[P];
    load_act<P>(a, actT + row0);
#pragma unroll 1
    for (int p0 = 0; p0 < NP; p0 += 4){
#pragma unroll
        for (int j = 0; j < 4; ++j){
            const int p = p0 + j;
#pragma unroll
            for (int s = 0; s < 2; ++s){
                const int k = 2 * p + s;
                ull na[P];
                load_act<P>(na, actT + (size_t)(k + 1) * STT + row0);
                ull d0 = dup2(s ? w[j][0].y : w[j][0].x);
                ull d1 = dup2(s ? w[j][1].y : w[j][1].x);
                ull d2 = dup2(s ? w[j][2].y : w[j][2].x);
#pragma unroll
                for (int pp = 0; pp < P; ++pp) ffma2(acc[0][pp], a[pp], d0);
#pragma unroll
                for (int pp = 0; pp < P; ++pp) ffma2(acc[1][pp], a[pp], d1);
#pragma unroll
                for (int pp = 0; pp < P; ++pp) ffma2(acc[2][pp], a[pp], d2);
#pragma unroll
                for (int pp = 0; pp < P; ++pp) a[pp] = na[pp];
            }
            const int pn = p + 4;
            w[j][0] = *(const float2*)(w0p + (size_t)pn * RL);
            w[j][1] = *(const float2*)(w1p + (size_t)pn * RL);
            w[j][2] = *(const float2*)(w2p + (size_t)pn * RL);
        }
    }
}

template<int P, int STT, int KK, int RL>
__device__ __forceinline__ void chain1CT(ull (&acc)[P],
    const float* __restrict__ wT, int col,
    const float* __restrict__ actT, int row0)
{
    const float* wp = wT + 2 * col;
    constexpr int NP = KK / 2;
    float2 w[4];
#pragma unroll
    for (int j = 0; j < 4; ++j)
        w[j] = *(const float2*)(wp + (size_t)j * RL);
    ull a[P];
    load_act<P>(a, actT + row0);
#pragma unroll 1
    for (int p0 = 0; p0 < NP; p0 += 4){
#pragma unroll
        for (int j = 0; j < 4; ++j){
            const int p = p0 + j;
#pragma unroll
            for (int s = 0; s < 2; ++s){
                const int k = 2 * p + s;
                ull na[P];
                load_act<P>(na, actT + (size_t)(k + 1) * STT + row0);
                ull d0 = dup2(s ? w[j].y : w[j].x);
#pragma unroll
                for (int pp = 0; pp < P; ++pp) ffma2(acc[pp], a[pp], d0);
#pragma unroll
                for (int pp = 0; pp < P; ++pp) a[pp] = na[pp];
            }
            w[j] = *(const float2*)(wp + (size_t)(p + 4) * RL);
        }
    }
}

// ---- shared epilogue helpers ----
__device__ __forceinline__ void gru_epilogue_pair(
    float* hnxt, const float* hcur, int col, int STT, int row,
    float dIR, float dIZ, float dIN, float dHR, float dHZ, float dHN,
    float bir, float biz, float bin, float bhr, float bhz, float bhn)
{
    float ir = __fadd_rn(dIR, bir), hr = __fadd_rn(dHR, bhr);
    float iz = __fadd_rn(dIZ, biz), hz = __fadd_rn(dHZ, bhz);
    float in_ = __fadd_rn(dIN, bin), hn = __fadd_rn(dHN, bhn);
    float rg = xla_sigmoid(__fadd_rn(ir, hr));
    float zg = xla_sigmoid(__fadd_rn(iz, hz));
    float npre = __fadd_rn(in_, __fmul_rn(rg, hn));
    float n  = xla_tanh(npre);
    float ho = hcur[col * STT + row];
    float omz = __fadd_rn(1.0f, -zg);
    hnxt[col * STT + row] = __fadd_rn(__fmul_rn(omz, n), __fmul_rn(zg, ho));
}

// ---- logits + argmax + gather (shared; rows = MTT, NA = MTT/2) ----
template<int MTT, int STT>
__device__ __forceinline__ void logits_argmax_gather(
    int b0, int t, float* hnxt, float* slog, int* stok,
    const float* __restrict__ emb, const float* __restrict__ bout,
    float* __restrict__ tokf, int* __restrict__ toki, float* __restrict__ lg,
    float* iT)
{
    constexpr int NA = MTT / 2;
    const int tid  = threadIdx.x;
    const int lane = tid & 31;
    const int wid  = tid >> 5;
    {
        const int colA = tid & 255;
        ull aA[NA];
#pragma unroll
        for (int p = 0; p < NA; ++p) aA[p] = 0ULL;
        const float* wp = g_WoutT + 2 * colA;
        constexpr int NPL = H_ / 2;
        float2 w[4];
#pragma unroll
        for (int j = 0; j < 4; ++j)
            w[j] = *(const float2*)(wp + (size_t)j * 512);
        ull av[NA];
#pragma unroll
        for (int h2 = 0; h2 < NA / 2; ++h2){
            ulonglong2 v = *(const ulonglong2*)(hnxt + 4 * h2);
            av[2 * h2] = v.x; av[2 * h2 + 1] = v.y;
        }
#pragma unroll 1
        for (int p0 = 0; p0 < NPL; p0 += 4){
#pragma unroll
            for (int j = 0; j < 4; ++j){
                const int p = p0 + j;
#pragma unroll
                for (int s = 0; s < 2; ++s){
                    const int k = 2 * p + s;
                    ull nav[NA];
                    {
                        const float* abn = hnxt + (size_t)(k + 1) * STT;
#pragma unroll
                        for (int h2 = 0; h2 < NA / 2; ++h2){
                            ulonglong2 v = *(const ulonglong2*)(abn + 4 * h2);
                            nav[2 * h2] = v.x; nav[2 * h2 + 1] = v.y;
                        }
                    }
                    ull da = dup2(s ? w[j].y : w[j].x);
#pragma unroll
                    for (int p2 = 0; p2 < NA; ++p2) ffma2(aA[p2], av[p2], da);
#pragma unroll
                    for (int p2 = 0; p2 < NA; ++p2) av[p2] = nav[p2];
                }
                w[j] = *(const float2*)(wp + (size_t)(p + 4) * 512);
            }
        }
        const float boA = bout[colA];
#pragma unroll
        for (int p = 0; p < NA; ++p){
            float a0, a1; unpack2(aA[p], a0, a1);
            const int rA = 2 * p, rB = rA + 1;
            float lv0 = __fadd_rn(a0, boA), lv1 = __fadd_rn(a1, boA);
            slog[rA * V_ + colA] = lv0;
            slog[rB * V_ + colA] = lv1;
            if (lg){
                lg[(size_t)(b0 + rA) * (L_ * V_) + (size_t)t * V_ + colA] = lv0;
                lg[(size_t)(b0 + rB) * (L_ * V_) + (size_t)t * V_ + colA] = lv1;
            }
        }
    }
    __syncthreads();   // slog complete

#pragma unroll
    for (int rr2 = 0; rr2 < 2; ++rr2){
        const int row = wid * 2 + rr2;
        if (row < MTT){
            float bv = -1e30f; int bi = 0;
#pragma unroll
            for (int j = 0; j < 8; ++j){
                const int idx = lane + 32 * j;
                float v = slog[row * V_ + idx];
                if (v > bv){ bv = v; bi = idx; }
            }
#pragma unroll
            for (int off = 16; off > 0; off >>= 1){
                float ov = __shfl_down_sync(0xffffffffu, bv, off);
                int   oi = __shfl_down_sync(0xffffffffu, bi, off);
                if (ov > bv || (ov == bv && oi < bi)){ bv = ov; bi = oi; }
            }
            if (lane == 0){
                stok[row] = bi;
                if (tokf) tokf[(size_t)(b0 + row) * L_ + t] = (float)bi;
                if (toki) toki[(size_t)(b0 + row) * L_ + t] = bi;
            }
        }
    }
    __syncthreads();   // stok visible

    for (int q = threadIdx.x; q < MTT * (E_ / 4); q += NT){
        const int row = q >> 6;
        const int ch  = q & 63;
        float4 v = *(const float4*)(emb + (size_t)stok[row] * E_ + ch * 4);
        iT[(4 * ch + 0) * STT + row] = v.x;
        iT[(4 * ch + 1) * STT + row] = v.y;
        iT[(4 * ch + 2) * STT + row] = v.z;
        iT[(4 * ch + 3) * STT + row] = v.w;
    }
}

// ================== MT16, 2 groups x 8 rows (unchanged) ==================
__device__ __forceinline__ void run_tile16(
    int b0,
    const float* __restrict__ x,    const float* __restrict__ emb,
    const float* __restrict__ sos,
    const float* __restrict__ bi2h,
    const float* __restrict__ bih,  const float* __restrict__ bhh,
    const float* __restrict__ bout,
    float* __restrict__ tokf, int* __restrict__ toki, float* __restrict__ lg)
{
    constexpr int MTT = 16, STT = 20, P = 4, RPG = 8;
    constexpr int OVL = (IROWS * STT > MTT * V_) ? IROWS * STT : MTT * V_;

    extern __shared__ float sm[];
    float* hT0  = sm;
    float* hT1  = hT0 + HROWS * STT;
    float* iT   = hT1 + HROWS * STT;
    float* slog = iT;
    int*   stok = (int*)(iT + OVL);

    const int tid  = threadIdx.x;
    const int cx   = tid & 127;
    const int row0 = (tid >> 7) * RPG;

    for (int q = tid; q < MTT * (DIN / 4); q += NT){
        const int ch  = q & 63;
        const int row = q >> 6;
        float4 v = *(const float4*)(x + (size_t)(b0 + row) * DIN + ch * 4);
        iT[(4 * ch + 0) * STT + row] = v.x;
        iT[(4 * ch + 1) * STT + row] = v.y;
        iT[(4 * ch + 2) * STT + row] = v.z;
        iT[(4 * ch + 3) * STT + row] = v.w;
    }
    __syncthreads();

    float* hcur = hT0;
    float* hnxt = hT1;

#pragma unroll 1
    for (int c = 0; c < H_; c += 128){
        const int col = c + cx;
        ull acc[P] = {};
        chain1CT<P, STT, DIN, 2 * H_>(acc, g_Wi2hT, col, iT, row0);
        const float b = bi2h[col];
#pragma unroll
        for (int p = 0; p < P; ++p){
            float lo, hi; unpack2(acc[p], lo, hi);
            hcur[col * STT + row0 + 2 * p + 0] = __fadd_rn(lo, b);
            hcur[col * STT + row0 + 2 * p + 1] = __fadd_rn(hi, b);
        }
    }
    __syncthreads();

    for (int q = tid; q < E_ * MTT; q += NT){
        const int e = q / MTT, r = q % MTT;
        iT[e * STT + r] = sos[e];
    }

#pragma unroll 1
    for (int t = 0; t < L_; ++t){
        __syncthreads();
#pragma unroll 1
        for (int c = 0; c < H_; c += 128){
            const int col = c + cx;
            ull gi[3][P] = {};
            ull gh[3][P] = {};
            chain3CT<P, STT, E_, 2 * 3 * H_>(gi, g_WihT, col, iT,   row0);
            chain3CT<P, STT, H_, 2 * 3 * H_>(gh, g_WhhT, col, hcur, row0);
            const float bir = bih[col], biz = bih[col + H_], bin = bih[col + 2 * H_];
            const float bhr = bhh[col], bhz = bhh[col + H_], bhn = bhh[col + 2 * H_];
#pragma unroll
            for (int p = 0; p < P; ++p){
                float giR0, giR1, giZ0, giZ1, giN0, giN1;
                float ghR0, ghR1, ghZ0, ghZ1, ghN0, ghN1;
                unpack2(gi[0][p], giR0, giR1); unpack2(gi[1][p], giZ0, giZ1); unpack2(gi[2][p], giN0, giN1);
                unpack2(gh[0][p], ghR0, ghR1); unpack2(gh[1][p], ghZ0, ghZ1); unpack2(gh[2][p], ghN0, ghN1);
                gru_epilogue_pair(hnxt, hcur, col, STT, row0 + 2 * p + 0,
                                  giR0, giZ0, giN0, ghR0, ghZ0, ghN0, bir, biz, bin, bhr, bhz, bhn);
                gru_epilogue_pair(hnxt, hcur, col, STT, row0 + 2 * p + 1,
                                  giR1, giZ1, giN1, ghR1, ghZ1, ghN1, bir, biz, bin, bhr, bhz, bhn);
            }
        }
        __syncthreads();

        logits_argmax_gather<MTT, STT>(b0, t, hnxt, slog, stok, emb, bout, tokf, toki, lg, iT);

        float* tmp = hcur; hcur = hnxt; hnxt = tmp;
    }
}

// ================== MT12, 1 group x 12 rows ==================
// R14: weight prefetch depth 2 -> 4 (covers L2 latency); activation prefetch
// removed (29-cyc LDS easily covered by 4 warps/SMSP) to pay the register bill.
template<int KK, int RL>
__device__ __forceinline__ void chain3G(ull (&acc)[3][6],
    const float* __restrict__ wT, int col,
    const float* __restrict__ actT /* STT = 16 */)
{
    const float* w0p = wT + 2 * col;
    const float* w1p = wT + 2 * (col + H_);
    const float* w2p = wT + 2 * (col + 2 * H_);
    constexpr int NP = KK / 2;
    float2 w[4][3];
#pragma unroll
    for (int j = 0; j < 4; ++j){
        w[j][0] = *(const float2*)(w0p + (size_t)j * RL);
        w[j][1] = *(const float2*)(w1p + (size_t)j * RL);
        w[j][2] = *(const float2*)(w2p + (size_t)j * RL);
    }
#pragma unroll 1
    for (int p0 = 0; p0 < NP; p0 += 4){
#pragma unroll
        for (int j = 0; j < 4; ++j){
            const int p = p0 + j;
#pragma unroll
            for (int s = 0; s < 2; ++s){
                const int k = 2 * p + s;
                ull a[6];
                load_act<6>(a, actT + (size_t)k * 16);
                ull d0 = dup2(s ? w[j][0].y : w[j][0].x);
                ull d1 = dup2(s ? w[j][1].y : w[j][1].x);
                ull d2 = dup2(s ? w[j][2].y : w[j][2].x);
#pragma unroll
                for (int pp = 0; pp < 6; ++pp) ffma2(acc[0][pp], a[pp], d0);
#pragma unroll
                for (int pp = 0; pp < 6; ++pp) ffma2(acc[1][pp], a[pp], d1);
#pragma unroll
                for (int pp = 0; pp < 6; ++pp) ffma2(acc[2][pp], a[pp], d2);
            }
            const int pn = p + 4;                       // pad rows absorb p>=NP
            w[j][0] = *(const float2*)(w0p + (size_t)pn * RL);
            w[j][1] = *(const float2*)(w1p + (size_t)pn * RL);
            w[j][2] = *(const float2*)(w2p + (size_t)pn * RL);
        }
    }
}

template<int KK, int RL>
__device__ __forceinline__ void chain1G(ull (&acc)[6],
    const float* __restrict__ wT, int col,
    const float* __restrict__ actT)
{
    const float* wp = wT + 2 * col;
    constexpr int NP = KK / 2;
    float2 w[4];
#pragma unroll
    for (int j = 0; j < 4; ++j)
        w[j] = *(const float2*)(wp + (size_t)j * RL);
#pragma unroll 1
    for (int p0 = 0; p0 < NP; p0 += 4){
#pragma unroll
        for (int j = 0; j < 4; ++j){
            const int p = p0 + j;
#pragma unroll
            for (int s = 0; s < 2; ++s){
                const int k = 2 * p + s;
                ull a[6];
                load_act<6>(a, actT + (size_t)k * 16);
                ull d0 = dup2(s ? w[j].y : w[j].x);
#pragma unroll
                for (int pp = 0; pp < 6; ++pp) ffma2(acc[pp], a[pp], d0);
            }
            w[j] = *(const float2*)(wp + (size_t)(p + 4) * RL);
        }
    }
}

__device__ __forceinline__ void run_tile12(
    int b0,
    const float* __restrict__ x,    const float* __restrict__ emb,
    const float* __restrict__ sos,
    const float* __restrict__ bi2h,
    const float* __restrict__ bih,  const float* __restrict__ bhh,
    const float* __restrict__ bout,
    float* __restrict__ tokf, int* __restrict__ toki, float* __restrict__ lg)
{
    constexpr int MTT = 12, STT = 16;
    constexpr int OVL = (IROWS * STT > MTT * V_) ? IROWS * STT : MTT * V_;

    extern __shared__ float sm[];
    float* hT0  = sm;
    float* hT1  = hT0 + HROWS * STT;
    float* iT   = hT1 + HROWS * STT;
    float* slog = iT;
    int*   stok = (int*)(iT + OVL);

    const int tid = threadIdx.x;

    for (int q = tid; q < MTT * (DIN / 4); q += NT){
        const int ch  = q & 63;
        const int row = q >> 6;
        float4 v = *(const float4*)(x + (size_t)(b0 + row) * DIN + ch * 4);
        iT[(4 * ch + 0) * STT + row] = v.x;
        iT[(4 * ch + 1) * STT + row] = v.y;
        iT[(4 * ch + 2) * STT + row] = v.z;
        iT[(4 * ch + 3) * STT + row] = v.w;
    }
    __syncthreads();

    float* hcur = hT0;
    float* hnxt = hT1;

#pragma unroll 1
    for (int c = 0; c < H_; c += 256){
        const int col = c + tid;
        ull acc[6] = {};
        chain1G<DIN, 2 * H_>(acc, g_Wi2hT, col, iT);
        const float b = bi2h[col];
#pragma unroll
        for (int p = 0; p < 6; ++p){
            float lo, hi; unpack2(acc[p], lo, hi);
            hcur[col * STT + 2 * p + 0] = __fadd_rn(lo, b);
            hcur[col * STT + 2 * p + 1] = __fadd_rn(hi, b);
        }
    }
    __syncthreads();

    for (int q = tid; q < E_ * MTT; q += NT){
        const int e = q / MTT, r = q % MTT;
        iT[e * STT + r] = sos[e];
    }

#pragma unroll 1
    for (int t = 0; t < L_; ++t){
        __syncthreads();
#pragma unroll 1
        for (int c = 0; c < H_; c += 256){
            const int col = c + tid;
            ull gi[3][6] = {};
            ull gh[3][6] = {};
            chain3G<E_, 2 * 3 * H_>(gi, g_WihT, col, iT);
            chain3G<H_, 2 * 3 * H_>(gh, g_WhhT, col, hcur);
            const float bir = bih[col], biz = bih[col + H_], bin = bih[col + 2 * H_];
            const float bhr = bhh[col], bhz = bhh[col + H_], bhn = bhh[col + 2 * H_];
#pragma unroll
            for (int p = 0; p < 6; ++p){
                float giR0, giR1, giZ0, giZ1, giN0, giN1;
                float ghR0, ghR1, ghZ0, ghZ1, ghN0, ghN1;
                unpack2(gi[0][p], giR0, giR1); unpack2(gi[1][p], giZ0, giZ1); unpack2(gi[2][p], giN0, giN1);
                unpack2(gh[0][p], ghR0, ghR1); unpack2(gh[1][p], ghZ0, ghZ1); unpack2(gh[2][p], ghN0, ghN1);
                gru_epilogue_pair(hnxt, hcur, col, STT, 2 * p + 0,
                                  giR0, giZ0, giN0, ghR0, ghZ0, ghN0, bir, biz, bin, bhr, bhz, bhn);
                gru_epilogue_pair(hnxt, hcur, col, STT, 2 * p + 1,
                                  giR1, giZ1, giN1, ghR1, ghZ1, ghN1, bir, biz, bin, bhr, bhz, bhn);
            }
        }
        __syncthreads();

        logits_argmax_gather<MTT, STT>(b0, t, hnxt, slog, stok, emb, bout, tokf, toki, lg, iT);

        float* tmp = hcur; hcur = hnxt; hnxt = tmp;
    }
}

// ================== dispatch: pair one MT16 with one MT12 per SM via bid%148 ==================
__global__ void __launch_bounds__(NT, 2)
rnn_decoder_kernel(
    const float* __restrict__ x,    const float* __restrict__ emb,
    const float* __restrict__ sos,
    const float* __restrict__ bi2h,
    const float* __restrict__ bih,  const float* __restrict__ bhh,
    const float* __restrict__ bout,
    float* __restrict__ tokf, int* __restrict__ toki, float* __restrict__ lg)
{
    const int bid = blockIdx.x;
    int n16, n12; bool is16;
    if (bid < 148)      { n16 = bid;              n12 = 0;                 is16 = true;  }
    else if (bid < 296) { n16 = 148;              n12 = bid - 148;         is16 = false; }
    else if (bid < 420) { n16 = 148 + bid - 296;  n12 = 148;               is16 = true;  }
    else                { n16 = 272;              n12 = 148 + (bid - 420); is16 = false; }
    const int b0 = n16 * 16 + n12 * 12;
    if (is16) run_tile16(b0, x, emb, sos, bi2h, bih, bhh, bout, tokf, toki, lg);
    else      run_tile12(b0, x, emb, sos, bi2h, bih, bhh, bout, tokf, toki, lg);
}

extern "C" void kernel_launch(void* const* d_in, const int* in_sizes, int n_in,
                              void* d_out, int out_size) {
    const float* x    = (const float*)d_in[0];
    const float* emb  = (const float*)d_in[1];
    const float* sos  = (const float*)d_in[2];
    const float* Wi2h = (const float*)d_in[3];
    const float* bi2h = (const float*)d_in[4];
    const float* Wih  = (const float*)d_in[5];
    const float* Whh  = (const float*)d_in[6];
    const float* bih  = (const float*)d_in[7];
    const float* bhh  = (const float*)d_in[8];
    const float* Wout = (const float*)d_in[9];
    const float* bout = (const float*)d_in[10];

    float *dWihT, *dWhhT, *dWoutT, *dWi2hT;
    cudaGetSymbolAddress((void**)&dWihT,  g_WihT);
    cudaGetSymbolAddress((void**)&dWhhT,  g_WhhT);
    cudaGetSymbolAddress((void**)&dWoutT, g_WoutT);
    cudaGetSymbolAddress((void**)&dWi2hT, g_Wi2hT);

    stage_weights_kernel<<<1024, 256>>>(Wih, Whh, Wout, Wi2h,
                                        dWihT, dWhhT, dWoutT, dWi2hT);

    const long long TOKN = (long long)B_ * L_;        // 262144
    const long long LGN  = TOKN * V_;                 // 67108864
    const long long os   = (long long)out_size;

    float* tokf = nullptr;
    int*   toki = nullptr;
    float* lg   = nullptr;

    if (os == TOKN + LGN){           // (tokens, logits) concatenated as float32
        tokf = (float*)d_out;
        lg   = (float*)d_out + TOKN;
    } else if (os == LGN){           // logits only
        lg   = (float*)d_out;
    } else if (os == TOKN){          // tokens only (int32)
        toki = (int*)d_out;
    } else {                         // best guess
        tokf = (float*)d_out;
        lg   = (float*)d_out + TOKN;
    }

    // smem sized for the larger (MT=16) tile
    constexpr int ST16  = 20;
    constexpr int OVL16 = (IROWS * ST16 > 16 * V_) ? IROWS * ST16 : 16 * V_;
    const size_t smem = (size_t)(2 * HROWS * ST16 + OVL16) * sizeof(float) + 16 * sizeof(int);
    cudaFuncSetAttribute(rnn_decoder_kernel,
                         cudaFuncAttributeMaxDynamicSharedMemorySize, (int)smem);
    rnn_decoder_kernel<<<GRID, NT, smem>>>(
        x, emb, sos, bi2h, bih, bhh, bout,
        tokf, toki, lg);
}

// round 15
// speedup vs baseline: 5.8592x; 1.0305x over previous
#include <cuda_runtime.h>
#include <math.h>

// ---------------- problem dims ----------------
constexpr int B_  = 8192;
constexpr int L_  = 32;
constexpr int V_  = 256;
constexpr int DIN = 256;
constexpr int H_  = 512;
constexpr int E_  = 256;

constexpr int NT  = 256;   // threads per CTA
constexpr int GRID = 592;  // 2 clean waves on 296 dual-slots; 272*16 + 320*12 = 8192

typedef unsigned long long ull;

// ---------------- paired-k weight scratch (NOT duplicated), padded +4 pair-rows ----------------
__device__ float g_WihT [(E_  / 2 + 4) * 2 * (3 * H_)];
__device__ float g_WhhT [(H_  / 2 + 4) * 2 * (3 * H_)];
__device__ float g_WoutT[(H_  / 2 + 4) * 2 * V_];
__device__ float g_Wi2hT[(DIN / 2 + 4) * 2 * H_];

__global__ void stage_weights_kernel(
    const float* __restrict__ Wih,  const float* __restrict__ Whh,
    const float* __restrict__ Wout, const float* __restrict__ Wi2h,
    float* __restrict__ o_ih, float* __restrict__ o_hh,
    float* __restrict__ o_out, float* __restrict__ o_i2h)
{
    const long N0 = 1536L * 256, N1 = 1536L * 512, N2 = 256L * 512, N3 = 512L * 256;
    const long NTOT = N0 + N1 + N2 + N3;
    for (long e = (long)blockIdx.x * blockDim.x + threadIdx.x; e < NTOT;
         e += (long)gridDim.x * blockDim.x){
        const float* W; float* o; int J, K; long r = e;
        if (r < N0)            { W = Wih;  o = o_ih;  J = 1536; K = 256; }
        else if ((r -= N0) < N1){ W = Whh;  o = o_hh;  J = 1536; K = 512; }
        else if ((r -= N1) < N2){ W = Wout; o = o_out; J = 256;  K = 512; }
        else { r -= N2;          W = Wi2h; o = o_i2h; J = 512;  K = 256; }
        int j = (int)(r / K), k = (int)(r % K);
        o[(size_t)(k >> 1) * (2 * J) + 2 * j + (k & 1)] = W[r];
    }
}

// ---------------- packed f32x2 FMA ----------------
__device__ __forceinline__ void ffma2(ull &d, ull a, ull b){
    asm("fma.rn.f32x2 %0, %1, %2, %0;" : "+l"(d) : "l"(a), "l"(b));
}
__device__ __forceinline__ ull dup2(float w){
    ull r; asm("mov.b64 %0, {%1, %1};" : "=l"(r) : "f"(w)); return r;
}
__device__ __forceinline__ void unpack2(ull v, float &lo, float &hi){
    asm("mov.b64 {%0, %1}, %2;" : "=f"(lo), "=f"(hi) : "l"(v));
}

// ---------------- XLA:CPU exp/sigmoid/tanh (bit-exact emulation) ----------------
__device__ __forceinline__ float xla_exp(float x){
    float c  = fminf(fmaxf(x, -88.3762626647949f), 88.3762626647950f);
    float fx = floorf(__fmaf_rn(c, 1.44269504088896341f, 0.5f));
    float t1 = __fmul_rn(0.693359375f, fx);
    float t2 = __fmul_rn(-2.12194440e-4f, fx);
    float r  = __fadd_rn(c, -t1);
    r        = __fadd_rn(r, -t2);
    float r2 = __fmul_rn(r, r);
    float y  = 1.9875691500e-4f;
    y = __fmaf_rn(y, r, 1.3981999507e-3f);
    y = __fmaf_rn(y, r, 8.3334519073e-3f);
    y = __fmaf_rn(y, r, 4.1665795894e-2f);
    y = __fmaf_rn(y, r, 1.6666665459e-1f);
    y = __fmaf_rn(y, r, 5.0000001201e-1f);
    y = __fmaf_rn(y, r2, r);
    y = __fadd_rn(y, 1.0f);
    int n = (int)fx;
    float p2n = __int_as_float((n + 127) << 23);
    return __fmul_rn(y, p2n);
}
__device__ __forceinline__ float xla_sigmoid(float x){
    float e = xla_exp(-x);
    return __fdiv_rn(1.0f, __fadd_rn(1.0f, e));
}
__device__ __forceinline__ float xla_tanh(float x){
    float ax = fabsf(x);
    float xc = fminf(fmaxf(x, -9.0f), 9.0f);
    float x2 = __fmul_rn(xc, xc);
    float np = -2.76076847742355e-16f;
    np = __fmaf_rn(np, x2, 2.00018790482477e-13f);
    np = __fmaf_rn(np, x2, -8.60467152213735e-11f);
    np = __fmaf_rn(np, x2, 5.12229709037114e-08f);
    np = __fmaf_rn(np, x2, 1.48572235717979e-05f);
    np = __fmaf_rn(np, x2, 6.37261928875436e-04f);
    np = __fmaf_rn(np, x2, 4.89352455891786e-03f);
    np = __fmul_rn(np, xc);
    float dp = 1.19825839466702e-06f;
    dp = __fmaf_rn(dp, x2, 1.18534705686654e-04f);
    dp = __fmaf_rn(dp, x2, 2.26843463243900e-03f);
    dp = __fmaf_rn(dp, x2, 4.89352518554385e-03f);
    float res = __fdiv_rn(np, dp);
    return (ax < 0.0004f) ? x : res;
}

// ---- activation loads: P row-pairs starting at base ----
template<int P>
__device__ __forceinline__ void load_act(ull (&a)[P], const float* base){
    if constexpr (P == 8){
        ulonglong2 v0 = *(const ulonglong2*)(base);
        ulonglong2 v1 = *(const ulonglong2*)(base + 4);
        ulonglong2 v2 = *(const ulonglong2*)(base + 8);
        ulonglong2 v3 = *(const ulonglong2*)(base + 12);
        a[0] = v0.x; a[1] = v0.y; a[2] = v1.x; a[3] = v1.y;
        a[4] = v2.x; a[5] = v2.y; a[6] = v3.x; a[7] = v3.y;
    } else if constexpr (P == 6){
        ulonglong2 v0 = *(const ulonglong2*)(base);
        ulonglong2 v1 = *(const ulonglong2*)(base + 4);
        ulonglong2 v2 = *(const ulonglong2*)(base + 8);
        a[0] = v0.x; a[1] = v0.y; a[2] = v1.x; a[3] = v1.y; a[4] = v2.x; a[5] = v2.y;
    } else if constexpr (P == 4){
        ulonglong2 v0 = *(const ulonglong2*)(base);
        ulonglong2 v1 = *(const ulonglong2*)(base + 4);
        a[0] = v0.x; a[1] = v0.y; a[2] = v1.x; a[3] = v1.y;
    }
}

constexpr int HROWS = H_ + 1;   // +1 pad k-row for unconditional prefetch
constexpr int IROWS = E_ + 1;

// ---- shared epilogue helper ----
__device__ __forceinline__ void gru_epilogue_pair(
    float* hnxt, const float* hcur, int col, int STT, int row,
    float dIR, float dIZ, float dIN, float dHR, float dHZ, float dHN,
    float bir, float biz, float bin, float bhr, float bhz, float bhn)
{
    float ir = __fadd_rn(dIR, bir), hr = __fadd_rn(dHR, bhr);
    float iz = __fadd_rn(dIZ, biz), hz = __fadd_rn(dHZ, bhz);
    float in_ = __fadd_rn(dIN, bin), hn = __fadd_rn(dHN, bhn);
    float rg = xla_sigmoid(__fadd_rn(ir, hr));
    float zg = xla_sigmoid(__fadd_rn(iz, hz));
    float npre = __fadd_rn(in_, __fmul_rn(rg, hn));
    float n  = xla_tanh(npre);
    float ho = hcur[col * STT + row];
    float omz = __fadd_rn(1.0f, -zg);
    hnxt[col * STT + row] = __fadd_rn(__fmul_rn(omz, n), __fmul_rn(zg, ho));
}

// ---- logits + argmax + gather (shared; rows = MTT, NA = MTT/2) ----
template<int MTT, int STT>
__device__ __forceinline__ void logits_argmax_gather(
    int b0, int t, float* hnxt, float* slog, int* stok,
    const float* __restrict__ emb, const float* __restrict__ bout,
    float* __restrict__ tokf, int* __restrict__ toki, float* __restrict__ lg,
    float* iT)
{
    constexpr int NA = MTT / 2;
    const int tid  = threadIdx.x;
    const int lane = tid & 31;
    const int wid  = tid >> 5;
    {
        const int colA = tid & 255;
        ull aA[NA];
#pragma unroll
        for (int p = 0; p < NA; ++p) aA[p] = 0ULL;
        const float* wp = g_WoutT + 2 * colA;
        constexpr int NPL = H_ / 2;
        float2 w[4];
#pragma unroll
        for (int j = 0; j < 4; ++j)
            w[j] = *(const float2*)(wp + (size_t)j * 512);
        ull av[NA];
#pragma unroll
        for (int h2 = 0; h2 < NA / 2; ++h2){
            ulonglong2 v = *(const ulonglong2*)(hnxt + 4 * h2);
            av[2 * h2] = v.x; av[2 * h2 + 1] = v.y;
        }
#pragma unroll 1
        for (int p0 = 0; p0 < NPL; p0 += 4){
#pragma unroll
            for (int j = 0; j < 4; ++j){
                const int p = p0 + j;
#pragma unroll
                for (int s = 0; s < 2; ++s){
                    const int k = 2 * p + s;
                    ull nav[NA];
                    {
                        const float* abn = hnxt + (size_t)(k + 1) * STT;
#pragma unroll
                        for (int h2 = 0; h2 < NA / 2; ++h2){
                            ulonglong2 v = *(const ulonglong2*)(abn + 4 * h2);
                            nav[2 * h2] = v.x; nav[2 * h2 + 1] = v.y;
                        }
                    }
                    ull da = dup2(s ? w[j].y : w[j].x);
#pragma unroll
                    for (int p2 = 0; p2 < NA; ++p2) ffma2(aA[p2], av[p2], da);
#pragma unroll
                    for (int p2 = 0; p2 < NA; ++p2) av[p2] = nav[p2];
                }
                w[j] = *(const float2*)(wp + (size_t)(p + 4) * 512);
            }
        }
        const float boA = bout[colA];
#pragma unroll
        for (int p = 0; p < NA; ++p){
            float a0, a1; unpack2(aA[p], a0, a1);
            const int rA = 2 * p, rB = rA + 1;
            float lv0 = __fadd_rn(a0, boA), lv1 = __fadd_rn(a1, boA);
            slog[rA * V_ + colA] = lv0;
            slog[rB * V_ + colA] = lv1;
            if (lg){
                lg[(size_t)(b0 + rA) * (L_ * V_) + (size_t)t * V_ + colA] = lv0;
                lg[(size_t)(b0 + rB) * (L_ * V_) + (size_t)t * V_ + colA] = lv1;
            }
        }
    }
    __syncthreads();   // slog complete

#pragma unroll
    for (int rr2 = 0; rr2 < 2; ++rr2){
        const int row = wid * 2 + rr2;
        if (row < MTT){
            float bv = -1e30f; int bi = 0;
#pragma unroll
            for (int j = 0; j < 8; ++j){
                const int idx = lane + 32 * j;
                float v = slog[row * V_ + idx];
                if (v > bv){ bv = v; bi = idx; }
            }
#pragma unroll
            for (int off = 16; off > 0; off >>= 1){
                float ov = __shfl_down_sync(0xffffffffu, bv, off);
                int   oi = __shfl_down_sync(0xffffffffu, bi, off);
                if (ov > bv || (ov == bv && oi < bi)){ bv = ov; bi = oi; }
            }
            if (lane == 0){
                stok[row] = bi;
                if (tokf) tokf[(size_t)(b0 + row) * L_ + t] = (float)bi;
                if (toki) toki[(size_t)(b0 + row) * L_ + t] = bi;
            }
        }
    }
    __syncthreads();   // stok visible

    for (int q = threadIdx.x; q < MTT * (E_ / 4); q += NT){
        const int row = q >> 6;
        const int ch  = q & 63;
        float4 v = *(const float4*)(emb + (size_t)stok[row] * E_ + ch * 4);
        iT[(4 * ch + 0) * STT + row] = v.x;
        iT[(4 * ch + 1) * STT + row] = v.y;
        iT[(4 * ch + 2) * STT + row] = v.z;
        iT[(4 * ch + 3) * STT + row] = v.w;
    }
}

// ================== MT16 single-group chains: P=8, weight depth-2, no act prefetch ==================
template<int KK, int RL>
__device__ __forceinline__ void chain3H(ull (&acc)[3][8],
    const float* __restrict__ wT, int col,
    const float* __restrict__ actT /* STT = 20 */)
{
    const float* w0p = wT + 2 * col;
    const float* w1p = wT + 2 * (col + H_);
    const float* w2p = wT + 2 * (col + 2 * H_);
    constexpr int NP = KK / 2;
    float2 w[2][3];
#pragma unroll
    for (int j = 0; j < 2; ++j){
        w[j][0] = *(const float2*)(w0p + (size_t)j * RL);
        w[j][1] = *(const float2*)(w1p + (size_t)j * RL);
        w[j][2] = *(const float2*)(w2p + (size_t)j * RL);
    }
#pragma unroll 1
    for (int p0 = 0; p0 < NP; p0 += 2){
#pragma unroll
        for (int j = 0; j < 2; ++j){
            const int p = p0 + j;
#pragma unroll
            for (int s = 0; s < 2; ++s){
                const int k = 2 * p + s;
                ull a[8];
                load_act<8>(a, actT + (size_t)k * 20);
                ull d0 = dup2(s ? w[j][0].y : w[j][0].x);
                ull d1 = dup2(s ? w[j][1].y : w[j][1].x);
                ull d2 = dup2(s ? w[j][2].y : w[j][2].x);
#pragma unroll
                for (int pp = 0; pp < 8; ++pp) ffma2(acc[0][pp], a[pp], d0);
#pragma unroll
                for (int pp = 0; pp < 8; ++pp) ffma2(acc[1][pp], a[pp], d1);
#pragma unroll
                for (int pp = 0; pp < 8; ++pp) ffma2(acc[2][pp], a[pp], d2);
            }
            const int pn = p + 2;                        // pad rows absorb p>=NP
            w[j][0] = *(const float2*)(w0p + (size_t)pn * RL);
            w[j][1] = *(const float2*)(w1p + (size_t)pn * RL);
            w[j][2] = *(const float2*)(w2p + (size_t)pn * RL);
        }
    }
}

template<int KK, int RL>
__device__ __forceinline__ void chain1H(ull (&acc)[8],
    const float* __restrict__ wT, int col,
    const float* __restrict__ actT)
{
    const float* wp = wT + 2 * col;
    constexpr int NP = KK / 2;
    float2 w[2];
    w[0] = *(const float2*)(wp);
    w[1] = *(const float2*)(wp + RL);
#pragma unroll 1
    for (int p0 = 0; p0 < NP; p0 += 2){
#pragma unroll
        for (int j = 0; j < 2; ++j){
            const int p = p0 + j;
#pragma unroll
            for (int s = 0; s < 2; ++s){
                const int k = 2 * p + s;
                ull a[8];
                load_act<8>(a, actT + (size_t)k * 20);
                ull d0 = dup2(s ? w[j].y : w[j].x);
#pragma unroll
                for (int pp = 0; pp < 8; ++pp) ffma2(acc[pp], a[pp], d0);
            }
            w[j] = *(const float2*)(wp + (size_t)(p + 2) * RL);
        }
    }
}

// ================== MT16, SINGLE group x 16 rows (weights stream once) ==================
__device__ __forceinline__ void run_tile16(
    int b0,
    const float* __restrict__ x,    const float* __restrict__ emb,
    const float* __restrict__ sos,
    const float* __restrict__ bi2h,
    const float* __restrict__ bih,  const float* __restrict__ bhh,
    const float* __restrict__ bout,
    float* __restrict__ tokf, int* __restrict__ toki, float* __restrict__ lg)
{
    constexpr int MTT = 16, STT = 20;
    constexpr int OVL = (IROWS * STT > MTT * V_) ? IROWS * STT : MTT * V_;

    extern __shared__ float sm[];
    float* hT0  = sm;
    float* hT1  = hT0 + HROWS * STT;
    float* iT   = hT1 + HROWS * STT;
    float* slog = iT;
    int*   stok = (int*)(iT + OVL);

    const int tid = threadIdx.x;

    for (int q = tid; q < MTT * (DIN / 4); q += NT){
        const int ch  = q & 63;
        const int row = q >> 6;
        float4 v = *(const float4*)(x + (size_t)(b0 + row) * DIN + ch * 4);
        iT[(4 * ch + 0) * STT + row] = v.x;
        iT[(4 * ch + 1) * STT + row] = v.y;
        iT[(4 * ch + 2) * STT + row] = v.z;
        iT[(4 * ch + 3) * STT + row] = v.w;
    }
    __syncthreads();

    float* hcur = hT0;
    float* hnxt = hT1;

    // ---- h0 = x @ Wi2h^T + bi2h : 2 chunks x 256 cols, 16 rows/thread ----
#pragma unroll 1
    for (int c = 0; c < H_; c += 256){
        const int col = c + tid;
        ull acc[8] = {};
        chain1H<DIN, 2 * H_>(acc, g_Wi2hT, col, iT);
        const float b = bi2h[col];
#pragma unroll
        for (int p = 0; p < 8; ++p){
            float lo, hi; unpack2(acc[p], lo, hi);
            hcur[col * STT + 2 * p + 0] = __fadd_rn(lo, b);
            hcur[col * STT + 2 * p + 1] = __fadd_rn(hi, b);
        }
    }
    __syncthreads();

    for (int q = tid; q < E_ * MTT; q += NT){
        const int e = q / MTT, r = q % MTT;
        iT[e * STT + r] = sos[e];
    }

#pragma unroll 1
    for (int t = 0; t < L_; ++t){
        __syncthreads();
#pragma unroll 1
        for (int c = 0; c < H_; c += 256){
            const int col = c + tid;
            // Phase 1: gi chains (3 gates x 8 pairs)
            {
                ull gi[3][8] = {};
                chain3H<E_, 2 * 3 * H_>(gi, g_WihT, col, iT);
                // spill gi_n into this thread's own hnxt slots (stale buffer; read back in epilogue)
#pragma unroll
                for (int q4 = 0; q4 < 4; ++q4){
                    ulonglong2 v; v.x = gi[2][2 * q4]; v.y = gi[2][2 * q4 + 1];
                    *(ulonglong2*)(hnxt + col * STT + 4 * q4) = v;
                }
                // keep r,z in registers via persistent locals below
                ull giR[8], giZ[8];
#pragma unroll
                for (int p = 0; p < 8; ++p){ giR[p] = gi[0][p]; giZ[p] = gi[1][p]; }

                // Phase 2: gh chains
                ull gh[3][8] = {};
                chain3H<H_, 2 * 3 * H_>(gh, g_WhhT, col, hcur);

                const float bir = bih[col], biz = bih[col + H_], bin = bih[col + 2 * H_];
                const float bhr = bhh[col], bhz = bhh[col + H_], bhn = bhh[col + 2 * H_];
                // Phase 3: epilogue — read spilled gi_n pair, then overwrite same slots with h
#pragma unroll
                for (int p = 0; p < 8; ++p){
                    ull ginp = *(const ull*)(hnxt + col * STT + 2 * p);
                    float giN0, giN1; unpack2(ginp, giN0, giN1);
                    float giR0, giR1, giZ0, giZ1;
                    unpack2(giR[p], giR0, giR1); unpack2(giZ[p], giZ0, giZ1);
                    float ghR0, ghR1, ghZ0, ghZ1, ghN0, ghN1;
                    unpack2(gh[0][p], ghR0, ghR1); unpack2(gh[1][p], ghZ0, ghZ1); unpack2(gh[2][p], ghN0, ghN1);
                    gru_epilogue_pair(hnxt, hcur, col, STT, 2 * p + 0,
                                      giR0, giZ0, giN0, ghR0, ghZ0, ghN0, bir, biz, bin, bhr, bhz, bhn);
                    gru_epilogue_pair(hnxt, hcur, col, STT, 2 * p + 1,
                                      giR1, giZ1, giN1, ghR1, ghZ1, ghN1, bir, biz, bin, bhr, bhz, bhn);
                }
            }
        }
        __syncthreads();

        logits_argmax_gather<MTT, STT>(b0, t, hnxt, slog, stok, emb, bout, tokf, toki, lg, iT);

        float* tmp = hcur; hcur = hnxt; hnxt = tmp;
    }
}

// ================== MT12, 1 group x 12 rows (R14-proven, unchanged) ==================
template<int KK, int RL>
__device__ __forceinline__ void chain3G(ull (&acc)[3][6],
    const float* __restrict__ wT, int col,
    const float* __restrict__ actT /* STT = 16 */)
{
    const float* w0p = wT + 2 * col;
    const float* w1p = wT + 2 * (col + H_);
    const float* w2p = wT + 2 * (col + 2 * H_);
    constexpr int NP = KK / 2;
    float2 w[4][3];
#pragma unroll
    for (int j = 0; j < 4; ++j){
        w[j][0] = *(const float2*)(w0p + (size_t)j * RL);
        w[j][1] = *(const float2*)(w1p + (size_t)j * RL);
        w[j][2] = *(const float2*)(w2p + (size_t)j * RL);
    }
#pragma unroll 1
    for (int p0 = 0; p0 < NP; p0 += 4){
#pragma unroll
        for (int j = 0; j < 4; ++j){
            const int p = p0 + j;
#pragma unroll
            for (int s = 0; s < 2; ++s){
                const int k = 2 * p + s;
                ull a[6];
                load_act<6>(a, actT + (size_t)k * 16);
                ull d0 = dup2(s ? w[j][0].y : w[j][0].x);
                ull d1 = dup2(s ? w[j][1].y : w[j][1].x);
                ull d2 = dup2(s ? w[j][2].y : w[j][2].x);
#pragma unroll
                for (int pp = 0; pp < 6; ++pp) ffma2(acc[0][pp], a[pp], d0);
#pragma unroll
                for (int pp = 0; pp < 6; ++pp) ffma2(acc[1][pp], a[pp], d1);
#pragma unroll
                for (int pp = 0; pp < 6; ++pp) ffma2(acc[2][pp], a[pp], d2);
            }
            const int pn = p + 4;
            w[j][0] = *(const float2*)(w0p + (size_t)pn * RL);
            w[j][1] = *(const float2*)(w1p + (size_t)pn * RL);
            w[j][2] = *(const float2*)(w2p + (size_t)pn * RL);
        }
    }
}

template<int KK, int RL>
__device__ __forceinline__ void chain1G(ull (&acc)[6],
    const float* __restrict__ wT, int col,
    const float* __restrict__ actT)
{
    const float* wp = wT + 2 * col;
    constexpr int NP = KK / 2;
    float2 w[4];
#pragma unroll
    for (int j = 0; j < 4; ++j)
        w[j] = *(const float2*)(wp + (size_t)j * RL);
#pragma unroll 1
    for (int p0 = 0; p0 < NP; p0 += 4){
#pragma unroll
        for (int j = 0; j < 4; ++j){
            const int p = p0 + j;
#pragma unroll
            for (int s = 0; s < 2; ++s){
                const int k = 2 * p + s;
                ull a[6];
                load_act<6>(a, actT + (size_t)k * 16);
                ull d0 = dup2(s ? w[j].y : w[j].x);
#pragma unroll
                for (int pp = 0; pp < 6; ++pp) ffma2(acc[pp], a[pp], d0);
            }
            w[j] = *(const float2*)(wp + (size_t)(p + 4) * RL);
        }
    }
}

__device__ __forceinline__ void run_tile12(
    int b0,
    const float* __restrict__ x,    const float* __restrict__ emb,
    const float* __restrict__ sos,
    const float* __restrict__ bi2h,
    const float* __restrict__ bih,  const float* __restrict__ bhh,
    const float* __restrict__ bout,
    float* __restrict__ tokf, int* __restrict__ toki, float* __restrict__ lg)
{
    constexpr int MTT = 12, STT = 16;
    constexpr int OVL = (IROWS * STT > MTT * V_) ? IROWS * STT : MTT * V_;

    extern __shared__ float sm[];
    float* hT0  = sm;
    float* hT1  = hT0 + HROWS * STT;
    float* iT   = hT1 + HROWS * STT;
    float* slog = iT;
    int*   stok = (int*)(iT + OVL);

    const int tid = threadIdx.x;

    for (int q = tid; q < MTT * (DIN / 4); q += NT){
        const int ch  = q & 63;
        const int row = q >> 6;
        float4 v = *(const float4*)(x + (size_t)(b0 + row) * DIN + ch * 4);
        iT[(4 * ch + 0) * STT + row] = v.x;
        iT[(4 * ch + 1) * STT + row] = v.y;
        iT[(4 * ch + 2) * STT + row] = v.z;
        iT[(4 * ch + 3) * STT + row] = v.w;
    }
    __syncthreads();

    float* hcur = hT0;
    float* hnxt = hT1;

#pragma unroll 1
    for (int c = 0; c < H_; c += 256){
        const int col = c + tid;
        ull acc[6] = {};
        chain1G<DIN, 2 * H_>(acc, g_Wi2hT, col, iT);
        const float b = bi2h[col];
#pragma unroll
        for (int p = 0; p < 6; ++p){
            float lo, hi; unpack2(acc[p], lo, hi);
            hcur[col * STT + 2 * p + 0] = __fadd_rn(lo, b);
            hcur[col * STT + 2 * p + 1] = __fadd_rn(hi, b);
        }
    }
    __syncthreads();

    for (int q = tid; q < E_ * MTT; q += NT){
        const int e = q / MTT, r = q % MTT;
        iT[e * STT + r] = sos[e];
    }

#pragma unroll 1
    for (int t = 0; t < L_; ++t){
        __syncthreads();
#pragma unroll 1
        for (int c = 0; c < H_; c += 256){
            const int col = c + tid;
            ull gi[3][6] = {};
            ull gh[3][6] = {};
            chain3G<E_, 2 * 3 * H_>(gi, g_WihT, col, iT);
            chain3G<H_, 2 * 3 * H_>(gh, g_WhhT, col, hcur);
            const float bir = bih[col], biz = bih[col + H_], bin = bih[col + 2 * H_];
            const float bhr = bhh[col], bhz = bhh[col + H_], bhn = bhh[col + 2 * H_];
#pragma unroll
            for (int p = 0; p < 6; ++p){
                float giR0, giR1, giZ0, giZ1, giN0, giN1;
                float ghR0, ghR1, ghZ0, ghZ1, ghN0, ghN1;
                unpack2(gi[0][p], giR0, giR1); unpack2(gi[1][p], giZ0, giZ1); unpack2(gi[2][p], giN0, giN1);
                unpack2(gh[0][p], ghR0, ghR1); unpack2(gh[1][p], ghZ0, ghZ1); unpack2(gh[2][p], ghN0, ghN1);
                gru_epilogue_pair(hnxt, hcur, col, STT, 2 * p + 0,
                                  giR0, giZ0, giN0, ghR0, ghZ0, ghN0, bir, biz, bin, bhr, bhz, bhn);
                gru_epilogue_pair(hnxt, hcur, col, STT, 2 * p + 1,
                                  giR1, giZ1, giN1, ghR1, ghZ1, ghN1, bir, biz, bin, bhr, bhz, bhn);
            }
        }
        __syncthreads();

        logits_argmax_gather<MTT, STT>(b0, t, hnxt, slog, stok, emb, bout, tokf, toki, lg, iT);

        float* tmp = hcur; hcur = hnxt; hnxt = tmp;
    }
}

// ================== dispatch: pair one MT16 with one MT12 per SM via bid%148 ==================
__global__ void __launch_bounds__(NT, 2)
rnn_decoder_kernel(
    const float* __restrict__ x,    const float* __restrict__ emb,
    const float* __restrict__ sos,
    const float* __restrict__ bi2h,
    const float* __restrict__ bih,  const float* __restrict__ bhh,
    const float* __restrict__ bout,
    float* __restrict__ tokf, int* __restrict__ toki, float* __restrict__ lg)
{
    const int bid = blockIdx.x;
    int n16, n12; bool is16;
    if (bid < 148)      { n16 = bid;              n12 = 0;                 is16 = true;  }
    else if (bid < 296) { n16 = 148;              n12 = bid - 148;         is16 = false; }
    else if (bid < 420) { n16 = 148 + bid - 296;  n12 = 148;               is16 = true;  }
    else                { n16 = 272;              n12 = 148 + (bid - 420); is16 = false; }
    const int b0 = n16 * 16 + n12 * 12;
    if (is16) run_tile16(b0, x, emb, sos, bi2h, bih, bhh, bout, tokf, toki, lg);
    else      run_tile12(b0, x, emb, sos, bi2h, bih, bhh, bout, tokf, toki, lg);
}

extern "C" void kernel_launch(void* const* d_in, const int* in_sizes, int n_in,
                              void* d_out, int out_size) {
    const float* x    = (const float*)d_in[0];
    const float* emb  = (const float*)d_in[1];
    const float* sos  = (const float*)d_in[2];
    const float* Wi2h = (const float*)d_in[3];
    const float* bi2h = (const float*)d_in[4];
    const float* Wih  = (const float*)d_in[5];
    const float* Whh  = (const float*)d_in[6];
    const float* bih  = (const float*)d_in[7];
    const float* bhh  = (const float*)d_in[8];
    const float* Wout = (const float*)d_in[9];
    const float* bout = (const float*)d_in[10];

    float *dWihT, *dWhhT, *dWoutT, *dWi2hT;
    cudaGetSymbolAddress((void**)&dWihT,  g_WihT);
    cudaGetSymbolAddress((void**)&dWhhT,  g_WhhT);
    cudaGetSymbolAddress((void**)&dWoutT, g_WoutT);
    cudaGetSymbolAddress((void**)&dWi2hT, g_Wi2hT);

    stage_weights_kernel<<<1024, 256>>>(Wih, Whh, Wout, Wi2h,
                                        dWihT, dWhhT, dWoutT, dWi2hT);

    const long long TOKN = (long long)B_ * L_;        // 262144
    const long long LGN  = TOKN * V_;                 // 67108864
    const long long os   = (long long)out_size;

    float* tokf = nullptr;
    int*   toki = nullptr;
    float* lg   = nullptr;

    if (os == TOKN + LGN){           // (tokens, logits) concatenated as float32
        tokf = (float*)d_out;
        lg   = (float*)d_out + TOKN;
    } else if (os == LGN){           // logits only
        lg   = (float*)d_out;
    } else if (os == TOKN){          // tokens only (int32)
        toki = (int*)d_out;
    } else {                         // best guess
        tokf = (float*)d_out;
        lg   = (float*)d_out + TOKN;
    }

    // smem sized for the larger (MT=16) tile
    constexpr int ST16  = 20;
    constexpr int OVL16 = (IROWS * ST16 > 16 * V_) ? IROWS * ST16 : 16 * V_;
    const size_t smem = (size_t)(2 * HROWS * ST16 + OVL16) * sizeof(float) + 16 * sizeof(int);
    cudaFuncSetAttribute(rnn_decoder_kernel,
                         cudaFuncAttributeMaxDynamicSharedMemorySize, (int)smem);
    rnn_decoder_kernel<<<GRID, NT, smem>>>(
        x, emb, sos, bi2h, bih, bhh, bout,
        tokf, toki, lg);
}

// round 16
// speedup vs baseline: 5.9402x; 1.0138x over previous
#include <cuda_runtime.h>
#include <math.h>

// ---------------- problem dims ----------------
constexpr int B_  = 8192;
constexpr int L_  = 32;
constexpr int V_  = 256;
constexpr int DIN = 256;
constexpr int H_  = 512;
constexpr int E_  = 256;

constexpr int NT  = 256;   // threads per CTA
constexpr int GRID = 592;  // 2 clean waves on 296 dual-slots; 272*16 + 320*12 = 8192

typedef unsigned long long ull;

// ---------------- paired-k weight scratch (NOT duplicated), padded +4 pair-rows ----------------
__device__ float g_WihT [(E_  / 2 + 4) * 2 * (3 * H_)];
__device__ float g_WhhT [(H_  / 2 + 4) * 2 * (3 * H_)];
__device__ float g_WoutT[(H_  / 2 + 4) * 2 * V_];
__device__ float g_Wi2hT[(DIN / 2 + 4) * 2 * H_];

__global__ void stage_weights_kernel(
    const float* __restrict__ Wih,  const float* __restrict__ Whh,
    const float* __restrict__ Wout, const float* __restrict__ Wi2h,
    float* __restrict__ o_ih, float* __restrict__ o_hh,
    float* __restrict__ o_out, float* __restrict__ o_i2h)
{
    const long N0 = 1536L * 256, N1 = 1536L * 512, N2 = 256L * 512, N3 = 512L * 256;
    const long NTOT = N0 + N1 + N2 + N3;
    for (long e = (long)blockIdx.x * blockDim.x + threadIdx.x; e < NTOT;
         e += (long)gridDim.x * blockDim.x){
        const float* W; float* o; int J, K; long r = e;
        if (r < N0)            { W = Wih;  o = o_ih;  J = 1536; K = 256; }
        else if ((r -= N0) < N1){ W = Whh;  o = o_hh;  J = 1536; K = 512; }
        else if ((r -= N1) < N2){ W = Wout; o = o_out; J = 256;  K = 512; }
        else { r -= N2;          W = Wi2h; o = o_i2h; J = 512;  K = 256; }
        int j = (int)(r / K), k = (int)(r % K);
        o[(size_t)(k >> 1) * (2 * J) + 2 * j + (k & 1)] = W[r];
    }
}

// ---------------- packed f32x2 FMA ----------------
__device__ __forceinline__ void ffma2(ull &d, ull a, ull b){
    asm("fma.rn.f32x2 %0, %1, %2, %0;" : "+l"(d) : "l"(a), "l"(b));
}
__device__ __forceinline__ ull dup2(float w){
    ull r; asm("mov.b64 %0, {%1, %1};" : "=l"(r) : "f"(w)); return r;
}
__device__ __forceinline__ void unpack2(ull v, float &lo, float &hi){
    asm("mov.b64 {%0, %1}, %2;" : "=f"(lo), "=f"(hi) : "l"(v));
}

// ---------------- XLA:CPU exp/sigmoid/tanh (bit-exact emulation) ----------------
__device__ __forceinline__ float xla_exp(float x){
    float c  = fminf(fmaxf(x, -88.3762626647949f), 88.3762626647950f);
    float fx = floorf(__fmaf_rn(c, 1.44269504088896341f, 0.5f));
    float t1 = __fmul_rn(0.693359375f, fx);
    float t2 = __fmul_rn(-2.12194440e-4f, fx);
    float r  = __fadd_rn(c, -t1);
    r        = __fadd_rn(r, -t2);
    float r2 = __fmul_rn(r, r);
    float y  = 1.9875691500e-4f;
    y = __fmaf_rn(y, r, 1.3981999507e-3f);
    y = __fmaf_rn(y, r, 8.3334519073e-3f);
    y = __fmaf_rn(y, r, 4.1665795894e-2f);
    y = __fmaf_rn(y, r, 1.6666665459e-1f);
    y = __fmaf_rn(y, r, 5.0000001201e-1f);
    y = __fmaf_rn(y, r2, r);
    y = __fadd_rn(y, 1.0f);
    int n = (int)fx;
    float p2n = __int_as_float((n + 127) << 23);
    return __fmul_rn(y, p2n);
}
__device__ __forceinline__ float xla_sigmoid(float x){
    float e = xla_exp(-x);
    return __fdiv_rn(1.0f, __fadd_rn(1.0f, e));
}
__device__ __forceinline__ float xla_tanh(float x){
    float ax = fabsf(x);
    float xc = fminf(fmaxf(x, -9.0f), 9.0f);
    float x2 = __fmul_rn(xc, xc);
    float np = -2.76076847742355e-16f;
    np = __fmaf_rn(np, x2, 2.00018790482477e-13f);
    np = __fmaf_rn(np, x2, -8.60467152213735e-11f);
    np = __fmaf_rn(np, x2, 5.12229709037114e-08f);
    np = __fmaf_rn(np, x2, 1.48572235717979e-05f);
    np = __fmaf_rn(np, x2, 6.37261928875436e-04f);
    np = __fmaf_rn(np, x2, 4.89352455891786e-03f);
    np = __fmul_rn(np, xc);
    float dp = 1.19825839466702e-06f;
    dp = __fmaf_rn(dp, x2, 1.18534705686654e-04f);
    dp = __fmaf_rn(dp, x2, 2.26843463243900e-03f);
    dp = __fmaf_rn(dp, x2, 4.89352518554385e-03f);
    float res = __fdiv_rn(np, dp);
    return (ax < 0.0004f) ? x : res;
}

// ---- activation loads: P row-pairs starting at base ----
template<int P>
__device__ __forceinline__ void load_act(ull (&a)[P], const float* base){
    if constexpr (P == 8){
        ulonglong2 v0 = *(const ulonglong2*)(base);
        ulonglong2 v1 = *(const ulonglong2*)(base + 4);
        ulonglong2 v2 = *(const ulonglong2*)(base + 8);
        ulonglong2 v3 = *(const ulonglong2*)(base + 12);
        a[0] = v0.x; a[1] = v0.y; a[2] = v1.x; a[3] = v1.y;
        a[4] = v2.x; a[5] = v2.y; a[6] = v3.x; a[7] = v3.y;
    } else if constexpr (P == 6){
        ulonglong2 v0 = *(const ulonglong2*)(base);
        ulonglong2 v1 = *(const ulonglong2*)(base + 4);
        ulonglong2 v2 = *(const ulonglong2*)(base + 8);
        a[0] = v0.x; a[1] = v0.y; a[2] = v1.x; a[3] = v1.y; a[4] = v2.x; a[5] = v2.y;
    } else if constexpr (P == 4){
        ulonglong2 v0 = *(const ulonglong2*)(base);
        ulonglong2 v1 = *(const ulonglong2*)(base + 4);
        a[0] = v0.x; a[1] = v0.y; a[2] = v1.x; a[3] = v1.y;
    } else {  // P == 3 : base only 8B-aligned
        a[0] = *(const ull*)(base);
        a[1] = *(const ull*)(base + 2);
        a[2] = *(const ull*)(base + 4);
    }
}

constexpr int HROWS = H_ + 1;   // +1 pad k-row for unconditional prefetch
constexpr int IROWS = E_ + 1;

// ---- shared epilogue helper ----
__device__ __forceinline__ void gru_epilogue_pair(
    float* hnxt, const float* hcur, int col, int STT, int row,
    float dIR, float dIZ, float dIN, float dHR, float dHZ, float dHN,
    float bir, float biz, float bin, float bhr, float bhz, float bhn)
{
    float ir = __fadd_rn(dIR, bir), hr = __fadd_rn(dHR, bhr);
    float iz = __fadd_rn(dIZ, biz), hz = __fadd_rn(dHZ, bhz);
    float in_ = __fadd_rn(dIN, bin), hn = __fadd_rn(dHN, bhn);
    float rg = xla_sigmoid(__fadd_rn(ir, hr));
    float zg = xla_sigmoid(__fadd_rn(iz, hz));
    float npre = __fadd_rn(in_, __fmul_rn(rg, hn));
    float n  = xla_tanh(npre);
    float ho = hcur[col * STT + row];
    float omz = __fadd_rn(1.0f, -zg);
    hnxt[col * STT + row] = __fadd_rn(__fmul_rn(omz, n), __fmul_rn(zg, ho));
}

// ---- logits + argmax + gather ----
// R16: 2 cols x (MTT/2) rows per thread — halves act LDS wavefronts in the
// L1-capped logits phase. Each (row,col) output keeps one strict ascending-k
// chain -> bit-exact.
template<int MTT, int STT>
__device__ __forceinline__ void logits_argmax_gather(
    int b0, int t, float* hnxt, float* slog, int* stok,
    const float* __restrict__ emb, const float* __restrict__ bout,
    float* __restrict__ tokf, int* __restrict__ toki, float* __restrict__ lg,
    float* iT)
{
    constexpr int NR  = MTT / 2;   // rows per thread (8 or 6)
    constexpr int NP2 = NR / 2;    // row pairs per thread (4 or 3)
    const int tid  = threadIdx.x;
    const int lane = tid & 31;
    const int wid  = tid >> 5;
    {
        const int rg = tid >> 7;           // row group: 0 or 1
        const int tx = tid & 127;
        const int colA = tx, colB = tx + 128;
        const int r0 = rg * NR;
        ull aA[NP2], aB[NP2];
#pragma unroll
        for (int p = 0; p < NP2; ++p){ aA[p] = 0ULL; aB[p] = 0ULL; }
        const float* wpA = g_WoutT + 2 * colA;
        const float* wpB = g_WoutT + 2 * colB;
        constexpr int NPL = H_ / 2;
        float2 wA[4], wB[4];
#pragma unroll
        for (int j = 0; j < 4; ++j){
            wA[j] = *(const float2*)(wpA + (size_t)j * 512);
            wB[j] = *(const float2*)(wpB + (size_t)j * 512);
        }
#pragma unroll 1
        for (int p0 = 0; p0 < NPL; p0 += 4){
#pragma unroll
            for (int j = 0; j < 4; ++j){
                const int p = p0 + j;
#pragma unroll
                for (int s = 0; s < 2; ++s){
                    const int k = 2 * p + s;
                    ull a[NP2];
                    load_act<NP2>(a, hnxt + (size_t)k * STT + r0);
                    ull dA = dup2(s ? wA[j].y : wA[j].x);
                    ull dB = dup2(s ? wB[j].y : wB[j].x);
#pragma unroll
                    for (int p2 = 0; p2 < NP2; ++p2) ffma2(aA[p2], a[p2], dA);
#pragma unroll
                    for (int p2 = 0; p2 < NP2; ++p2) ffma2(aB[p2], a[p2], dB);
                }
                wA[j] = *(const float2*)(wpA + (size_t)(p + 4) * 512);   // pad rows absorb
                wB[j] = *(const float2*)(wpB + (size_t)(p + 4) * 512);
            }
        }
        const float boA = bout[colA], boB = bout[colB];
#pragma unroll
        for (int p = 0; p < NP2; ++p){
            const int rA = r0 + 2 * p, rB = rA + 1;
            float a0, a1, b0v, b1v;
            unpack2(aA[p], a0, a1); unpack2(aB[p], b0v, b1v);
            float lvA0 = __fadd_rn(a0, boA), lvA1 = __fadd_rn(a1, boA);
            float lvB0 = __fadd_rn(b0v, boB), lvB1 = __fadd_rn(b1v, boB);
            slog[rA * V_ + colA] = lvA0;
            slog[rB * V_ + colA] = lvA1;
            slog[rA * V_ + colB] = lvB0;
            slog[rB * V_ + colB] = lvB1;
            if (lg){
                lg[(size_t)(b0 + rA) * (L_ * V_) + (size_t)t * V_ + colA] = lvA0;
                lg[(size_t)(b0 + rB) * (L_ * V_) + (size_t)t * V_ + colA] = lvA1;
                lg[(size_t)(b0 + rA) * (L_ * V_) + (size_t)t * V_ + colB] = lvB0;
                lg[(size_t)(b0 + rB) * (L_ * V_) + (size_t)t * V_ + colB] = lvB1;
            }
        }
    }
    __syncthreads();   // slog complete

#pragma unroll
    for (int rr2 = 0; rr2 < 2; ++rr2){
        const int row = wid * 2 + rr2;
        if (row < MTT){
            float bv = -1e30f; int bi = 0;
#pragma unroll
            for (int j = 0; j < 8; ++j){
                const int idx = lane + 32 * j;
                float v = slog[row * V_ + idx];
                if (v > bv){ bv = v; bi = idx; }
            }
#pragma unroll
            for (int off = 16; off > 0; off >>= 1){
                float ov = __shfl_down_sync(0xffffffffu, bv, off);
                int   oi = __shfl_down_sync(0xffffffffu, bi, off);
                if (ov > bv || (ov == bv && oi < bi)){ bv = ov; bi = oi; }
            }
            if (lane == 0){
                stok[row] = bi;
                if (tokf) tokf[(size_t)(b0 + row) * L_ + t] = (float)bi;
                if (toki) toki[(size_t)(b0 + row) * L_ + t] = bi;
            }
        }
    }
    __syncthreads();   // stok visible

    for (int q = threadIdx.x; q < MTT * (E_ / 4); q += NT){
        const int row = q >> 6;
        const int ch  = q & 63;
        float4 v = *(const float4*)(emb + (size_t)stok[row] * E_ + ch * 4);
        iT[(4 * ch + 0) * STT + row] = v.x;
        iT[(4 * ch + 1) * STT + row] = v.y;
        iT[(4 * ch + 2) * STT + row] = v.z;
        iT[(4 * ch + 3) * STT + row] = v.w;
    }
}

// ================== MT16 single-group chains: P=8, weight depth-2, no act prefetch ==================
template<int KK, int RL>
__device__ __forceinline__ void chain3H(ull (&acc)[3][8],
    const float* __restrict__ wT, int col,
    const float* __restrict__ actT /* STT = 20 */)
{
    const float* w0p = wT + 2 * col;
    const float* w1p = wT + 2 * (col + H_);
    const float* w2p = wT + 2 * (col + 2 * H_);
    constexpr int NP = KK / 2;
    float2 w[2][3];
#pragma unroll
    for (int j = 0; j < 2; ++j){
        w[j][0] = *(const float2*)(w0p + (size_t)j * RL);
        w[j][1] = *(const float2*)(w1p + (size_t)j * RL);
        w[j][2] = *(const float2*)(w2p + (size_t)j * RL);
    }
#pragma unroll 1
    for (int p0 = 0; p0 < NP; p0 += 2){
#pragma unroll
        for (int j = 0; j < 2; ++j){
            const int p = p0 + j;
#pragma unroll
            for (int s = 0; s < 2; ++s){
                const int k = 2 * p + s;
                ull a[8];
                load_act<8>(a, actT + (size_t)k * 20);
                ull d0 = dup2(s ? w[j][0].y : w[j][0].x);
                ull d1 = dup2(s ? w[j][1].y : w[j][1].x);
                ull d2 = dup2(s ? w[j][2].y : w[j][2].x);
#pragma unroll
                for (int pp = 0; pp < 8; ++pp) ffma2(acc[0][pp], a[pp], d0);
#pragma unroll
                for (int pp = 0; pp < 8; ++pp) ffma2(acc[1][pp], a[pp], d1);
#pragma unroll
                for (int pp = 0; pp < 8; ++pp) ffma2(acc[2][pp], a[pp], d2);
            }
            const int pn = p + 2;                        // pad rows absorb p>=NP
            w[j][0] = *(const float2*)(w0p + (size_t)pn * RL);
            w[j][1] = *(const float2*)(w1p + (size_t)pn * RL);
            w[j][2] = *(const float2*)(w2p + (size_t)pn * RL);
        }
    }
}

template<int KK, int RL>
__device__ __forceinline__ void chain1H(ull (&acc)[8],
    const float* __restrict__ wT, int col,
    const float* __restrict__ actT)
{
    const float* wp = wT + 2 * col;
    constexpr int NP = KK / 2;
    float2 w[2];
    w[0] = *(const float2*)(wp);
    w[1] = *(const float2*)(wp + RL);
#pragma unroll 1
    for (int p0 = 0; p0 < NP; p0 += 2){
#pragma unroll
        for (int j = 0; j < 2; ++j){
            const int p = p0 + j;
#pragma unroll
            for (int s = 0; s < 2; ++s){
                const int k = 2 * p + s;
                ull a[8];
                load_act<8>(a, actT + (size_t)k * 20);
                ull d0 = dup2(s ? w[j].y : w[j].x);
#pragma unroll
                for (int pp = 0; pp < 8; ++pp) ffma2(acc[pp], a[pp], d0);
            }
            w[j] = *(const float2*)(wp + (size_t)(p + 2) * RL);
        }
    }
}

// ================== MT16, SINGLE group x 16 rows (weights stream once) ==================
__device__ __forceinline__ void run_tile16(
    int b0,
    const float* __restrict__ x,    const float* __restrict__ emb,
    const float* __restrict__ sos,
    const float* __restrict__ bi2h,
    const float* __restrict__ bih,  const float* __restrict__ bhh,
    const float* __restrict__ bout,
    float* __restrict__ tokf, int* __restrict__ toki, float* __restrict__ lg)
{
    constexpr int MTT = 16, STT = 20;
    constexpr int OVL = (IROWS * STT > MTT * V_) ? IROWS * STT : MTT * V_;

    extern __shared__ float sm[];
    float* hT0  = sm;
    float* hT1  = hT0 + HROWS * STT;
    float* iT   = hT1 + HROWS * STT;
    float* slog = iT;
    int*   stok = (int*)(iT + OVL);

    const int tid = threadIdx.x;

    for (int q = tid; q < MTT * (DIN / 4); q += NT){
        const int ch  = q & 63;
        const int row = q >> 6;
        float4 v = *(const float4*)(x + (size_t)(b0 + row) * DIN + ch * 4);
        iT[(4 * ch + 0) * STT + row] = v.x;
        iT[(4 * ch + 1) * STT + row] = v.y;
        iT[(4 * ch + 2) * STT + row] = v.z;
        iT[(4 * ch + 3) * STT + row] = v.w;
    }
    __syncthreads();

    float* hcur = hT0;
    float* hnxt = hT1;

    // ---- h0 = x @ Wi2h^T + bi2h : 2 chunks x 256 cols, 16 rows/thread ----
#pragma unroll 1
    for (int c = 0; c < H_; c += 256){
        const int col = c + tid;
        ull acc[8] = {};
        chain1H<DIN, 2 * H_>(acc, g_Wi2hT, col, iT);
        const float b = bi2h[col];
#pragma unroll
        for (int p = 0; p < 8; ++p){
            float lo, hi; unpack2(acc[p], lo, hi);
            hcur[col * STT + 2 * p + 0] = __fadd_rn(lo, b);
            hcur[col * STT + 2 * p + 1] = __fadd_rn(hi, b);
        }
    }
    __syncthreads();

    for (int q = tid; q < E_ * MTT; q += NT){
        const int e = q / MTT, r = q % MTT;
        iT[e * STT + r] = sos[e];
    }

#pragma unroll 1
    for (int t = 0; t < L_; ++t){
        __syncthreads();
#pragma unroll 1
        for (int c = 0; c < H_; c += 256){
            const int col = c + tid;
            // Phase 1: gi chains (3 gates x 8 pairs)
            {
                ull gi[3][8] = {};
                chain3H<E_, 2 * 3 * H_>(gi, g_WihT, col, iT);
                // spill gi_n into this thread's own hnxt slots (stale buffer; read back in epilogue)
#pragma unroll
                for (int q4 = 0; q4 < 4; ++q4){
                    ulonglong2 v; v.x = gi[2][2 * q4]; v.y = gi[2][2 * q4 + 1];
                    *(ulonglong2*)(hnxt + col * STT + 4 * q4) = v;
                }
                ull giR[8], giZ[8];
#pragma unroll
                for (int p = 0; p < 8; ++p){ giR[p] = gi[0][p]; giZ[p] = gi[1][p]; }

                // Phase 2: gh chains
                ull gh[3][8] = {};
                chain3H<H_, 2 * 3 * H_>(gh, g_WhhT, col, hcur);

                const float bir = bih[col], biz = bih[col + H_], bin = bih[col + 2 * H_];
                const float bhr = bhh[col], bhz = bhh[col + H_], bhn = bhh[col + 2 * H_];
                // Phase 3: epilogue — read spilled gi_n pair, then overwrite same slots with h
#pragma unroll
                for (int p = 0; p < 8; ++p){
                    ull ginp = *(const ull*)(hnxt + col * STT + 2 * p);
                    float giN0, giN1; unpack2(ginp, giN0, giN1);
                    float giR0, giR1, giZ0, giZ1;
                    unpack2(giR[p], giR0, giR1); unpack2(giZ[p], giZ0, giZ1);
                    float ghR0, ghR1, ghZ0, ghZ1, ghN0, ghN1;
                    unpack2(gh[0][p], ghR0, ghR1); unpack2(gh[1][p], ghZ0, ghZ1); unpack2(gh[2][p], ghN0, ghN1);
                    gru_epilogue_pair(hnxt, hcur, col, STT, 2 * p + 0,
                                      giR0, giZ0, giN0, ghR0, ghZ0, ghN0, bir, biz, bin, bhr, bhz, bhn);
                    gru_epilogue_pair(hnxt, hcur, col, STT, 2 * p + 1,
                                      giR1, giZ1, giN1, ghR1, ghZ1, ghN1, bir, biz, bin, bhr, bhz, bhn);
                }
            }
        }
        __syncthreads();

        logits_argmax_gather<MTT, STT>(b0, t, hnxt, slog, stok, emb, bout, tokf, toki, lg, iT);

        float* tmp = hcur; hcur = hnxt; hnxt = tmp;
    }
}

// ================== MT12, 1 group x 12 rows (R14-proven, unchanged) ==================
template<int KK, int RL>
__device__ __forceinline__ void chain3G(ull (&acc)[3][6],
    const float* __restrict__ wT, int col,
    const float* __restrict__ actT /* STT = 16 */)
{
    const float* w0p = wT + 2 * col;
    const float* w1p = wT + 2 * (col + H_);
    const float* w2p = wT + 2 * (col + 2 * H_);
    constexpr int NP = KK / 2;
    float2 w[4][3];
#pragma unroll
    for (int j = 0; j < 4; ++j){
        w[j][0] = *(const float2*)(w0p + (size_t)j * RL);
        w[j][1] = *(const float2*)(w1p + (size_t)j * RL);
        w[j][2] = *(const float2*)(w2p + (size_t)j * RL);
    }
#pragma unroll 1
    for (int p0 = 0; p0 < NP; p0 += 4){
#pragma unroll
        for (int j = 0; j < 4; ++j){
            const int p = p0 + j;
#pragma unroll
            for (int s = 0; s < 2; ++s){
                const int k = 2 * p + s;
                ull a[6];
                load_act<6>(a, actT + (size_t)k * 16);
                ull d0 = dup2(s ? w[j][0].y : w[j][0].x);
                ull d1 = dup2(s ? w[j][1].y : w[j][1].x);
                ull d2 = dup2(s ? w[j][2].y : w[j][2].x);
#pragma unroll
                for (int pp = 0; pp < 6; ++pp) ffma2(acc[0][pp], a[pp], d0);
#pragma unroll
                for (int pp = 0; pp < 6; ++pp) ffma2(acc[1][pp], a[pp], d1);
#pragma unroll
                for (int pp = 0; pp < 6; ++pp) ffma2(acc[2][pp], a[pp], d2);
            }
            const int pn = p + 4;
            w[j][0] = *(const float2*)(w0p + (size_t)pn * RL);
            w[j][1] = *(const float2*)(w1p + (size_t)pn * RL);
            w[j][2] = *(const float2*)(w2p + (size_t)pn * RL);
        }
    }
}

template<int KK, int RL>
__device__ __forceinline__ void chain1G(ull (&acc)[6],
    const float* __restrict__ wT, int col,
    const float* __restrict__ actT)
{
    const float* wp = wT + 2 * col;
    constexpr int NP = KK / 2;
    float2 w[4];
#pragma unroll
    for (int j = 0; j < 4; ++j)
        w[j] = *(const float2*)(wp + (size_t)j * RL);
#pragma unroll 1
    for (int p0 = 0; p0 < NP; p0 += 4){
#pragma unroll
        for (int j = 0; j < 4; ++j){
            const int p = p0 + j;
#pragma unroll
            for (int s = 0; s < 2; ++s){
                const int k = 2 * p + s;
                ull a[6];
                load_act<6>(a, actT + (size_t)k * 16);
                ull d0 = dup2(s ? w[j].y : w[j].x);
#pragma unroll
                for (int pp = 0; pp < 6; ++pp) ffma2(acc[pp], a[pp], d0);
            }
            w[j] = *(const float2*)(wp + (size_t)(p + 4) * RL);
        }
    }
}

__device__ __forceinline__ void run_tile12(
    int b0,
    const float* __restrict__ x,    const float* __restrict__ emb,
    const float* __restrict__ sos,
    const float* __restrict__ bi2h,
    const float* __restrict__ bih,  const float* __restrict__ bhh,
    const float* __restrict__ bout,
    float* __restrict__ tokf, int* __restrict__ toki, float* __restrict__ lg)
{
    constexpr int MTT = 12, STT = 16;
    constexpr int OVL = (IROWS * STT > MTT * V_) ? IROWS * STT : MTT * V_;

    extern __shared__ float sm[];
    float* hT0  = sm;
    float* hT1  = hT0 + HROWS * STT;
    float* iT   = hT1 + HROWS * STT;
    float* slog = iT;
    int*   stok = (int*)(iT + OVL);

    const int tid = threadIdx.x;

    for (int q = tid; q < MTT * (DIN / 4); q += NT){
        const int ch  = q & 63;
        const int row = q >> 6;
        float4 v = *(const float4*)(x + (size_t)(b0 + row) * DIN + ch * 4);
        iT[(4 * ch + 0) * STT + row] = v.x;
        iT[(4 * ch + 1) * STT + row] = v.y;
        iT[(4 * ch + 2) * STT + row] = v.z;
        iT[(4 * ch + 3) * STT + row] = v.w;
    }
    __syncthreads();

    float* hcur = hT0;
    float* hnxt = hT1;

#pragma unroll 1
    for (int c = 0; c < H_; c += 256){
        const int col = c + tid;
        ull acc[6] = {};
        chain1G<DIN, 2 * H_>(acc, g_Wi2hT, col, iT);
        const float b = bi2h[col];
#pragma unroll
        for (int p = 0; p < 6; ++p){
            float lo, hi; unpack2(acc[p], lo, hi);
            hcur[col * STT + 2 * p + 0] = __fadd_rn(lo, b);
            hcur[col * STT + 2 * p + 1] = __fadd_rn(hi, b);
        }
    }
    __syncthreads();

    for (int q = tid; q < E_ * MTT; q += NT){
        const int e = q / MTT, r = q % MTT;
        iT[e * STT + r] = sos[e];
    }

#pragma unroll 1
    for (int t = 0; t < L_; ++t){
        __syncthreads();
#pragma unroll 1
        for (int c = 0; c < H_; c += 256){
            const int col = c + tid;
            ull gi[3][6] = {};
            ull gh[3][6] = {};
            chain3G<E_, 2 * 3 * H_>(gi, g_WihT, col, iT);
            chain3G<H_, 2 * 3 * H_>(gh, g_WhhT, col, hcur);
            const float bir = bih[col], biz = bih[col + H_], bin = bih[col + 2 * H_];
            const float bhr = bhh[col], bhz = bhh[col + H_], bhn = bhh[col + 2 * H_];
#pragma unroll
            for (int p = 0; p < 6; ++p){
                float giR0, giR1, giZ0, giZ1, giN0, giN1;
                float ghR0, ghR1, ghZ0, ghZ1, ghN0, ghN1;
                unpack2(gi[0][p], giR0, giR1); unpack2(gi[1][p], giZ0, giZ1); unpack2(gi[2][p], giN0, giN1);
                unpack2(gh[0][p], ghR0, ghR1); unpack2(gh[1][p], ghZ0, ghZ1); unpack2(gh[2][p], ghN0, ghN1);
                gru_epilogue_pair(hnxt, hcur, col, STT, 2 * p + 0,
                                  giR0, giZ0, giN0, ghR0, ghZ0, ghN0, bir, biz, bin, bhr, bhz, bhn);
                gru_epilogue_pair(hnxt, hcur, col, STT, 2 * p + 1,
                                  giR1, giZ1, giN1, ghR1, ghZ1, ghN1, bir, biz, bin, bhr, bhz, bhn);
            }
        }
        __syncthreads();

        logits_argmax_gather<MTT, STT>(b0, t, hnxt, slog, stok, emb, bout, tokf, toki, lg, iT);

        float* tmp = hcur; hcur = hnxt; hnxt = tmp;
    }
}

// ================== dispatch: pair one MT16 with one MT12 per SM via bid%148 ==================
__global__ void __launch_bounds__(NT, 2)
rnn_decoder_kernel(
    const float* __restrict__ x,    const float* __restrict__ emb,
    const float* __restrict__ sos,
    const float* __restrict__ bi2h,
    const float* __restrict__ bih,  const float* __restrict__ bhh,
    const float* __restrict__ bout,
    float* __restrict__ tokf, int* __restrict__ toki, float* __restrict__ lg)
{
    const int bid = blockIdx.x;
    int n16, n12; bool is16;
    if (bid < 148)      { n16 = bid;              n12 = 0;                 is16 = true;  }
    else if (bid < 296) { n16 = 148;              n12 = bid - 148;         is16 = false; }
    else if (bid < 420) { n16 = 148 + bid - 296;  n12 = 148;               is16 = true;  }
    else                { n16 = 272;              n12 = 148 + (bid - 420); is16 = false; }
    const int b0 = n16 * 16 + n12 * 12;
    if (is16) run_tile16(b0, x, emb, sos, bi2h, bih, bhh, bout, tokf, toki, lg);
    else      run_tile12(b0, x, emb, sos, bi2h, bih, bhh, bout, tokf, toki, lg);
}

extern "C" void kernel_launch(void* const* d_in, const int* in_sizes, int n_in,
                              void* d_out, int out_size) {
    const float* x    = (const float*)d_in[0];
    const float* emb  = (const float*)d_in[1];
    const float* sos  = (const float*)d_in[2];
    const float* Wi2h = (const float*)d_in[3];
    const float* bi2h = (const float*)d_in[4];
    const float* Wih  = (const float*)d_in[5];
    const float* Whh  = (const float*)d_in[6];
    const float* bih  = (const float*)d_in[7];
    const float* bhh  = (const float*)d_in[8];
    const float* Wout = (const float*)d_in[9];
    const float* bout = (const float*)d_in[10];

    float *dWihT, *dWhhT, *dWoutT, *dWi2hT;
    cudaGetSymbolAddress((void**)&dWihT,  g_WihT);
    cudaGetSymbolAddress((void**)&dWhhT,  g_WhhT);
    cudaGetSymbolAddress((void**)&dWoutT, g_WoutT);
    cudaGetSymbolAddress((void**)&dWi2hT, g_Wi2hT);

    stage_weights_kernel<<<1024, 256>>>(Wih, Whh, Wout, Wi2h,
                                        dWihT, dWhhT, dWoutT, dWi2hT);

    const long long TOKN = (long long)B_ * L_;        // 262144
    const long long LGN  = TOKN * V_;                 // 67108864
    const long long os   = (long long)out_size;

    float* tokf = nullptr;
    int*   toki = nullptr;
    float* lg   = nullptr;

    if (os == TOKN + LGN){           // (tokens, logits) concatenated as float32
        tokf = (float*)d_out;
        lg   = (float*)d_out + TOKN;
    } else if (os == LGN){           // logits only
        lg   = (float*)d_out;
    } else if (os == TOKN){          // tokens only (int32)
        toki = (int*)d_out;
    } else {                         // best guess
        tokf = (float*)d_out;
        lg   = (float*)d_out + TOKN;
    }

    // smem sized for the larger (MT=16) tile
    constexpr int ST16  = 20;
    constexpr int OVL16 = (IROWS * ST16 > 16 * V_) ? IROWS * ST16 : 16 * V_;
    const size_t smem = (size_t)(2 * HROWS * ST16 + OVL16) * sizeof(float) + 16 * sizeof(int);
    cudaFuncSetAttribute(rnn_decoder_kernel,
                         cudaFuncAttributeMaxDynamicSharedMemorySize, (int)smem);
    rnn_decoder_kernel<<<GRID, NT, smem>>>(
        x, emb, sos, bi2h, bih, bhh, bout,
        tokf, toki, lg);
}

// round 17
// speedup vs baseline: 6.0844x; 1.0243x over previous
#include <cuda_runtime.h>
#include <math.h>

// ---------------- problem dims ----------------
constexpr int B_  = 8192;
constexpr int L_  = 32;
constexpr int V_  = 256;
constexpr int DIN = 256;
constexpr int H_  = 512;
constexpr int E_  = 256;

constexpr int NT  = 256;   // threads per CTA
constexpr int GRID = 592;  // 2 clean waves on 296 dual-slots; 272*16 + 320*12 = 8192

typedef unsigned long long ull;

// ---------------- paired-k weight scratch (NOT duplicated), padded +4 pair-rows ----------------
__device__ float g_WihT [(E_  / 2 + 4) * 2 * (3 * H_)];
__device__ float g_WhhT [(H_  / 2 + 4) * 2 * (3 * H_)];
__device__ float g_WoutT[(H_  / 2 + 4) * 2 * V_];
__device__ float g_Wi2hT[(DIN / 2 + 4) * 2 * H_];

__global__ void stage_weights_kernel(
    const float* __restrict__ Wih,  const float* __restrict__ Whh,
    const float* __restrict__ Wout, const float* __restrict__ Wi2h,
    float* __restrict__ o_ih, float* __restrict__ o_hh,
    float* __restrict__ o_out, float* __restrict__ o_i2h)
{
    const long N0 = 1536L * 256, N1 = 1536L * 512, N2 = 256L * 512, N3 = 512L * 256;
    const long NTOT = N0 + N1 + N2 + N3;
    for (long e = (long)blockIdx.x * blockDim.x + threadIdx.x; e < NTOT;
         e += (long)gridDim.x * blockDim.x){
        const float* W; float* o; int J, K; long r = e;
        if (r < N0)            { W = Wih;  o = o_ih;  J = 1536; K = 256; }
        else if ((r -= N0) < N1){ W = Whh;  o = o_hh;  J = 1536; K = 512; }
        else if ((r -= N1) < N2){ W = Wout; o = o_out; J = 256;  K = 512; }
        else { r -= N2;          W = Wi2h; o = o_i2h; J = 512;  K = 256; }
        int j = (int)(r / K), k = (int)(r % K);
        o[(size_t)(k >> 1) * (2 * J) + 2 * j + (k & 1)] = W[r];
    }
}

// ---------------- packed f32x2 FMA ----------------
__device__ __forceinline__ void ffma2(ull &d, ull a, ull b){
    asm("fma.rn.f32x2 %0, %1, %2, %0;" : "+l"(d) : "l"(a), "l"(b));
}
__device__ __forceinline__ ull dup2(float w){
    ull r; asm("mov.b64 %0, {%1, %1};" : "=l"(r) : "f"(w)); return r;
}
__device__ __forceinline__ void unpack2(ull v, float &lo, float &hi){
    asm("mov.b64 {%0, %1}, %2;" : "=f"(lo), "=f"(hi) : "l"(v));
}

// ---------------- XLA:CPU exp/sigmoid/tanh (bit-exact emulation) ----------------
__device__ __forceinline__ float xla_exp(float x){
    float c  = fminf(fmaxf(x, -88.3762626647949f), 88.3762626647950f);
    float fx = floorf(__fmaf_rn(c, 1.44269504088896341f, 0.5f));
    float t1 = __fmul_rn(0.693359375f, fx);
    float t2 = __fmul_rn(-2.12194440e-4f, fx);
    float r  = __fadd_rn(c, -t1);
    r        = __fadd_rn(r, -t2);
    float r2 = __fmul_rn(r, r);
    float y  = 1.9875691500e-4f;
    y = __fmaf_rn(y, r, 1.3981999507e-3f);
    y = __fmaf_rn(y, r, 8.3334519073e-3f);
    y = __fmaf_rn(y, r, 4.1665795894e-2f);
    y = __fmaf_rn(y, r, 1.6666665459e-1f);
    y = __fmaf_rn(y, r, 5.0000001201e-1f);
    y = __fmaf_rn(y, r2, r);
    y = __fadd_rn(y, 1.0f);
    int n = (int)fx;
    float p2n = __int_as_float((n + 127) << 23);
    return __fmul_rn(y, p2n);
}
__device__ __forceinline__ float xla_sigmoid(float x){
    float e = xla_exp(-x);
    return __fdiv_rn(1.0f, __fadd_rn(1.0f, e));
}
__device__ __forceinline__ float xla_tanh(float x){
    float ax = fabsf(x);
    float xc = fminf(fmaxf(x, -9.0f), 9.0f);
    float x2 = __fmul_rn(xc, xc);
    float np = -2.76076847742355e-16f;
    np = __fmaf_rn(np, x2, 2.00018790482477e-13f);
    np = __fmaf_rn(np, x2, -8.60467152213735e-11f);
    np = __fmaf_rn(np, x2, 5.12229709037114e-08f);
    np = __fmaf_rn(np, x2, 1.48572235717979e-05f);
    np = __fmaf_rn(np, x2, 6.37261928875436e-04f);
    np = __fmaf_rn(np, x2, 4.89352455891786e-03f);
    np = __fmul_rn(np, xc);
    float dp = 1.19825839466702e-06f;
    dp = __fmaf_rn(dp, x2, 1.18534705686654e-04f);
    dp = __fmaf_rn(dp, x2, 2.26843463243900e-03f);
    dp = __fmaf_rn(dp, x2, 4.89352518554385e-03f);
    float res = __fdiv_rn(np, dp);
    return (ax < 0.0004f) ? x : res;
}

// ---- activation loads: P row-pairs starting at base ----
template<int P>
__device__ __forceinline__ void load_act(ull (&a)[P], const float* base){
    if constexpr (P == 8){
        ulonglong2 v0 = *(const ulonglong2*)(base);
        ulonglong2 v1 = *(const ulonglong2*)(base + 4);
        ulonglong2 v2 = *(const ulonglong2*)(base + 8);
        ulonglong2 v3 = *(const ulonglong2*)(base + 12);
        a[0] = v0.x; a[1] = v0.y; a[2] = v1.x; a[3] = v1.y;
        a[4] = v2.x; a[5] = v2.y; a[6] = v3.x; a[7] = v3.y;
    } else if constexpr (P == 6){
        ulonglong2 v0 = *(const ulonglong2*)(base);
        ulonglong2 v1 = *(const ulonglong2*)(base + 4);
        ulonglong2 v2 = *(const ulonglong2*)(base + 8);
        a[0] = v0.x; a[1] = v0.y; a[2] = v1.x; a[3] = v1.y; a[4] = v2.x; a[5] = v2.y;
    } else if constexpr (P == 4){
        ulonglong2 v0 = *(const ulonglong2*)(base);
        ulonglong2 v1 = *(const ulonglong2*)(base + 4);
        a[0] = v0.x; a[1] = v0.y; a[2] = v1.x; a[3] = v1.y;
    } else {  // P == 3 : base only 8B-aligned
        a[0] = *(const ull*)(base);
        a[1] = *(const ull*)(base + 2);
        a[2] = *(const ull*)(base + 4);
    }
}

constexpr int HROWS = H_ + 1;   // +1 pad k-row for unconditional prefetch
constexpr int IROWS = E_ + 1;

// ---- shared epilogue helper ----
__device__ __forceinline__ void gru_epilogue_pair(
    float* hnxt, const float* hcur, int col, int STT, int row,
    float dIR, float dIZ, float dIN, float dHR, float dHZ, float dHN,
    float bir, float biz, float bin, float bhr, float bhz, float bhn)
{
    float ir = __fadd_rn(dIR, bir), hr = __fadd_rn(dHR, bhr);
    float iz = __fadd_rn(dIZ, biz), hz = __fadd_rn(dHZ, bhz);
    float in_ = __fadd_rn(dIN, bin), hn = __fadd_rn(dHN, bhn);
    float rg = xla_sigmoid(__fadd_rn(ir, hr));
    float zg = xla_sigmoid(__fadd_rn(iz, hz));
    float npre = __fadd_rn(in_, __fmul_rn(rg, hn));
    float n  = xla_tanh(npre);
    float ho = hcur[col * STT + row];
    float omz = __fadd_rn(1.0f, -zg);
    hnxt[col * STT + row] = __fadd_rn(__fmul_rn(omz, n), __fmul_rn(zg, ho));
}

// ---- logits + argmax + gather (R16-proven: 2 cols x MTT/2 rows per thread) ----
template<int MTT, int STT>
__device__ __forceinline__ void logits_argmax_gather(
    int b0, int t, float* hnxt, float* slog, int* stok,
    const float* __restrict__ emb, const float* __restrict__ bout,
    float* __restrict__ tokf, int* __restrict__ toki, float* __restrict__ lg,
    float* iT)
{
    constexpr int NR  = MTT / 2;   // rows per thread (8 or 6)
    constexpr int NP2 = NR / 2;    // row pairs per thread (4 or 3)
    const int tid  = threadIdx.x;
    const int lane = tid & 31;
    const int wid  = tid >> 5;
    {
        const int rg = tid >> 7;           // row group: 0 or 1
        const int tx = tid & 127;
        const int colA = tx, colB = tx + 128;
        const int r0 = rg * NR;
        ull aA[NP2], aB[NP2];
#pragma unroll
        for (int p = 0; p < NP2; ++p){ aA[p] = 0ULL; aB[p] = 0ULL; }
        const float* wpA = g_WoutT + 2 * colA;
        const float* wpB = g_WoutT + 2 * colB;
        constexpr int NPL = H_ / 2;
        float2 wA[4], wB[4];
#pragma unroll
        for (int j = 0; j < 4; ++j){
            wA[j] = *(const float2*)(wpA + (size_t)j * 512);
            wB[j] = *(const float2*)(wpB + (size_t)j * 512);
        }
#pragma unroll 1
        for (int p0 = 0; p0 < NPL; p0 += 4){
#pragma unroll
            for (int j = 0; j < 4; ++j){
                const int p = p0 + j;
#pragma unroll
                for (int s = 0; s < 2; ++s){
                    const int k = 2 * p + s;
                    ull a[NP2];
                    load_act<NP2>(a, hnxt + (size_t)k * STT + r0);
                    ull dA = dup2(s ? wA[j].y : wA[j].x);
                    ull dB = dup2(s ? wB[j].y : wB[j].x);
#pragma unroll
                    for (int p2 = 0; p2 < NP2; ++p2) ffma2(aA[p2], a[p2], dA);
#pragma unroll
                    for (int p2 = 0; p2 < NP2; ++p2) ffma2(aB[p2], a[p2], dB);
                }
                wA[j] = *(const float2*)(wpA + (size_t)(p + 4) * 512);   // pad rows absorb
                wB[j] = *(const float2*)(wpB + (size_t)(p + 4) * 512);
            }
        }
        const float boA = bout[colA], boB = bout[colB];
#pragma unroll
        for (int p = 0; p < NP2; ++p){
            const int rA = r0 + 2 * p, rB = rA + 1;
            float a0, a1, b0v, b1v;
            unpack2(aA[p], a0, a1); unpack2(aB[p], b0v, b1v);
            float lvA0 = __fadd_rn(a0, boA), lvA1 = __fadd_rn(a1, boA);
            float lvB0 = __fadd_rn(b0v, boB), lvB1 = __fadd_rn(b1v, boB);
            slog[rA * V_ + colA] = lvA0;
            slog[rB * V_ + colA] = lvA1;
            slog[rA * V_ + colB] = lvB0;
            slog[rB * V_ + colB] = lvB1;
            if (lg){
                lg[(size_t)(b0 + rA) * (L_ * V_) + (size_t)t * V_ + colA] = lvA0;
                lg[(size_t)(b0 + rB) * (L_ * V_) + (size_t)t * V_ + colA] = lvA1;
                lg[(size_t)(b0 + rA) * (L_ * V_) + (size_t)t * V_ + colB] = lvB0;
                lg[(size_t)(b0 + rB) * (L_ * V_) + (size_t)t * V_ + colB] = lvB1;
            }
        }
    }
    __syncthreads();   // slog complete

#pragma unroll
    for (int rr2 = 0; rr2 < 2; ++rr2){
        const int row = wid * 2 + rr2;
        if (row < MTT){
            float bv = -1e30f; int bi = 0;
#pragma unroll
            for (int j = 0; j < 8; ++j){
                const int idx = lane + 32 * j;
                float v = slog[row * V_ + idx];
                if (v > bv){ bv = v; bi = idx; }
            }
#pragma unroll
            for (int off = 16; off > 0; off >>= 1){
                float ov = __shfl_down_sync(0xffffffffu, bv, off);
                int   oi = __shfl_down_sync(0xffffffffu, bi, off);
                if (ov > bv || (ov == bv && oi < bi)){ bv = ov; bi = oi; }
            }
            if (lane == 0){
                stok[row] = bi;
                if (tokf) tokf[(size_t)(b0 + row) * L_ + t] = (float)bi;
                if (toki) toki[(size_t)(b0 + row) * L_ + t] = bi;
            }
        }
    }
    __syncthreads();   // stok visible; slog dead

    for (int q = threadIdx.x; q < MTT * (E_ / 4); q += NT){
        const int row = q >> 6;
        const int ch  = q & 63;
        float4 v = *(const float4*)(emb + (size_t)stok[row] * E_ + ch * 4);
        iT[(4 * ch + 0) * STT + row] = v.x;
        iT[(4 * ch + 1) * STT + row] = v.y;
        iT[(4 * ch + 2) * STT + row] = v.z;
        iT[(4 * ch + 3) * STT + row] = v.w;
    }
}

// ================== MT16 single-group chains ==================
// R17: weight prefetch depth 2 -> 4 (covers far-die L2 latency with ~3-pair
// use distance); activation block split into two quads consumed immediately
// (live act regs 16 -> 8 pays the weight-buffer register bill). Per-accumulator
// k-order unchanged -> bit-exact.
template<int KK, int RL>
__device__ __forceinline__ void chain3H(ull (&acc)[3][8],
    const float* __restrict__ wT, int col,
    const float* __restrict__ actT /* STT = 20 */)
{
    const float* w0p = wT + 2 * col;
    const float* w1p = wT + 2 * (col + H_);
    const float* w2p = wT + 2 * (col + 2 * H_);
    constexpr int NP = KK / 2;
    float2 w[4][3];
#pragma unroll
    for (int j = 0; j < 4; ++j){
        w[j][0] = *(const float2*)(w0p + (size_t)j * RL);
        w[j][1] = *(const float2*)(w1p + (size_t)j * RL);
        w[j][2] = *(const float2*)(w2p + (size_t)j * RL);
    }
#pragma unroll 1
    for (int p0 = 0; p0 < NP; p0 += 4){
#pragma unroll
        for (int j = 0; j < 4; ++j){
            const int p = p0 + j;
#pragma unroll
            for (int s = 0; s < 2; ++s){
                const int k = 2 * p + s;
                ull d0 = dup2(s ? w[j][0].y : w[j][0].x);
                ull d1 = dup2(s ? w[j][1].y : w[j][1].x);
                ull d2 = dup2(s ? w[j][2].y : w[j][2].x);
                // quad A: rows 0..7 (pairs 0..3)
                {
                    ull a[4];
                    load_act<4>(a, actT + (size_t)k * 20);
#pragma unroll
                    for (int pp = 0; pp < 4; ++pp) ffma2(acc[0][pp], a[pp], d0);
#pragma unroll
                    for (int pp = 0; pp < 4; ++pp) ffma2(acc[1][pp], a[pp], d1);
#pragma unroll
                    for (int pp = 0; pp < 4; ++pp) ffma2(acc[2][pp], a[pp], d2);
                }
                // quad B: rows 8..15 (pairs 4..7)
                {
                    ull a[4];
                    load_act<4>(a, actT + (size_t)k * 20 + 8);
#pragma unroll
                    for (int pp = 0; pp < 4; ++pp) ffma2(acc[0][4 + pp], a[pp], d0);
#pragma unroll
                    for (int pp = 0; pp < 4; ++pp) ffma2(acc[1][4 + pp], a[pp], d1);
#pragma unroll
                    for (int pp = 0; pp < 4; ++pp) ffma2(acc[2][4 + pp], a[pp], d2);
                }
            }
            const int pn = p + 4;                        // pad rows absorb p>=NP
            w[j][0] = *(const float2*)(w0p + (size_t)pn * RL);
            w[j][1] = *(const float2*)(w1p + (size_t)pn * RL);
            w[j][2] = *(const float2*)(w2p + (size_t)pn * RL);
        }
    }
}

template<int KK, int RL>
__device__ __forceinline__ void chain1H(ull (&acc)[8],
    const float* __restrict__ wT, int col,
    const float* __restrict__ actT)
{
    const float* wp = wT + 2 * col;
    constexpr int NP = KK / 2;
    float2 w[4];
#pragma unroll
    for (int j = 0; j < 4; ++j)
        w[j] = *(const float2*)(wp + (size_t)j * RL);
#pragma unroll 1
    for (int p0 = 0; p0 < NP; p0 += 4){
#pragma unroll
        for (int j = 0; j < 4; ++j){
            const int p = p0 + j;
#pragma unroll
            for (int s = 0; s < 2; ++s){
                const int k = 2 * p + s;
                ull d0 = dup2(s ? w[j].y : w[j].x);
                {
                    ull a[4];
                    load_act<4>(a, actT + (size_t)k * 20);
#pragma unroll
                    for (int pp = 0; pp < 4; ++pp) ffma2(acc[pp], a[pp], d0);
                }
                {
                    ull a[4];
                    load_act<4>(a, actT + (size_t)k * 20 + 8);
#pragma unroll
                    for (int pp = 0; pp < 4; ++pp) ffma2(acc[4 + pp], a[pp], d0);
                }
            }
            w[j] = *(const float2*)(wp + (size_t)(p + 4) * RL);
        }
    }
}

// ================== MT16, SINGLE group x 16 rows (weights stream once) ==================
__device__ __forceinline__ void run_tile16(
    int b0,
    const float* __restrict__ x,    const float* __restrict__ emb,
    const float* __restrict__ sos,
    const float* __restrict__ bi2h,
    const float* __restrict__ bih,  const float* __restrict__ bhh,
    const float* __restrict__ bout,
    float* __restrict__ tokf, int* __restrict__ toki, float* __restrict__ lg)
{
    constexpr int MTT = 16, STT = 20;
    constexpr int OVL = (IROWS * STT > MTT * V_) ? IROWS * STT : MTT * V_;

    extern __shared__ float sm[];
    float* hT0  = sm;
    float* hT1  = hT0 + HROWS * STT;
    float* iT   = hT1 + HROWS * STT;
    float* slog = iT;
    int*   stok = (int*)(iT + OVL);

    const int tid = threadIdx.x;

    for (int q = tid; q < MTT * (DIN / 4); q += NT){
        const int ch  = q & 63;
        const int row = q >> 6;
        float4 v = *(const float4*)(x + (size_t)(b0 + row) * DIN + ch * 4);
        iT[(4 * ch + 0) * STT + row] = v.x;
        iT[(4 * ch + 1) * STT + row] = v.y;
        iT[(4 * ch + 2) * STT + row] = v.z;
        iT[(4 * ch + 3) * STT + row] = v.w;
    }
    __syncthreads();

    float* hcur = hT0;
    float* hnxt = hT1;

    // ---- h0 = x @ Wi2h^T + bi2h : 2 chunks x 256 cols, 16 rows/thread ----
#pragma unroll 1
    for (int c = 0; c < H_; c += 256){
        const int col = c + tid;
        ull acc[8] = {};
        chain1H<DIN, 2 * H_>(acc, g_Wi2hT, col, iT);
        const float b = bi2h[col];
#pragma unroll
        for (int p = 0; p < 8; ++p){
            float lo, hi; unpack2(acc[p], lo, hi);
            hcur[col * STT + 2 * p + 0] = __fadd_rn(lo, b);
            hcur[col * STT + 2 * p + 1] = __fadd_rn(hi, b);
        }
    }
    __syncthreads();

    for (int q = tid; q < E_ * MTT; q += NT){
        const int e = q / MTT, r = q % MTT;
        iT[e * STT + r] = sos[e];
    }

#pragma unroll 1
    for (int t = 0; t < L_; ++t){
        __syncthreads();
#pragma unroll 1
        for (int c = 0; c < H_; c += 256){
            const int col = c + tid;
            // Phase 1: gi chains (3 gates x 8 pairs)
            {
                ull gi[3][8] = {};
                chain3H<E_, 2 * 3 * H_>(gi, g_WihT, col, iT);
                // spill gi_n into this thread's own hnxt slots (stale buffer; read back in epilogue)
#pragma unroll
                for (int q4 = 0; q4 < 4; ++q4){
                    ulonglong2 v; v.x = gi[2][2 * q4]; v.y = gi[2][2 * q4 + 1];
                    *(ulonglong2*)(hnxt + col * STT + 4 * q4) = v;
                }
                ull giR[8], giZ[8];
#pragma unroll
                for (int p = 0; p < 8; ++p){ giR[p] = gi[0][p]; giZ[p] = gi[1][p]; }

                // Phase 2: gh chains
                ull gh[3][8] = {};
                chain3H<H_, 2 * 3 * H_>(gh, g_WhhT, col, hcur);

                const float bir = bih[col], biz = bih[col + H_], bin = bih[col + 2 * H_];
                const float bhr = bhh[col], bhz = bhh[col + H_], bhn = bhh[col + 2 * H_];
                // Phase 3: epilogue — read spilled gi_n pair, then overwrite same slots with h
#pragma unroll
                for (int p = 0; p < 8; ++p){
                    ull ginp = *(const ull*)(hnxt + col * STT + 2 * p);
                    float giN0, giN1; unpack2(ginp, giN0, giN1);
                    float giR0, giR1, giZ0, giZ1;
                    unpack2(giR[p], giR0, giR1); unpack2(giZ[p], giZ0, giZ1);
                    float ghR0, ghR1, ghZ0, ghZ1, ghN0, ghN1;
                    unpack2(gh[0][p], ghR0, ghR1); unpack2(gh[1][p], ghZ0, ghZ1); unpack2(gh[2][p], ghN0, ghN1);
                    gru_epilogue_pair(hnxt, hcur, col, STT, 2 * p + 0,
                                      giR0, giZ0, giN0, ghR0, ghZ0, ghN0, bir, biz, bin, bhr, bhz, bhn);
                    gru_epilogue_pair(hnxt, hcur, col, STT, 2 * p + 1,
                                      giR1, giZ1, giN1, ghR1, ghZ1, ghN1, bir, biz, bin, bhr, bhz, bhn);
                }
            }
        }
        __syncthreads();

        logits_argmax_gather<MTT, STT>(b0, t, hnxt, slog, stok, emb, bout, tokf, toki, lg, iT);

        float* tmp = hcur; hcur = hnxt; hnxt = tmp;
    }
}

// ================== MT12, 1 group x 12 rows (R14-proven, unchanged) ==================
template<int KK, int RL>
__device__ __forceinline__ void chain3G(ull (&acc)[3][6],
    const float* __restrict__ wT, int col,
    const float* __restrict__ actT /* STT = 16 */)
{
    const float* w0p = wT + 2 * col;
    const float* w1p = wT + 2 * (col + H_);
    const float* w2p = wT + 2 * (col + 2 * H_);
    constexpr int NP = KK / 2;
    float2 w[4][3];
#pragma unroll
    for (int j = 0; j < 4; ++j){
        w[j][0] = *(const float2*)(w0p + (size_t)j * RL);
        w[j][1] = *(const float2*)(w1p + (size_t)j * RL);
        w[j][2] = *(const float2*)(w2p + (size_t)j * RL);
    }
#pragma unroll 1
    for (int p0 = 0; p0 < NP; p0 += 4){
#pragma unroll
        for (int j = 0; j < 4; ++j){
            const int p = p0 + j;
#pragma unroll
            for (int s = 0; s < 2; ++s){
                const int k = 2 * p + s;
                ull a[6];
                load_act<6>(a, actT + (size_t)k * 16);
                ull d0 = dup2(s ? w[j][0].y : w[j][0].x);
                ull d1 = dup2(s ? w[j][1].y : w[j][1].x);
                ull d2 = dup2(s ? w[j][2].y : w[j][2].x);
#pragma unroll
                for (int pp = 0; pp < 6; ++pp) ffma2(acc[0][pp], a[pp], d0);
#pragma unroll
                for (int pp = 0; pp < 6; ++pp) ffma2(acc[1][pp], a[pp], d1);
#pragma unroll
                for (int pp = 0; pp < 6; ++pp) ffma2(acc[2][pp], a[pp], d2);
            }
            const int pn = p + 4;
            w[j][0] = *(const float2*)(w0p + (size_t)pn * RL);
            w[j][1] = *(const float2*)(w1p + (size_t)pn * RL);
            w[j][2] = *(const float2*)(w2p + (size_t)pn * RL);
        }
    }
}

template<int KK, int RL>
__device__ __forceinline__ void chain1G(ull (&acc)[6],
    const float* __restrict__ wT, int col,
    const float* __restrict__ actT)
{
    const float* wp = wT + 2 * col;
    constexpr int NP = KK / 2;
    float2 w[4];
#pragma unroll
    for (int j = 0; j < 4; ++j)
        w[j] = *(const float2*)(wp + (size_t)j * RL);
#pragma unroll 1
    for (int p0 = 0; p0 < NP; p0 += 4){
#pragma unroll
        for (int j = 0; j < 4; ++j){
            const int p = p0 + j;
#pragma unroll
            for (int s = 0; s < 2; ++s){
                const int k = 2 * p + s;
                ull a[6];
                load_act<6>(a, actT + (size_t)k * 16);
                ull d0 = dup2(s ? w[j].y : w[j].x);
#pragma unroll
                for (int pp = 0; pp < 6; ++pp) ffma2(acc[pp], a[pp], d0);
            }
            w[j] = *(const float2*)(wp + (size_t)(p + 4) * RL);
        }
    }
}

__device__ __forceinline__ void run_tile12(
    int b0,
    const float* __restrict__ x,    const float* __restrict__ emb,
    const float* __restrict__ sos,
    const float* __restrict__ bi2h,
    const float* __restrict__ bih,  const float* __restrict__ bhh,
    const float* __restrict__ bout,
    float* __restrict__ tokf, int* __restrict__ toki, float* __restrict__ lg)
{
    constexpr int MTT = 12, STT = 16;
    constexpr int OVL = (IROWS * STT > MTT * V_) ? IROWS * STT : MTT * V_;

    extern __shared__ float sm[];
    float* hT0  = sm;
    float* hT1  = hT0 + HROWS * STT;
    float* iT   = hT1 + HROWS * STT;
    float* slog = iT;
    int*   stok = (int*)(iT + OVL);

    const int tid = threadIdx.x;

    for (int q = tid; q < MTT * (DIN / 4); q += NT){
        const int ch  = q & 63;
        const int row = q >> 6;
        float4 v = *(const float4*)(x + (size_t)(b0 + row) * DIN + ch * 4);
        iT[(4 * ch + 0) * STT + row] = v.x;
        iT[(4 * ch + 1) * STT + row] = v.y;
        iT[(4 * ch + 2) * STT + row] = v.z;
        iT[(4 * ch + 3) * STT + row] = v.w;
    }
    __syncthreads();

    float* hcur = hT0;
    float* hnxt = hT1;

#pragma unroll 1
    for (int c = 0; c < H_; c += 256){
        const int col = c + tid;
        ull acc[6] = {};
        chain1G<DIN, 2 * H_>(acc, g_Wi2hT, col, iT);
        const float b = bi2h[col];
#pragma unroll
        for (int p = 0; p < 6; ++p){
            float lo, hi; unpack2(acc[p], lo, hi);
            hcur[col * STT + 2 * p + 0] = __fadd_rn(lo, b);
            hcur[col * STT + 2 * p + 1] = __fadd_rn(hi, b);
        }
    }
    __syncthreads();

    for (int q = tid; q < E_ * MTT; q += NT){
        const int e = q / MTT, r = q % MTT;
        iT[e * STT + r] = sos[e];
    }

#pragma unroll 1
    for (int t = 0; t < L_; ++t){
        __syncthreads();
#pragma unroll 1
        for (int c = 0; c < H_; c += 256){
            const int col = c + tid;
            ull gi[3][6] = {};
            ull gh[3][6] = {};
            chain3G<E_, 2 * 3 * H_>(gi, g_WihT, col, iT);
            chain3G<H_, 2 * 3 * H_>(gh, g_WhhT, col, hcur);
            const float bir = bih[col], biz = bih[col + H_], bin = bih[col + 2 * H_];
            const float bhr = bhh[col], bhz = bhh[col + H_], bhn = bhh[col + 2 * H_];
#pragma unroll
            for (int p = 0; p < 6; ++p){
                float giR0, giR1, giZ0, giZ1, giN0, giN1;
                float ghR0, ghR1, ghZ0, ghZ1, ghN0, ghN1;
                unpack2(gi[0][p], giR0, giR1); unpack2(gi[1][p], giZ0, giZ1); unpack2(gi[2][p], giN0, giN1);
                unpack2(gh[0][p], ghR0, ghR1); unpack2(gh[1][p], ghZ0, ghZ1); unpack2(gh[2][p], ghN0, ghN1);
                gru_epilogue_pair(hnxt, hcur, col, STT, 2 * p + 0,
                                  giR0, giZ0, giN0, ghR0, ghZ0, ghN0, bir, biz, bin, bhr, bhz, bhn);
                gru_epilogue_pair(hnxt, hcur, col, STT, 2 * p + 1,
                                  giR1, giZ1, giN1, ghR1, ghZ1, ghN1, bir, biz, bin, bhr, bhz, bhn);
            }
        }
        __syncthreads();

        logits_argmax_gather<MTT, STT>(b0, t, hnxt, slog, stok, emb, bout, tokf, toki, lg, iT);

        float* tmp = hcur; hcur = hnxt; hnxt = tmp;
    }
}

// ================== dispatch: pair one MT16 with one MT12 per SM via bid%148 ==================
__global__ void __launch_bounds__(NT, 2)
rnn_decoder_kernel(
    const float* __restrict__ x,    const float* __restrict__ emb,
    const float* __restrict__ sos,
    const float* __restrict__ bi2h,
    const float* __restrict__ bih,  const float* __restrict__ bhh,
    const float* __restrict__ bout,
    float* __restrict__ tokf, int* __restrict__ toki, float* __restrict__ lg)
{
    const int bid = blockIdx.x;
    int n16, n12; bool is16;
    if (bid < 148)      { n16 = bid;              n12 = 0;                 is16 = true;  }
    else if (bid < 296) { n16 = 148;              n12 = bid - 148;         is16 = false; }
    else if (bid < 420) { n16 = 148 + bid - 296;  n12 = 148;               is16 = true;  }
    else                { n16 = 272;              n12 = 148 + (bid - 420); is16 = false; }
    const int b0 = n16 * 16 + n12 * 12;
    if (is16) run_tile16(b0, x, emb, sos, bi2h, bih, bhh, bout, tokf, toki, lg);
    else      run_tile12(b0, x, emb, sos, bi2h, bih, bhh, bout, tokf, toki, lg);
}

extern "C" void kernel_launch(void* const* d_in, const int* in_sizes, int n_in,
                              void* d_out, int out_size) {
    const float* x    = (const float*)d_in[0];
    const float* emb  = (const float*)d_in[1];
    const float* sos  = (const float*)d_in[2];
    const float* Wi2h = (const float*)d_in[3];
    const float* bi2h = (const float*)d_in[4];
    const float* Wih  = (const float*)d_in[5];
    const float* Whh  = (const float*)d_in[6];
    const float* bih  = (const float*)d_in[7];
    const float* bhh  = (const float*)d_in[8];
    const float* Wout = (const float*)d_in[9];
    const float* bout = (const float*)d_in[10];

    float *dWihT, *dWhhT, *dWoutT, *dWi2hT;
    cudaGetSymbolAddress((void**)&dWihT,  g_WihT);
    cudaGetSymbolAddress((void**)&dWhhT,  g_WhhT);
    cudaGetSymbolAddress((void**)&dWoutT, g_WoutT);
    cudaGetSymbolAddress((void**)&dWi2hT, g_Wi2hT);

    stage_weights_kernel<<<1024, 256>>>(Wih, Whh, Wout, Wi2h,
                                        dWihT, dWhhT, dWoutT, dWi2hT);

    const long long TOKN = (long long)B_ * L_;        // 262144
    const long long LGN  = TOKN * V_;                 // 67108864
    const long long os   = (long long)out_size;

    float* tokf = nullptr;
    int*   toki = nullptr;
    float* lg   = nullptr;

    if (os == TOKN + LGN){           // (tokens, logits) concatenated as float32
        tokf = (float*)d_out;
        lg   = (float*)d_out + TOKN;
    } else if (os == LGN){           // logits only
        lg   = (float*)d_out;
    } else if (os == TOKN){          // tokens only (int32)
        toki = (int*)d_out;
    } else {                         // best guess
        tokf = (float*)d_out;
        lg   = (float*)d_out + TOKN;
    }

    // smem sized for the larger (MT=16) tile
    constexpr int ST16  = 20;
    constexpr int OVL16 = (IROWS * ST16 > 16 * V_) ? IROWS * ST16 : 16 * V_;
    const size_t smem = (size_t)(2 * HROWS * ST16 + OVL16) * sizeof(float) + 16 * sizeof(int);
    cudaFuncSetAttribute(rnn_decoder_kernel,
                         cudaFuncAttributeMaxDynamicSharedMemorySize, (int)smem);
    rnn_decoder_kernel<<<GRID, NT, smem>>>(
        x, emb, sos, bi2h, bih, bhh, bout,
        tokf, toki, lg);
}